// round 11
// baseline (speedup 1.0000x reference)
#include <cuda_runtime.h>
#include <cuda_bf16.h>
#include <cfloat>
#include <cstdint>

// ---------------- scratch (__device__ globals; no allocations) ----------------
__device__ float g_qkv[1024 * 3072];              // 12 MB  (T, 3C)
__device__ float g_ksnorm[16 * 8192];             // (H, M)
__device__ __nv_bfloat16 g_kh[16 * 1024 * 64];    // bf16-hi of k, [h][t][d]
__device__ __nv_bfloat16 g_kl[16 * 1024 * 64];    // bf16-lo of k
__device__ __nv_bfloat16 g_qh[16 * 1024 * 64];    // bf16-hi of q*0.125, [h][t][d]
__device__ __nv_bfloat16 g_ql[16 * 1024 * 64];    // bf16-lo
__device__ __nv_bfloat16 g_mh[16 * 8192 * 64];    // bf16-hi of key_store
__device__ __nv_bfloat16 g_ml[16 * 8192 * 64];    // bf16-lo of key_store
__device__ __nv_bfloat16 g_xh[1024 * 1024];       // bf16-hi of x
__device__ __nv_bfloat16 g_xl[1024 * 1024];
__device__ __nv_bfloat16 g_awh[3072 * 1024];      // bf16-hi of c_attn_w
__device__ __nv_bfloat16 g_awl[3072 * 1024];
__device__ __nv_bfloat16 g_pwh[1024 * 1024];      // bf16-hi of c_proj_w
__device__ __nv_bfloat16 g_pwl[1024 * 1024];
__device__ __nv_bfloat16 g_yh[1024 * 1024];       // bf16-hi of y
__device__ __nv_bfloat16 g_yl[1024 * 1024];
__device__ __nv_bfloat16 g_vth[16 * 64 * 1024];   // bf16-hi of v_new^T, [h][d][t]
__device__ __nv_bfloat16 g_vtl[16 * 64 * 1024];   // bf16-lo
__device__ float g_lg[16 * 1024];                 // last-row logits
__device__ int   g_idx[16 * 1024 * 4];            // (H, T, 4)
__device__ int   g_sel[16 * 1024];                // (H, T)
__device__ float g_vnew[16 * 1024 * 64];          // (H, T, d)
__device__ float g_y[1024 * 1024];                // (T, C)

// ---------------- helpers ----------------
__device__ __forceinline__ void mma_bf16(float& c0, float& c1, float& c2, float& c3,
                                         uint32_t a0, uint32_t a1, uint32_t a2, uint32_t a3,
                                         uint32_t b0, uint32_t b1) {
    asm volatile(
        "mma.sync.aligned.m16n8k16.row.col.f32.bf16.bf16.f32 "
        "{%0,%1,%2,%3}, {%4,%5,%6,%7}, {%8,%9}, {%0,%1,%2,%3};"
        : "+f"(c0), "+f"(c1), "+f"(c2), "+f"(c3)
        : "r"(a0), "r"(a1), "r"(a2), "r"(a3), "r"(b0), "r"(b1));
}

__device__ __forceinline__ uint32_t pack_bf16(__nv_bfloat16 lo, __nv_bfloat16 hi) {
    __nv_bfloat162 t;
    t.x = lo; t.y = hi;
    return *(uint32_t*)&t;
}

// ---------- vectorized contiguous bf16 hi/lo split (4 floats / thread) ----------
__global__ void split_bf16_v4(const float4* __restrict__ src,
                              __nv_bfloat162* __restrict__ hi,
                              __nv_bfloat162* __restrict__ lo) {
    size_t i = (size_t)blockIdx.x * 256 + threadIdx.x;
    float4 v = src[i];
    __nv_bfloat16 h0 = __float2bfloat16(v.x), h1 = __float2bfloat16(v.y);
    __nv_bfloat16 h2 = __float2bfloat16(v.z), h3 = __float2bfloat16(v.w);
    __nv_bfloat16 l0 = __float2bfloat16(v.x - __bfloat162float(h0));
    __nv_bfloat16 l1 = __float2bfloat16(v.y - __bfloat162float(h1));
    __nv_bfloat16 l2 = __float2bfloat16(v.z - __bfloat162float(h2));
    __nv_bfloat16 l3 = __float2bfloat16(v.w - __bfloat162float(h3));
    hi[i * 2 + 0] = __nv_bfloat162{h0, h1};
    hi[i * 2 + 1] = __nv_bfloat162{h2, h3};
    lo[i * 2 + 0] = __nv_bfloat162{l0, l1};
    lo[i * 2 + 1] = __nv_bfloat162{l2, l3};
}

// -- bf16 hi/lo split of k AND q (scaled 0.125) from qkv, relayout to [h][t][d] --
__global__ void split_qk_bf16_kernel(const float* __restrict__ qkv,
                                     __nv_bfloat16* __restrict__ khi,
                                     __nv_bfloat16* __restrict__ klo,
                                     __nv_bfloat16* __restrict__ qhi,
                                     __nv_bfloat16* __restrict__ qlo) {
    int i = blockIdx.x * 1024 + threadIdx.x;  // 2M
    int which = i >> 20;                      // 0: k, 1: q
    int r = i & 0xFFFFF;
    int d = r & 63, t = (r >> 6) & 1023, h = r >> 16;
    float x = qkv[(size_t)t * 3072 + (which ? 0 : 1024) + h * 64 + d];
    if (which) x *= 0.125f;
    __nv_bfloat16 hf = __float2bfloat16(x);
    __nv_bfloat16 lf = __float2bfloat16(x - __bfloat162float(hf));
    if (which) { qhi[r] = hf; qlo[r] = lf; }
    else       { khi[r] = hf; klo[r] = lf; }
}

// ---- generic 3xBF16 mma GEMM: C = A * B^T + bias  (round-9 validated) ----
#define KAH 72
#define GM_SMEM_BYTES ((64 * KAH * 2 + 128 * KAH * 2) * 2)

__global__ __launch_bounds__(256) void mma_gemm_bf16_kernel(
    const __nv_bfloat16* __restrict__ Ahg, const __nv_bfloat16* __restrict__ Alg,
    const __nv_bfloat16* __restrict__ Bhg, const __nv_bfloat16* __restrict__ Blg,
    float* __restrict__ C, int ldc, int K, const float* __restrict__ bias) {
    extern __shared__ char smc[];
    __nv_bfloat16* Ah = (__nv_bfloat16*)smc;          // [64][72]
    __nv_bfloat16* Al = Ah + 64 * KAH;
    __nv_bfloat16* Bh = Al + 64 * KAH;                // [128][72]
    __nv_bfloat16* Bl = Bh + 128 * KAH;

    const int tid = threadIdx.x;
    const int bx = blockIdx.x, by = blockIdx.y;
    const int w = tid >> 5, lane = tid & 31;
    const int gid = lane >> 2, qid = lane & 3;
    const int rt = (w & 3) * 16;
    const int ch = (w >> 2) * 64;

    const __nv_bfloat16* Ahb = Ahg + (size_t)(by * 64) * K;
    const __nv_bfloat16* Alb = Alg + (size_t)(by * 64) * K;
    const __nv_bfloat16* Bhb = Bhg + (size_t)(bx * 128) * K;
    const __nv_bfloat16* Blb = Blg + (size_t)(bx * 128) * K;

    float c[8][4];
#pragma unroll
    for (int nb = 0; nb < 8; nb++)
#pragma unroll
        for (int k = 0; k < 4; k++) c[nb][k] = 0.f;

    for (int k0 = 0; k0 < K; k0 += 64) {
        __syncthreads();
        for (int i = tid; i < 512; i += 256) {
            int r = i >> 3, c8 = (i & 7) * 8;
            *(uint4*)&Ah[r * KAH + c8] = *(const uint4*)(Ahb + (size_t)r * K + k0 + c8);
            *(uint4*)&Al[r * KAH + c8] = *(const uint4*)(Alb + (size_t)r * K + k0 + c8);
        }
        for (int i = tid; i < 1024; i += 256) {
            int r = i >> 3, c8 = (i & 7) * 8;
            *(uint4*)&Bh[r * KAH + c8] = *(const uint4*)(Bhb + (size_t)r * K + k0 + c8);
            *(uint4*)&Bl[r * KAH + c8] = *(const uint4*)(Blb + (size_t)r * K + k0 + c8);
        }
        __syncthreads();

#pragma unroll
        for (int ks16 = 0; ks16 < 4; ks16++) {
            const int kk = ks16 * 16;
            const int ab = (rt + gid) * KAH + kk + 2 * qid;
            uint32_t ah0 = *(const uint32_t*)&Ah[ab];
            uint32_t ah1 = *(const uint32_t*)&Ah[ab + 8 * KAH];
            uint32_t ah2 = *(const uint32_t*)&Ah[ab + 8];
            uint32_t ah3 = *(const uint32_t*)&Ah[ab + 8 * KAH + 8];
            uint32_t al0 = *(const uint32_t*)&Al[ab];
            uint32_t al1 = *(const uint32_t*)&Al[ab + 8 * KAH];
            uint32_t al2 = *(const uint32_t*)&Al[ab + 8];
            uint32_t al3 = *(const uint32_t*)&Al[ab + 8 * KAH + 8];
#pragma unroll
            for (int nb = 0; nb < 8; nb++) {
                const int bb = (ch + nb * 8 + gid) * KAH + kk + 2 * qid;
                uint32_t bh0 = *(const uint32_t*)&Bh[bb];
                uint32_t bh1 = *(const uint32_t*)&Bh[bb + 8];
                uint32_t bl0 = *(const uint32_t*)&Bl[bb];
                uint32_t bl1 = *(const uint32_t*)&Bl[bb + 8];
                mma_bf16(c[nb][0], c[nb][1], c[nb][2], c[nb][3],
                         ah0, ah1, ah2, ah3, bh0, bh1);
                mma_bf16(c[nb][0], c[nb][1], c[nb][2], c[nb][3],
                         ah0, ah1, ah2, ah3, bl0, bl1);
                mma_bf16(c[nb][0], c[nb][1], c[nb][2], c[nb][3],
                         al0, al1, al2, al3, bh0, bh1);
            }
        }
    }

#pragma unroll
    for (int nb = 0; nb < 8; nb++) {
#pragma unroll
        for (int k = 0; k < 4; k++) {
            int row = by * 64 + rt + gid + (k >> 1) * 8;
            int col = bx * 128 + ch + nb * 8 + 2 * qid + (k & 1);
            C[(size_t)row * ldc + col] = c[nb][k] + bias[col];
        }
    }
}

// ---------------- ||key_store[h,m]||^2 (exact fp32) ----------------
__global__ void ksnorm_kernel(const float* __restrict__ ks, float* __restrict__ nrm) {
    int r = blockIdx.x * blockDim.x + threadIdx.x;
    if (r >= 16 * 8192) return;
    const float4* p = (const float4*)(ks + (size_t)r * 64);
    float s = 0.f;
#pragma unroll
    for (int i = 0; i < 16; i++) {
        float4 f = p[i];
        s += f.x * f.x + f.y * f.y + f.z * f.z + f.w * f.w;
    }
    nrm[r] = s;
}

// ------------- lexicographic (score, idx) compare: stable top-k --------------
__device__ __forceinline__ bool lex_lt(float sa, int ia, float sb, int ib) {
    return sa < sb || (sa == sb && ia < ib);
}

#define TOP4_INSERT(v, m, s0, x0, s1, x1, s2, x2, s3, x3)              \
    if (lex_lt(v, m, s3, x3)) {                                        \
        if (lex_lt(v, m, s2, x2)) {                                    \
            s3 = s2; x3 = x2;                                          \
            if (lex_lt(v, m, s1, x1)) {                                \
                s2 = s1; x2 = x1;                                      \
                if (lex_lt(v, m, s0, x0)) {                            \
                    s1 = s0; x1 = x0; s0 = v; x0 = m;                  \
                } else { s1 = v; x1 = m; }                             \
            } else { s2 = v; x2 = m; }                                 \
        } else { s3 = v; x3 = m; }                                     \
    }

// ---- fused kNN scores + top-4, bf16 mma, 128 t-rows/block (B-frag reuse x2) ----
// Warp w: rows (w&3)*32 .. +31 (two 16-row mma tiles), cols (w>>2)*64 .. +63.
// smem: Ah/Al [128][72], Bh/Bl [128][72], Ns [128]f
#define KNN_SMEM_BYTES ((128 * KAH * 2 + 128 * KAH * 2) * 2 + 128 * 4)

__global__ __launch_bounds__(256) void knn_mma_kernel(
    const __nv_bfloat16* __restrict__ kh, const __nv_bfloat16* __restrict__ kl,
    const __nv_bfloat16* __restrict__ mh, const __nv_bfloat16* __restrict__ ml,
    const float* __restrict__ ksn, int* __restrict__ idx_out) {
    extern __shared__ char smc[];
    __nv_bfloat16* Ah = (__nv_bfloat16*)smc;          // [128][72]
    __nv_bfloat16* Al = Ah + 128 * KAH;
    __nv_bfloat16* Bh = Al + 128 * KAH;               // [128][72]
    __nv_bfloat16* Bl = Bh + 128 * KAH;
    float* Ns = (float*)(Bl + 128 * KAH);             // [128]

    const int tid = threadIdx.x;
    const int t0 = blockIdx.x * 128;
    const int h = blockIdx.y;
    const int w = tid >> 5, lane = tid & 31;
    const int gid = lane >> 2, qid = lane & 3;
    const int rt = (w & 3) * 32;        // 32-row warp tile base (t)
    const int ch = (w >> 2) * 64;       // col half base (m)

    // A tiles (bf16 hi/lo), 128 rows x 64 halves
    const __nv_bfloat16* Ahg = kh + ((size_t)h * 1024 + t0) * 64;
    const __nv_bfloat16* Alg = kl + ((size_t)h * 1024 + t0) * 64;
    for (int i = tid; i < 1024; i += 256) {
        int r = i >> 3, c8 = (i & 7) * 8;
        *(uint4*)&Ah[r * KAH + c8] = *(const uint4*)(Ahg + (size_t)r * 64 + c8);
        *(uint4*)&Al[r * KAH + c8] = *(const uint4*)(Alg + (size_t)r * 64 + c8);
    }

    float S[4][4];
    int I[4][4];
#pragma unroll
    for (int r = 0; r < 4; r++)
#pragma unroll
        for (int k = 0; k < 4; k++) { S[r][k] = FLT_MAX; I[r][k] = 0x7fffffff; }

    const __nv_bfloat16* Bhg = mh + (size_t)h * 8192 * 64;
    const __nv_bfloat16* Blg = ml + (size_t)h * 8192 * 64;
    const float* Nbase = ksn + h * 8192;

    for (int chunk = 0; chunk < 64; chunk++) {
        const int m0 = chunk << 7;
        __syncthreads();
        if (tid < 128) Ns[tid] = Nbase[m0 + tid];
        for (int i = tid; i < 1024; i += 256) {
            int r = i >> 3, c8 = (i & 7) * 8;
            *(uint4*)&Bh[r * KAH + c8] = *(const uint4*)(Bhg + (size_t)(m0 + r) * 64 + c8);
            *(uint4*)&Bl[r * KAH + c8] = *(const uint4*)(Blg + (size_t)(m0 + r) * 64 + c8);
        }
        __syncthreads();

        float cA[8][4], cB[8][4];
#pragma unroll
        for (int nb = 0; nb < 8; nb++)
#pragma unroll
            for (int k = 0; k < 4; k++) { cA[nb][k] = 0.f; cB[nb][k] = 0.f; }

#pragma unroll
        for (int ks16 = 0; ks16 < 4; ks16++) {
            const int k0 = ks16 * 16;
            // A fragments for rows rt+gid, rt+8+gid (tile A)
            const int aA = (rt + gid) * KAH + k0 + 2 * qid;
            uint32_t aAh0 = *(const uint32_t*)&Ah[aA];
            uint32_t aAh1 = *(const uint32_t*)&Ah[aA + 8 * KAH];
            uint32_t aAh2 = *(const uint32_t*)&Ah[aA + 8];
            uint32_t aAh3 = *(const uint32_t*)&Ah[aA + 8 * KAH + 8];
            uint32_t aAl0 = *(const uint32_t*)&Al[aA];
            uint32_t aAl1 = *(const uint32_t*)&Al[aA + 8 * KAH];
            uint32_t aAl2 = *(const uint32_t*)&Al[aA + 8];
            uint32_t aAl3 = *(const uint32_t*)&Al[aA + 8 * KAH + 8];
            // A fragments for rows rt+16+gid, rt+24+gid (tile B)
            const int aB = aA + 16 * KAH;
            uint32_t aBh0 = *(const uint32_t*)&Ah[aB];
            uint32_t aBh1 = *(const uint32_t*)&Ah[aB + 8 * KAH];
            uint32_t aBh2 = *(const uint32_t*)&Ah[aB + 8];
            uint32_t aBh3 = *(const uint32_t*)&Ah[aB + 8 * KAH + 8];
            uint32_t aBl0 = *(const uint32_t*)&Al[aB];
            uint32_t aBl1 = *(const uint32_t*)&Al[aB + 8 * KAH];
            uint32_t aBl2 = *(const uint32_t*)&Al[aB + 8];
            uint32_t aBl3 = *(const uint32_t*)&Al[aB + 8 * KAH + 8];
#pragma unroll
            for (int nb = 0; nb < 8; nb++) {
                const int bb = (ch + nb * 8 + gid) * KAH + k0 + 2 * qid;
                uint32_t bh0 = *(const uint32_t*)&Bh[bb];
                uint32_t bh1 = *(const uint32_t*)&Bh[bb + 8];
                uint32_t bl0 = *(const uint32_t*)&Bl[bb];
                uint32_t bl1 = *(const uint32_t*)&Bl[bb + 8];
                mma_bf16(cA[nb][0], cA[nb][1], cA[nb][2], cA[nb][3],
                         aAh0, aAh1, aAh2, aAh3, bh0, bh1);
                mma_bf16(cA[nb][0], cA[nb][1], cA[nb][2], cA[nb][3],
                         aAh0, aAh1, aAh2, aAh3, bl0, bl1);
                mma_bf16(cA[nb][0], cA[nb][1], cA[nb][2], cA[nb][3],
                         aAl0, aAl1, aAl2, aAl3, bh0, bh1);
                mma_bf16(cB[nb][0], cB[nb][1], cB[nb][2], cB[nb][3],
                         aBh0, aBh1, aBh2, aBh3, bh0, bh1);
                mma_bf16(cB[nb][0], cB[nb][1], cB[nb][2], cB[nb][3],
                         aBh0, aBh1, aBh2, aBh3, bl0, bl1);
                mma_bf16(cB[nb][0], cB[nb][1], cB[nb][2], cB[nb][3],
                         aBl0, aBl1, aBl2, aBl3, bh0, bh1);
            }
        }

        // fold candidates (rows: S[0]=rt+gid, S[1]=+8, S[2]=+16, S[3]=+24)
#pragma unroll
        for (int nb = 0; nb < 8; nb++) {
#pragma unroll
            for (int k = 0; k < 4; k++) {
                int cl = ch + nb * 8 + 2 * qid + (k & 1);
                int mg = m0 + cl;
                float n = Ns[cl];
                int r = k >> 1;
                float vA = n - 2.0f * cA[nb][k];
                TOP4_INSERT(vA, mg, S[r][0], I[r][0], S[r][1], I[r][1],
                            S[r][2], I[r][2], S[r][3], I[r][3]);
                float vB = n - 2.0f * cB[nb][k];
                TOP4_INSERT(vB, mg, S[r + 2][0], I[r + 2][0], S[r + 2][1], I[r + 2][1],
                            S[r + 2][2], I[r + 2][2], S[r + 2][3], I[r + 2][3]);
            }
        }
    }

    // merge: 8 contributors per row (2 col-half warps x 4 qid), 32 cands/row, 128 rows
    __syncthreads();
    float* msc = (float*)smc;                 // [128][32] floats = 16 KB
    int* mix = (int*)(smc + 16384);           // [128][32] ints
    const int slot = (w >> 2) * 4 + qid;
#pragma unroll
    for (int rr = 0; rr < 4; rr++) {
        int row = rt + rr * 8 + gid;          // S[rr] row: rr=0:+0, 1:+8, 2:+16, 3:+24
#pragma unroll
        for (int k = 0; k < 4; k++) {
            msc[(row * 8 + slot) * 4 + k] = S[rr][k];
            mix[(row * 8 + slot) * 4 + k] = I[rr][k];
        }
    }
    __syncthreads();
    if (tid < 128) {
        float f0 = FLT_MAX, f1 = FLT_MAX, f2 = FLT_MAX, f3 = FLT_MAX;
        int g0 = 0x7fffffff, g1 = 0x7fffffff, g2 = 0x7fffffff, g3 = 0x7fffffff;
        for (int c2 = 0; c2 < 32; c2++) {
            float v = msc[tid * 32 + c2];
            int m = mix[tid * 32 + c2];
            TOP4_INSERT(v, m, f0, g0, f1, g1, f2, g2, f3, g3);
        }
        size_t row = (size_t)h * 1024 + t0 + tid;
        idx_out[row * 4 + 0] = g0;
        idx_out[row * 4 + 1] = g1;
        idx_out[row * 4 + 2] = g2;
        idx_out[row * 4 + 3] = g3;
    }
}

// NOTE: S[rr] row mapping above: rr=0 -> rt+gid, rr=1 -> rt+gid+8,
// rr=2 -> rt+gid+16, rr=3 -> rt+gid+24; merge store uses rt + rr*8 + gid which
// matches exactly.

// ---------------- warp-per-token last-row logits ----------------
__global__ void selA_kernel(const float* __restrict__ qkv, float* __restrict__ lg) {
    int h = blockIdx.y;
    int t = blockIdx.x * 8 + (threadIdx.x >> 5);
    int lane = threadIdx.x & 31;
    int d0 = lane * 2;
    const float* q = qkv + (size_t)1023 * 3072 + h * 64;
    const float* k = qkv + (size_t)t * 3072 + 1024 + h * 64;
    float s = q[d0] * k[d0] + q[d0 + 1] * k[d0 + 1];
#pragma unroll
    for (int o = 16; o > 0; o >>= 1) s += __shfl_xor_sync(0xffffffffu, s, o);
    if (lane == 0) lg[h * 1024 + t] = s * 0.125f;
}

// ---------------- per-head softmax of logits row -> sel ----------------
__global__ void selB_kernel(const float* __restrict__ lg, int* __restrict__ sel) {
    int h = blockIdx.x;
    int tid = threadIdx.x;
    int lane = tid & 31, warp = tid >> 5;
    __shared__ float red[8];
    __shared__ float bcast;

    float v[4];
#pragma unroll
    for (int u = 0; u < 4; u++) v[u] = lg[h * 1024 + tid + u * 256];
    float m = fmaxf(fmaxf(v[0], v[1]), fmaxf(v[2], v[3]));
#pragma unroll
    for (int o = 16; o > 0; o >>= 1) m = fmaxf(m, __shfl_xor_sync(0xffffffffu, m, o));
    if (lane == 0) red[warp] = m;
    __syncthreads();
    if (tid == 0) {
        float x = red[0];
#pragma unroll
        for (int w = 1; w < 8; w++) x = fmaxf(x, red[w]);
        bcast = x;
    }
    __syncthreads();
    m = bcast;
    float e[4], s = 0.f;
#pragma unroll
    for (int u = 0; u < 4; u++) { e[u] = __expf(v[u] - m); s += e[u]; }
#pragma unroll
    for (int o = 16; o > 0; o >>= 1) s += __shfl_xor_sync(0xffffffffu, s, o);
    if (lane == 0) red[warp] = s;
    __syncthreads();
    if (tid == 0) {
        float x = 0.f;
#pragma unroll
        for (int w = 0; w < 8; w++) x += red[w];
        bcast = x;
    }
    __syncthreads();
    float inv = 1.f / bcast;
#pragma unroll
    for (int u = 0; u < 4; u++)
        sel[h * 1024 + tid + u * 256] = (e[u] * inv >= (1.0f / 8192.0f)) ? 1 : 0;
}

// ---------------- per-token 5-way memory softmax & blend -> v_new ----------------
__device__ __forceinline__ float warp_sum(float v) {
#pragma unroll
    for (int o = 16; o > 0; o >>= 1) v += __shfl_xor_sync(0xffffffffu, v, o);
    return v;
}

__global__ void vnew_kernel(const float* __restrict__ qkv, const float* __restrict__ kstore,
                            const float* __restrict__ vstore, const int* __restrict__ idx,
                            const int* __restrict__ sel, float* __restrict__ vnew) {
    int gw = (blockIdx.x * blockDim.x + threadIdx.x) >> 5;
    int lane = threadIdx.x & 31;
    if (gw >= 16 * 1024) return;
    int h = gw >> 10, t = gw & 1023;

    const float* base = qkv + (size_t)t * 3072 + h * 64;
    int d0 = lane * 2;
    float q0 = base[d0],        q1 = base[d0 + 1];
    float k0 = base[1024 + d0], k1 = base[1024 + d0 + 1];
    float v0 = base[2048 + d0], v1 = base[2048 + d0 + 1];
    const float scale = 0.125f;

    float attf[5];
    attf[0] = warp_sum(q0 * k0 + q1 * k1) * scale;

    int ids[4];
#pragma unroll
    for (int s2 = 0; s2 < 4; s2++) ids[s2] = idx[(size_t)gw * 4 + s2];

    float fv0[4], fv1[4];
#pragma unroll
    for (int s2 = 0; s2 < 4; s2++) {
        const float* kp = kstore + ((size_t)h * 8192 + ids[s2]) * 64;
        attf[s2 + 1] = warp_sum(q0 * kp[d0] + q1 * kp[d0 + 1]) * scale;
        const float* vp = vstore + ((size_t)h * 8192 + ids[s2]) * 64;
        fv0[s2] = vp[d0]; fv1[s2] = vp[d0 + 1];
    }

    float mx = attf[0];
#pragma unroll
    for (int s2 = 1; s2 < 5; s2++) mx = fmaxf(mx, attf[s2]);
    float e[5], sum = 0.f;
#pragma unroll
    for (int s2 = 0; s2 < 5; s2++) { e[s2] = expf(attf[s2] - mx); sum += e[s2]; }
    float inv = 1.f / sum;

    float o0 = e[0] * v0, o1 = e[0] * v1;
#pragma unroll
    for (int s2 = 0; s2 < 4; s2++) { o0 += e[s2 + 1] * fv0[s2]; o1 += e[s2 + 1] * fv1[s2]; }
    o0 = o0 * inv * 0.5f + v0 * 0.5f;
    o1 = o1 * inv * 0.5f + v1 * 0.5f;

    bool sl = sel[gw] != 0;
    vnew[(size_t)gw * 64 + d0]     = sl ? o0 : v0;
    vnew[(size_t)gw * 64 + d0 + 1] = sl ? o1 : v1;
}

// ------- transpose+split v_new to bf16 hi/lo, [h][d][t] layout (for flash PV) -------
__global__ void vtrans_kernel(const float* __restrict__ vnew,
                              __nv_bfloat16* __restrict__ vth,
                              __nv_bfloat16* __restrict__ vtl) {
    __shared__ float sm[64][65];
    const int tid = threadIdx.x;
    const int t0 = blockIdx.x * 64, h = blockIdx.y;
    for (int i = tid; i < 4096; i += 256) {
        int tr = i >> 6, d = i & 63;
        sm[tr][d] = vnew[((size_t)h * 1024 + t0 + tr) * 64 + d];
    }
    __syncthreads();
    for (int i = tid; i < 4096; i += 256) {
        int d = i >> 6, tr = i & 63;
        float x = sm[tr][d];
        __nv_bfloat16 hh = __float2bfloat16(x);
        size_t o = ((size_t)h * 64 + d) * 1024 + t0 + tr;
        vth[o] = hh;
        vtl[o] = __float2bfloat16(x - __bfloat162float(hh));
    }
}

// ------- fused flash attention on bf16 mma: y = softmax_causal(qk^T/8) @ v_new -------
// Block: 256 thr (8 warps), 128 q-rows x one head. Warp w: rows w*16..w*16+15, all 64 cols.
// smem: Qh/Ql [128][72], Kh/Kl [64][72] (s-major), Vh/Vl [64][72] (d-major, pre-split)
#define FLM_SMEM_BYTES ((128 * KAH * 2 + 64 * KAH * 2 + 64 * KAH * 2) * 2)

__global__ __launch_bounds__(256) void flash_mma_kernel(
    const __nv_bfloat16* __restrict__ qhg, const __nv_bfloat16* __restrict__ qlg,
    const __nv_bfloat16* __restrict__ khg, const __nv_bfloat16* __restrict__ klg,
    const __nv_bfloat16* __restrict__ vth, const __nv_bfloat16* __restrict__ vtl,
    float* __restrict__ y) {
    extern __shared__ char smc[];
    __nv_bfloat16* Qh = (__nv_bfloat16*)smc;          // [128][72]
    __nv_bfloat16* Ql = Qh + 128 * KAH;
    __nv_bfloat16* Kh = Ql + 128 * KAH;               // [64][72]
    __nv_bfloat16* Kl = Kh + 64 * KAH;
    __nv_bfloat16* Vh = Kl + 64 * KAH;                // [64][72]  (row = d, col = s)
    __nv_bfloat16* Vl = Vh + 64 * KAH;

    const int tid = threadIdx.x;
    const int qb = blockIdx.x, h = blockIdx.y;
    const int w = tid >> 5, lane = tid & 31;
    const int gid = lane >> 2, qid = lane & 3;
    const int rt = w * 16;
    const int t0 = qb * 128;

    // Q tiles (pre-scaled by 0.125 at split time)
    const __nv_bfloat16* Qhg = qhg + ((size_t)h * 1024 + t0) * 64;
    const __nv_bfloat16* Qlg = qlg + ((size_t)h * 1024 + t0) * 64;
    for (int i = tid; i < 1024; i += 256) {
        int r = i >> 3, c8 = (i & 7) * 8;
        *(uint4*)&Qh[r * KAH + c8] = *(const uint4*)(Qhg + (size_t)r * 64 + c8);
        *(uint4*)&Ql[r * KAH + c8] = *(const uint4*)(Qlg + (size_t)r * 64 + c8);
    }

    float m0 = -FLT_MAX, m1 = -FLT_MAX, l0 = 0.f, l1 = 0.f;
    float O[8][4];
#pragma unroll
    for (int nb = 0; nb < 8; nb++)
#pragma unroll
        for (int k = 0; k < 4; k++) O[nb][k] = 0.f;

    const int row0 = t0 + rt + gid, row1 = row0 + 8;
    const int nj = 2 * qb + 2;

    for (int j = 0; j < nj; j++) {
        const int s0 = j * 64;
        __syncthreads();  // prior PV reads done (and Q loads on first iter)
        const __nv_bfloat16* Khg = khg + ((size_t)h * 1024 + s0) * 64;
        const __nv_bfloat16* Klg = klg + ((size_t)h * 1024 + s0) * 64;
        for (int i = tid; i < 512; i += 256) {
            int r = i >> 3, c8 = (i & 7) * 8;
            *(uint4*)&Kh[r * KAH + c8] = *(const uint4*)(Khg + (size_t)r * 64 + c8);
            *(uint4*)&Kl[r * KAH + c8] = *(const uint4*)(Klg + (size_t)r * 64 + c8);
        }
        // V tile: pre-split bf16 [d][t], direct copy
        const __nv_bfloat16* Vhg = vth + (size_t)h * 64 * 1024 + s0;
        const __nv_bfloat16* Vlg = vtl + (size_t)h * 64 * 1024 + s0;
        for (int i = tid; i < 512; i += 256) {
            int r = i >> 3, c8 = (i & 7) * 8;
            *(uint4*)&Vh[r * KAH + c8] = *(const uint4*)(Vhg + (size_t)r * 1024 + c8);
            *(uint4*)&Vl[r * KAH + c8] = *(const uint4*)(Vlg + (size_t)r * 1024 + c8);
        }
        __syncthreads();

        // S = Q K^T (3xBF16): warp rows rt..rt+15, cols 0..63
        float c[8][4];
#pragma unroll
        for (int nb = 0; nb < 8; nb++)
#pragma unroll
            for (int k = 0; k < 4; k++) c[nb][k] = 0.f;

#pragma unroll
        for (int ks16 = 0; ks16 < 4; ks16++) {
            const int kk = ks16 * 16;
            const int ab = (rt + gid) * KAH + kk + 2 * qid;
            uint32_t ah0 = *(const uint32_t*)&Qh[ab];
            uint32_t ah1 = *(const uint32_t*)&Qh[ab + 8 * KAH];
            uint32_t ah2 = *(const uint32_t*)&Qh[ab + 8];
            uint32_t ah3 = *(const uint32_t*)&Qh[ab + 8 * KAH + 8];
            uint32_t al0 = *(const uint32_t*)&Ql[ab];
            uint32_t al1 = *(const uint32_t*)&Ql[ab + 8 * KAH];
            uint32_t al2 = *(const uint32_t*)&Ql[ab + 8];
            uint32_t al3 = *(const uint32_t*)&Ql[ab + 8 * KAH + 8];
#pragma unroll
            for (int nb = 0; nb < 8; nb++) {
                const int bb = (nb * 8 + gid) * KAH + kk + 2 * qid;
                uint32_t bh0 = *(const uint32_t*)&Kh[bb];
                uint32_t bh1 = *(const uint32_t*)&Kh[bb + 8];
                uint32_t bl0 = *(const uint32_t*)&Kl[bb];
                uint32_t bl1 = *(const uint32_t*)&Kl[bb + 8];
                mma_bf16(c[nb][0], c[nb][1], c[nb][2], c[nb][3],
                         ah0, ah1, ah2, ah3, bh0, bh1);
                mma_bf16(c[nb][0], c[nb][1], c[nb][2], c[nb][3],
                         ah0, ah1, ah2, ah3, bl0, bl1);
                mma_bf16(c[nb][0], c[nb][1], c[nb][2], c[nb][3],
                         al0, al1, al2, al3, bh0, bh1);
            }
        }

        // causal mask (only blocks that can cross the diagonal for this warp)
        if (s0 + 63 > t0 + rt) {
#pragma unroll
            for (int nb = 0; nb < 8; nb++) {
                int cb = s0 + nb * 8 + 2 * qid;
                if (cb > row0)     c[nb][0] = -FLT_MAX;
                if (cb + 1 > row0) c[nb][1] = -FLT_MAX;
                if (cb > row1)     c[nb][2] = -FLT_MAX;
                if (cb + 1 > row1) c[nb][3] = -FLT_MAX;
            }
        }

        // online softmax: row stats across this thread's 16 cols + 4 qid lanes
        float rm0 = -FLT_MAX, rm1 = -FLT_MAX;
#pragma unroll
        for (int nb = 0; nb < 8; nb++) {
            rm0 = fmaxf(rm0, fmaxf(c[nb][0], c[nb][1]));
            rm1 = fmaxf(rm1, fmaxf(c[nb][2], c[nb][3]));
        }
        rm0 = fmaxf(rm0, __shfl_xor_sync(0xffffffffu, rm0, 1));
        rm0 = fmaxf(rm0, __shfl_xor_sync(0xffffffffu, rm0, 2));
        rm1 = fmaxf(rm1, __shfl_xor_sync(0xffffffffu, rm1, 1));
        rm1 = fmaxf(rm1, __shfl_xor_sync(0xffffffffu, rm1, 2));

        float mn0 = fmaxf(m0, rm0), mn1 = fmaxf(m1, rm1);
        float alpha0 = __expf(m0 - mn0), alpha1 = __expf(m1 - mn1);
        float ps0 = 0.f, ps1 = 0.f;
#pragma unroll
        for (int nb = 0; nb < 8; nb++) {
            c[nb][0] = __expf(c[nb][0] - mn0); ps0 += c[nb][0];
            c[nb][1] = __expf(c[nb][1] - mn0); ps0 += c[nb][1];
            c[nb][2] = __expf(c[nb][2] - mn1); ps1 += c[nb][2];
            c[nb][3] = __expf(c[nb][3] - mn1); ps1 += c[nb][3];
        }
        ps0 += __shfl_xor_sync(0xffffffffu, ps0, 1);
        ps0 += __shfl_xor_sync(0xffffffffu, ps0, 2);
        ps1 += __shfl_xor_sync(0xffffffffu, ps1, 1);
        ps1 += __shfl_xor_sync(0xffffffffu, ps1, 2);
        l0 = l0 * alpha0 + ps0; m0 = mn0;
        l1 = l1 * alpha1 + ps1; m1 = mn1;
#pragma unroll
        for (int nb = 0; nb < 8; nb++) {
            O[nb][0] *= alpha0; O[nb][1] *= alpha0;
            O[nb][2] *= alpha1; O[nb][3] *= alpha1;
        }

        // P@V: P (C-frag) is bitwise the A-frag layout — register-only conversion
#pragma unroll
        for (int kb = 0; kb < 4; kb++) {
            float p00 = c[2 * kb][0],     p01 = c[2 * kb][1];
            float p02 = c[2 * kb][2],     p03 = c[2 * kb][3];
            float p10 = c[2 * kb + 1][0], p11 = c[2 * kb + 1][1];
            float p12 = c[2 * kb + 1][2], p13 = c[2 * kb + 1][3];
            __nv_bfloat16 h00 = __float2bfloat16(p00), h01 = __float2bfloat16(p01);
            __nv_bfloat16 h02 = __float2bfloat16(p02), h03 = __float2bfloat16(p03);
            __nv_bfloat16 h10 = __float2bfloat16(p10), h11 = __float2bfloat16(p11);
            __nv_bfloat16 h12 = __float2bfloat16(p12), h13 = __float2bfloat16(p13);
            uint32_t Ah0 = pack_bf16(h00, h01);
            uint32_t Ah1 = pack_bf16(h02, h03);
            uint32_t Ah2 = pack_bf16(h10, h11);
            uint32_t Ah3 = pack_bf16(h12, h13);
            uint32_t Al0 = pack_bf16(__float2bfloat16(p00 - __bfloat162float(h00)),
                                     __float2bfloat16(p01 - __bfloat162float(h01)));
            uint32_t Al1 = pack_bf16(__float2bfloat16(p02 - __bfloat162float(h02)),
                                     __float2bfloat16(p03 - __bfloat162float(h03)));
            uint32_t Al2 = pack_bf16(__float2bfloat16(p10 - __bfloat162float(h10)),
                                     __float2bfloat16(p11 - __bfloat162float(h11)));
            uint32_t Al3 = pack_bf16(__float2bfloat16(p12 - __bfloat162float(h12)),
                                     __float2bfloat16(p13 - __bfloat162float(h13)));
#pragma unroll
            for (int nb = 0; nb < 8; nb++) {
                const int bb = (nb * 8 + gid) * KAH + kb * 16 + 2 * qid;
                uint32_t bh0 = *(const uint32_t*)&Vh[bb];
                uint32_t bh1 = *(const uint32_t*)&Vh[bb + 8];
                uint32_t bl0 = *(const uint32_t*)&Vl[bb];
                uint32_t bl1 = *(const uint32_t*)&Vl[bb + 8];
                mma_bf16(O[nb][0], O[nb][1], O[nb][2], O[nb][3],
                         Ah0, Ah1, Ah2, Ah3, bh0, bh1);
                mma_bf16(O[nb][0], O[nb][1], O[nb][2], O[nb][3],
                         Ah0, Ah1, Ah2, Ah3, bl0, bl1);
                mma_bf16(O[nb][0], O[nb][1], O[nb][2], O[nb][3],
                         Al0, Al1, Al2, Al3, bh0, bh1);
            }
        }
    }

    // epilogue: y[t][h*64 + d] = O / l
    float inv0 = 1.f / l0, inv1 = 1.f / l1;
#pragma unroll
    for (int nb = 0; nb < 8; nb++) {
        int colb = h * 64 + nb * 8 + 2 * qid;
        y[(size_t)row0 * 1024 + colb]     = O[nb][0] * inv0;
        y[(size_t)row0 * 1024 + colb + 1] = O[nb][1] * inv0;
        y[(size_t)row1 * 1024 + colb]     = O[nb][2] * inv1;
        y[(size_t)row1 * 1024 + colb + 1] = O[nb][3] * inv1;
    }
}

// ---------------- launch ----------------
extern "C" void kernel_launch(void* const* d_in, const int* in_sizes, int n_in,
                              void* d_out, int out_size) {
    const float* x  = (const float*)d_in[0];
    const float* aw = (const float*)d_in[1];
    const float* ab = (const float*)d_in[2];
    const float* pw = (const float*)d_in[3];
    const float* pb = (const float*)d_in[4];
    const float* ks = (const float*)d_in[5];
    const float* vs = (const float*)d_in[6];
    float* out = (float*)d_out;

    float *qkv, *ksn, *lg, *vnw, *y;
    __nv_bfloat16 *kh, *kl, *qh, *ql, *mh, *ml, *xh, *xl, *awh, *awl, *pwh, *pwl, *yh, *yl;
    __nv_bfloat16 *vth, *vtl;
    int *idx, *sel;
    cudaGetSymbolAddress((void**)&qkv, g_qkv);
    cudaGetSymbolAddress((void**)&ksn, g_ksnorm);
    cudaGetSymbolAddress((void**)&kh,  g_kh);
    cudaGetSymbolAddress((void**)&kl,  g_kl);
    cudaGetSymbolAddress((void**)&qh,  g_qh);
    cudaGetSymbolAddress((void**)&ql,  g_ql);
    cudaGetSymbolAddress((void**)&mh,  g_mh);
    cudaGetSymbolAddress((void**)&ml,  g_ml);
    cudaGetSymbolAddress((void**)&xh,  g_xh);
    cudaGetSymbolAddress((void**)&xl,  g_xl);
    cudaGetSymbolAddress((void**)&awh, g_awh);
    cudaGetSymbolAddress((void**)&awl, g_awl);
    cudaGetSymbolAddress((void**)&pwh, g_pwh);
    cudaGetSymbolAddress((void**)&pwl, g_pwl);
    cudaGetSymbolAddress((void**)&yh,  g_yh);
    cudaGetSymbolAddress((void**)&yl,  g_yl);
    cudaGetSymbolAddress((void**)&vth, g_vth);
    cudaGetSymbolAddress((void**)&vtl, g_vtl);
    cudaGetSymbolAddress((void**)&lg,  g_lg);
    cudaGetSymbolAddress((void**)&idx, g_idx);
    cudaGetSymbolAddress((void**)&sel, g_sel);
    cudaGetSymbolAddress((void**)&vnw, g_vnew);
    cudaGetSymbolAddress((void**)&y,   g_y);

    cudaFuncSetAttribute(knn_mma_kernel,
                         cudaFuncAttributeMaxDynamicSharedMemorySize, KNN_SMEM_BYTES);
    cudaFuncSetAttribute(mma_gemm_bf16_kernel,
                         cudaFuncAttributeMaxDynamicSharedMemorySize, GM_SMEM_BYTES);
    cudaFuncSetAttribute(flash_mma_kernel,
                         cudaFuncAttributeMaxDynamicSharedMemorySize, FLM_SMEM_BYTES);

    // 0) bf16 hi/lo splits (vectorized, 4 floats/thread)
    split_bf16_v4<<<1024, 256>>>((const float4*)x,
                                 (__nv_bfloat162*)xh, (__nv_bfloat162*)xl);
    split_bf16_v4<<<3072, 256>>>((const float4*)aw,
                                 (__nv_bfloat162*)awh, (__nv_bfloat162*)awl);
    split_bf16_v4<<<1024, 256>>>((const float4*)pw,
                                 (__nv_bfloat162*)pwh, (__nv_bfloat162*)pwl);
    split_bf16_v4<<<8192, 256>>>((const float4*)ks,
                                 (__nv_bfloat162*)mh, (__nv_bfloat162*)ml);
    // 1) qkv = x @ c_attn_w^T + b   (3xBF16 mma)
    mma_gemm_bf16_kernel<<<dim3(24, 16), 256, GM_SMEM_BYTES>>>(
        xh, xl, awh, awl, qkv, 3072, 1024, ab);
    // 2) key_store norms + k/q split/relayout (bf16, q pre-scaled)
    ksnorm_kernel<<<512, 256>>>(ks, ksn);
    split_qk_bf16_kernel<<<2048, 1024>>>(qkv, kh, kl, qh, ql);
    // 3) fused kNN scores + top-4 (bf16 mma, 128-row blocks)
    knn_mma_kernel<<<dim3(8, 16), 256, KNN_SMEM_BYTES>>>(
        kh, kl, mh, ml, ksn, idx);
    // 4) sel from last-row softmax
    selA_kernel<<<dim3(128, 16), 256>>>(qkv, lg);
    selB_kernel<<<16, 1024>>>(lg, sel);
    // 5) 5-way softmax blend -> v_new
    vnew_kernel<<<2048, 256>>>(qkv, ks, vs, idx, sel, vnw);
    // 5b) transpose+split v_new for flash PV
    vtrans_kernel<<<dim3(16, 16), 256>>>(vnw, vth, vtl);
    // 6) fused flash attention on bf16 mma -> y (T,C)
    flash_mma_kernel<<<dim3(8, 16), 256, FLM_SMEM_BYTES>>>(qh, ql, kh, kl, vth, vtl, y);
    // 7) out = y @ c_proj_w^T + b   (3xBF16 mma)
    split_bf16_v4<<<1024, 256>>>((const float4*)y,
                                 (__nv_bfloat162*)yh, (__nv_bfloat162*)yl);
    mma_gemm_bf16_kernel<<<dim3(8, 16), 256, GM_SMEM_BYTES>>>(
        yh, yl, pwh, pwl, out, 1024, 1024, pb);
}

// round 12
// speedup vs baseline: 1.3149x; 1.3149x over previous
#include <cuda_runtime.h>
#include <cuda_bf16.h>
#include <cfloat>
#include <cstdint>

// ---------------- scratch (__device__ globals; no allocations) ----------------
__device__ float g_qkv[1024 * 3072];              // 12 MB  (T, 3C)
__device__ float g_ksnorm[16 * 8192];             // (H, M)
__device__ __nv_bfloat16 g_kh[16 * 1024 * 64];    // bf16-hi of k, [h][t][d]
__device__ __nv_bfloat16 g_kl[16 * 1024 * 64];    // bf16-lo of k
__device__ __nv_bfloat16 g_qh[16 * 1024 * 64];    // bf16-hi of q*0.125, [h][t][d]
__device__ __nv_bfloat16 g_ql[16 * 1024 * 64];    // bf16-lo
__device__ __nv_bfloat16 g_mh[16 * 8192 * 64];    // bf16-hi of key_store
__device__ __nv_bfloat16 g_ml[16 * 8192 * 64];    // bf16-lo of key_store
__device__ __nv_bfloat16 g_xh[1024 * 1024];       // bf16-hi of x
__device__ __nv_bfloat16 g_xl[1024 * 1024];
__device__ __nv_bfloat16 g_awh[3072 * 1024];      // bf16-hi of c_attn_w
__device__ __nv_bfloat16 g_awl[3072 * 1024];
__device__ __nv_bfloat16 g_pwh[1024 * 1024];      // bf16-hi of c_proj_w
__device__ __nv_bfloat16 g_pwl[1024 * 1024];
__device__ __nv_bfloat16 g_yh[1024 * 1024];       // bf16-hi of y
__device__ __nv_bfloat16 g_yl[1024 * 1024];
__device__ __nv_bfloat16 g_vth[16 * 64 * 1024];   // bf16-hi of v_new^T, [h][d][t]
__device__ __nv_bfloat16 g_vtl[16 * 64 * 1024];   // bf16-lo
__device__ float g_lg[16 * 1024];                 // last-row logits
__device__ int   g_idx[16 * 1024 * 4];            // (H, T, 4)
__device__ int   g_sel[16 * 1024];                // (H, T)
__device__ float g_vnew[16 * 1024 * 64];          // (H, T, d)
__device__ float g_y[1024 * 1024];                // (T, C)

// ---------------- helpers ----------------
__device__ __forceinline__ void mma_bf16(float& c0, float& c1, float& c2, float& c3,
                                         uint32_t a0, uint32_t a1, uint32_t a2, uint32_t a3,
                                         uint32_t b0, uint32_t b1) {
    asm volatile(
        "mma.sync.aligned.m16n8k16.row.col.f32.bf16.bf16.f32 "
        "{%0,%1,%2,%3}, {%4,%5,%6,%7}, {%8,%9}, {%0,%1,%2,%3};"
        : "+f"(c0), "+f"(c1), "+f"(c2), "+f"(c3)
        : "r"(a0), "r"(a1), "r"(a2), "r"(a3), "r"(b0), "r"(b1));
}

__device__ __forceinline__ uint32_t pack_bf16(__nv_bfloat16 lo, __nv_bfloat16 hi) {
    __nv_bfloat162 t;
    t.x = lo; t.y = hi;
    return *(uint32_t*)&t;
}

// ---------- vectorized contiguous bf16 hi/lo split (4 floats / thread) ----------
__global__ void split_bf16_v4(const float4* __restrict__ src,
                              __nv_bfloat162* __restrict__ hi,
                              __nv_bfloat162* __restrict__ lo) {
    size_t i = (size_t)blockIdx.x * 256 + threadIdx.x;
    float4 v = src[i];
    __nv_bfloat16 h0 = __float2bfloat16(v.x), h1 = __float2bfloat16(v.y);
    __nv_bfloat16 h2 = __float2bfloat16(v.z), h3 = __float2bfloat16(v.w);
    __nv_bfloat16 l0 = __float2bfloat16(v.x - __bfloat162float(h0));
    __nv_bfloat16 l1 = __float2bfloat16(v.y - __bfloat162float(h1));
    __nv_bfloat16 l2 = __float2bfloat16(v.z - __bfloat162float(h2));
    __nv_bfloat16 l3 = __float2bfloat16(v.w - __bfloat162float(h3));
    hi[i * 2 + 0] = __nv_bfloat162{h0, h1};
    hi[i * 2 + 1] = __nv_bfloat162{h2, h3};
    lo[i * 2 + 0] = __nv_bfloat162{l0, l1};
    lo[i * 2 + 1] = __nv_bfloat162{l2, l3};
}

// -- bf16 hi/lo split of k AND q (scaled 0.125) from qkv, relayout to [h][t][d] --
__global__ void split_qk_bf16_kernel(const float* __restrict__ qkv,
                                     __nv_bfloat16* __restrict__ khi,
                                     __nv_bfloat16* __restrict__ klo,
                                     __nv_bfloat16* __restrict__ qhi,
                                     __nv_bfloat16* __restrict__ qlo) {
    int i = blockIdx.x * 1024 + threadIdx.x;  // 2M
    int which = i >> 20;                      // 0: k, 1: q
    int r = i & 0xFFFFF;
    int d = r & 63, t = (r >> 6) & 1023, h = r >> 16;
    float x = qkv[(size_t)t * 3072 + (which ? 0 : 1024) + h * 64 + d];
    if (which) x *= 0.125f;
    __nv_bfloat16 hf = __float2bfloat16(x);
    __nv_bfloat16 lf = __float2bfloat16(x - __bfloat162float(hf));
    if (which) { qhi[r] = hf; qlo[r] = lf; }
    else       { khi[r] = hf; klo[r] = lf; }
}

// ---- generic 3xBF16 mma GEMM: C = A * B^T + bias  (round-9 validated) ----
#define KAH 72
#define GM_SMEM_BYTES ((64 * KAH * 2 + 128 * KAH * 2) * 2)

__global__ __launch_bounds__(256) void mma_gemm_bf16_kernel(
    const __nv_bfloat16* __restrict__ Ahg, const __nv_bfloat16* __restrict__ Alg,
    const __nv_bfloat16* __restrict__ Bhg, const __nv_bfloat16* __restrict__ Blg,
    float* __restrict__ C, int ldc, int K, const float* __restrict__ bias) {
    extern __shared__ char smc[];
    __nv_bfloat16* Ah = (__nv_bfloat16*)smc;          // [64][72]
    __nv_bfloat16* Al = Ah + 64 * KAH;
    __nv_bfloat16* Bh = Al + 64 * KAH;                // [128][72]
    __nv_bfloat16* Bl = Bh + 128 * KAH;

    const int tid = threadIdx.x;
    const int bx = blockIdx.x, by = blockIdx.y;
    const int w = tid >> 5, lane = tid & 31;
    const int gid = lane >> 2, qid = lane & 3;
    const int rt = (w & 3) * 16;
    const int ch = (w >> 2) * 64;

    const __nv_bfloat16* Ahb = Ahg + (size_t)(by * 64) * K;
    const __nv_bfloat16* Alb = Alg + (size_t)(by * 64) * K;
    const __nv_bfloat16* Bhb = Bhg + (size_t)(bx * 128) * K;
    const __nv_bfloat16* Blb = Blg + (size_t)(bx * 128) * K;

    float c[8][4];
#pragma unroll
    for (int nb = 0; nb < 8; nb++)
#pragma unroll
        for (int k = 0; k < 4; k++) c[nb][k] = 0.f;

    for (int k0 = 0; k0 < K; k0 += 64) {
        __syncthreads();
        for (int i = tid; i < 512; i += 256) {
            int r = i >> 3, c8 = (i & 7) * 8;
            *(uint4*)&Ah[r * KAH + c8] = *(const uint4*)(Ahb + (size_t)r * K + k0 + c8);
            *(uint4*)&Al[r * KAH + c8] = *(const uint4*)(Alb + (size_t)r * K + k0 + c8);
        }
        for (int i = tid; i < 1024; i += 256) {
            int r = i >> 3, c8 = (i & 7) * 8;
            *(uint4*)&Bh[r * KAH + c8] = *(const uint4*)(Bhb + (size_t)r * K + k0 + c8);
            *(uint4*)&Bl[r * KAH + c8] = *(const uint4*)(Blb + (size_t)r * K + k0 + c8);
        }
        __syncthreads();

#pragma unroll
        for (int ks16 = 0; ks16 < 4; ks16++) {
            const int kk = ks16 * 16;
            const int ab = (rt + gid) * KAH + kk + 2 * qid;
            uint32_t ah0 = *(const uint32_t*)&Ah[ab];
            uint32_t ah1 = *(const uint32_t*)&Ah[ab + 8 * KAH];
            uint32_t ah2 = *(const uint32_t*)&Ah[ab + 8];
            uint32_t ah3 = *(const uint32_t*)&Ah[ab + 8 * KAH + 8];
            uint32_t al0 = *(const uint32_t*)&Al[ab];
            uint32_t al1 = *(const uint32_t*)&Al[ab + 8 * KAH];
            uint32_t al2 = *(const uint32_t*)&Al[ab + 8];
            uint32_t al3 = *(const uint32_t*)&Al[ab + 8 * KAH + 8];
#pragma unroll
            for (int nb = 0; nb < 8; nb++) {
                const int bb = (ch + nb * 8 + gid) * KAH + kk + 2 * qid;
                uint32_t bh0 = *(const uint32_t*)&Bh[bb];
                uint32_t bh1 = *(const uint32_t*)&Bh[bb + 8];
                uint32_t bl0 = *(const uint32_t*)&Bl[bb];
                uint32_t bl1 = *(const uint32_t*)&Bl[bb + 8];
                mma_bf16(c[nb][0], c[nb][1], c[nb][2], c[nb][3],
                         ah0, ah1, ah2, ah3, bh0, bh1);
                mma_bf16(c[nb][0], c[nb][1], c[nb][2], c[nb][3],
                         ah0, ah1, ah2, ah3, bl0, bl1);
                mma_bf16(c[nb][0], c[nb][1], c[nb][2], c[nb][3],
                         al0, al1, al2, al3, bh0, bh1);
            }
        }
    }

#pragma unroll
    for (int nb = 0; nb < 8; nb++) {
#pragma unroll
        for (int k = 0; k < 4; k++) {
            int row = by * 64 + rt + gid + (k >> 1) * 8;
            int col = bx * 128 + ch + nb * 8 + 2 * qid + (k & 1);
            C[(size_t)row * ldc + col] = c[nb][k] + bias[col];
        }
    }
}

// ---------------- ||key_store[h,m]||^2 (exact fp32) ----------------
__global__ void ksnorm_kernel(const float* __restrict__ ks, float* __restrict__ nrm) {
    int r = blockIdx.x * blockDim.x + threadIdx.x;
    if (r >= 16 * 8192) return;
    const float4* p = (const float4*)(ks + (size_t)r * 64);
    float s = 0.f;
#pragma unroll
    for (int i = 0; i < 16; i++) {
        float4 f = p[i];
        s += f.x * f.x + f.y * f.y + f.z * f.z + f.w * f.w;
    }
    nrm[r] = s;
}

// ------------- lexicographic (score, idx) compare: stable top-k --------------
__device__ __forceinline__ bool lex_lt(float sa, int ia, float sb, int ib) {
    return sa < sb || (sa == sb && ia < ib);
}

#define TOP4_INSERT(v, m, s0, x0, s1, x1, s2, x2, s3, x3)              \
    if (lex_lt(v, m, s3, x3)) {                                        \
        if (lex_lt(v, m, s2, x2)) {                                    \
            s3 = s2; x3 = x2;                                          \
            if (lex_lt(v, m, s1, x1)) {                                \
                s2 = s1; x2 = x1;                                      \
                if (lex_lt(v, m, s0, x0)) {                            \
                    s1 = s0; x1 = x0; s0 = v; x0 = m;                  \
                } else { s1 = v; x1 = m; }                             \
            } else { s2 = v; x2 = m; }                                 \
        } else { s3 = v; x3 = m; }                                     \
    }

// ---- fused kNN scores + top-4 via bf16 tensor cores (round-10 validated, 64-row) ----
#define KNN_SMEM_BYTES ((64 * KAH * 2 + 128 * KAH * 2) * 2 + 128 * 4)

__global__ __launch_bounds__(256) void knn_mma_kernel(
    const __nv_bfloat16* __restrict__ kh, const __nv_bfloat16* __restrict__ kl,
    const __nv_bfloat16* __restrict__ mh, const __nv_bfloat16* __restrict__ ml,
    const float* __restrict__ ksn, int* __restrict__ idx_out) {
    extern __shared__ char smc[];
    __nv_bfloat16* Ah = (__nv_bfloat16*)smc;          // [64][72]
    __nv_bfloat16* Al = Ah + 64 * KAH;
    __nv_bfloat16* Bh = Al + 64 * KAH;                // [128][72]
    __nv_bfloat16* Bl = Bh + 128 * KAH;
    float* Ns = (float*)(Bl + 128 * KAH);             // [128]

    const int tid = threadIdx.x;
    const int t0 = blockIdx.x * 64;
    const int h = blockIdx.y;
    const int w = tid >> 5, lane = tid & 31;
    const int gid = lane >> 2, qid = lane & 3;
    const int rt = (w & 3) * 16;
    const int ch = (w >> 2) * 64;

    const __nv_bfloat16* Ahg = kh + ((size_t)h * 1024 + t0) * 64;
    const __nv_bfloat16* Alg = kl + ((size_t)h * 1024 + t0) * 64;
    for (int i = tid; i < 512; i += 256) {
        int r = i >> 3, c8 = (i & 7) * 8;
        *(uint4*)&Ah[r * KAH + c8] = *(const uint4*)(Ahg + (size_t)r * 64 + c8);
        *(uint4*)&Al[r * KAH + c8] = *(const uint4*)(Alg + (size_t)r * 64 + c8);
    }

    float S[2][4];
    int I[2][4];
#pragma unroll
    for (int r = 0; r < 2; r++)
#pragma unroll
        for (int k = 0; k < 4; k++) { S[r][k] = FLT_MAX; I[r][k] = 0x7fffffff; }

    const __nv_bfloat16* Bhg = mh + (size_t)h * 8192 * 64;
    const __nv_bfloat16* Blg = ml + (size_t)h * 8192 * 64;
    const float* Nbase = ksn + h * 8192;

    for (int chunk = 0; chunk < 64; chunk++) {
        const int m0 = chunk << 7;
        __syncthreads();
        if (tid < 128) Ns[tid] = Nbase[m0 + tid];
        for (int i = tid; i < 1024; i += 256) {
            int r = i >> 3, c8 = (i & 7) * 8;
            *(uint4*)&Bh[r * KAH + c8] = *(const uint4*)(Bhg + (size_t)(m0 + r) * 64 + c8);
            *(uint4*)&Bl[r * KAH + c8] = *(const uint4*)(Blg + (size_t)(m0 + r) * 64 + c8);
        }
        __syncthreads();

        float c[8][4];
#pragma unroll
        for (int nb = 0; nb < 8; nb++)
#pragma unroll
            for (int k = 0; k < 4; k++) c[nb][k] = 0.f;

#pragma unroll
        for (int ks16 = 0; ks16 < 4; ks16++) {
            const int k0 = ks16 * 16;
            const int ab = (rt + gid) * KAH + k0 + 2 * qid;
            uint32_t ah0 = *(const uint32_t*)&Ah[ab];
            uint32_t ah1 = *(const uint32_t*)&Ah[ab + 8 * KAH];
            uint32_t ah2 = *(const uint32_t*)&Ah[ab + 8];
            uint32_t ah3 = *(const uint32_t*)&Ah[ab + 8 * KAH + 8];
            uint32_t al0 = *(const uint32_t*)&Al[ab];
            uint32_t al1 = *(const uint32_t*)&Al[ab + 8 * KAH];
            uint32_t al2 = *(const uint32_t*)&Al[ab + 8];
            uint32_t al3 = *(const uint32_t*)&Al[ab + 8 * KAH + 8];
#pragma unroll
            for (int nb = 0; nb < 8; nb++) {
                const int bb = (ch + nb * 8 + gid) * KAH + k0 + 2 * qid;
                uint32_t bh0 = *(const uint32_t*)&Bh[bb];
                uint32_t bh1 = *(const uint32_t*)&Bh[bb + 8];
                uint32_t bl0 = *(const uint32_t*)&Bl[bb];
                uint32_t bl1 = *(const uint32_t*)&Bl[bb + 8];
                mma_bf16(c[nb][0], c[nb][1], c[nb][2], c[nb][3],
                         ah0, ah1, ah2, ah3, bh0, bh1);
                mma_bf16(c[nb][0], c[nb][1], c[nb][2], c[nb][3],
                         ah0, ah1, ah2, ah3, bl0, bl1);
                mma_bf16(c[nb][0], c[nb][1], c[nb][2], c[nb][3],
                         al0, al1, al2, al3, bh0, bh1);
            }
        }

#pragma unroll
        for (int nb = 0; nb < 8; nb++) {
#pragma unroll
            for (int k = 0; k < 4; k++) {
                int cl = ch + nb * 8 + 2 * qid + (k & 1);
                int r = k >> 1;
                float v = Ns[cl] - 2.0f * c[nb][k];
                int mg = m0 + cl;
                TOP4_INSERT(v, mg, S[r][0], I[r][0], S[r][1], I[r][1],
                            S[r][2], I[r][2], S[r][3], I[r][3]);
            }
        }
    }

    __syncthreads();
    float* msc = (float*)smc;                 // [64][32]
    int* mix = (int*)(smc + 16384);
    const int slot = (w >> 2) * 4 + qid;
#pragma unroll
    for (int r = 0; r < 2; r++) {
        int row = rt + gid + r * 8;
#pragma unroll
        for (int k = 0; k < 4; k++) {
            msc[(row * 8 + slot) * 4 + k] = S[r][k];
            mix[(row * 8 + slot) * 4 + k] = I[r][k];
        }
    }
    __syncthreads();
    if (tid < 64) {
        float f0 = FLT_MAX, f1 = FLT_MAX, f2 = FLT_MAX, f3 = FLT_MAX;
        int g0 = 0x7fffffff, g1 = 0x7fffffff, g2 = 0x7fffffff, g3 = 0x7fffffff;
        for (int c2 = 0; c2 < 32; c2++) {
            float v = msc[tid * 32 + c2];
            int m = mix[tid * 32 + c2];
            TOP4_INSERT(v, m, f0, g0, f1, g1, f2, g2, f3, g3);
        }
        size_t row = (size_t)h * 1024 + t0 + tid;
        idx_out[row * 4 + 0] = g0;
        idx_out[row * 4 + 1] = g1;
        idx_out[row * 4 + 2] = g2;
        idx_out[row * 4 + 3] = g3;
    }
}

// ---------------- warp-per-token last-row logits ----------------
__global__ void selA_kernel(const float* __restrict__ qkv, float* __restrict__ lg) {
    int h = blockIdx.y;
    int t = blockIdx.x * 8 + (threadIdx.x >> 5);
    int lane = threadIdx.x & 31;
    int d0 = lane * 2;
    const float* q = qkv + (size_t)1023 * 3072 + h * 64;
    const float* k = qkv + (size_t)t * 3072 + 1024 + h * 64;
    float s = q[d0] * k[d0] + q[d0 + 1] * k[d0 + 1];
#pragma unroll
    for (int o = 16; o > 0; o >>= 1) s += __shfl_xor_sync(0xffffffffu, s, o);
    if (lane == 0) lg[h * 1024 + t] = s * 0.125f;
}

// ---------------- per-head softmax of logits row -> sel ----------------
__global__ void selB_kernel(const float* __restrict__ lg, int* __restrict__ sel) {
    int h = blockIdx.x;
    int tid = threadIdx.x;
    int lane = tid & 31, warp = tid >> 5;
    __shared__ float red[8];
    __shared__ float bcast;

    float v[4];
#pragma unroll
    for (int u = 0; u < 4; u++) v[u] = lg[h * 1024 + tid + u * 256];
    float m = fmaxf(fmaxf(v[0], v[1]), fmaxf(v[2], v[3]));
#pragma unroll
    for (int o = 16; o > 0; o >>= 1) m = fmaxf(m, __shfl_xor_sync(0xffffffffu, m, o));
    if (lane == 0) red[warp] = m;
    __syncthreads();
    if (tid == 0) {
        float x = red[0];
#pragma unroll
        for (int w = 1; w < 8; w++) x = fmaxf(x, red[w]);
        bcast = x;
    }
    __syncthreads();
    m = bcast;
    float e[4], s = 0.f;
#pragma unroll
    for (int u = 0; u < 4; u++) { e[u] = __expf(v[u] - m); s += e[u]; }
#pragma unroll
    for (int o = 16; o > 0; o >>= 1) s += __shfl_xor_sync(0xffffffffu, s, o);
    if (lane == 0) red[warp] = s;
    __syncthreads();
    if (tid == 0) {
        float x = 0.f;
#pragma unroll
        for (int w = 0; w < 8; w++) x += red[w];
        bcast = x;
    }
    __syncthreads();
    float inv = 1.f / bcast;
#pragma unroll
    for (int u = 0; u < 4; u++)
        sel[h * 1024 + tid + u * 256] = (e[u] * inv >= (1.0f / 8192.0f)) ? 1 : 0;
}

// ---------------- per-token 5-way memory softmax & blend -> v_new ----------------
__device__ __forceinline__ float warp_sum(float v) {
#pragma unroll
    for (int o = 16; o > 0; o >>= 1) v += __shfl_xor_sync(0xffffffffu, v, o);
    return v;
}

__global__ void vnew_kernel(const float* __restrict__ qkv, const float* __restrict__ kstore,
                            const float* __restrict__ vstore, const int* __restrict__ idx,
                            const int* __restrict__ sel, float* __restrict__ vnew) {
    int gw = (blockIdx.x * blockDim.x + threadIdx.x) >> 5;
    int lane = threadIdx.x & 31;
    if (gw >= 16 * 1024) return;
    int h = gw >> 10, t = gw & 1023;

    const float* base = qkv + (size_t)t * 3072 + h * 64;
    int d0 = lane * 2;
    float q0 = base[d0],        q1 = base[d0 + 1];
    float k0 = base[1024 + d0], k1 = base[1024 + d0 + 1];
    float v0 = base[2048 + d0], v1 = base[2048 + d0 + 1];
    const float scale = 0.125f;

    float attf[5];
    attf[0] = warp_sum(q0 * k0 + q1 * k1) * scale;

    int ids[4];
#pragma unroll
    for (int s2 = 0; s2 < 4; s2++) ids[s2] = idx[(size_t)gw * 4 + s2];

    float fv0[4], fv1[4];
#pragma unroll
    for (int s2 = 0; s2 < 4; s2++) {
        const float* kp = kstore + ((size_t)h * 8192 + ids[s2]) * 64;
        attf[s2 + 1] = warp_sum(q0 * kp[d0] + q1 * kp[d0 + 1]) * scale;
        const float* vp = vstore + ((size_t)h * 8192 + ids[s2]) * 64;
        fv0[s2] = vp[d0]; fv1[s2] = vp[d0 + 1];
    }

    float mx = attf[0];
#pragma unroll
    for (int s2 = 1; s2 < 5; s2++) mx = fmaxf(mx, attf[s2]);
    float e[5], sum = 0.f;
#pragma unroll
    for (int s2 = 0; s2 < 5; s2++) { e[s2] = expf(attf[s2] - mx); sum += e[s2]; }
    float inv = 1.f / sum;

    float o0 = e[0] * v0, o1 = e[0] * v1;
#pragma unroll
    for (int s2 = 0; s2 < 4; s2++) { o0 += e[s2 + 1] * fv0[s2]; o1 += e[s2 + 1] * fv1[s2]; }
    o0 = o0 * inv * 0.5f + v0 * 0.5f;
    o1 = o1 * inv * 0.5f + v1 * 0.5f;

    bool sl = sel[gw] != 0;
    vnew[(size_t)gw * 64 + d0]     = sl ? o0 : v0;
    vnew[(size_t)gw * 64 + d0 + 1] = sl ? o1 : v1;
}

// ------- transpose+split v_new to bf16 hi/lo, [h][d][t] layout (for flash PV) -------
__global__ void vtrans_kernel(const float* __restrict__ vnew,
                              __nv_bfloat16* __restrict__ vth,
                              __nv_bfloat16* __restrict__ vtl) {
    __shared__ float sm[64][65];
    const int tid = threadIdx.x;
    const int t0 = blockIdx.x * 64, h = blockIdx.y;
    for (int i = tid; i < 4096; i += 256) {
        int tr = i >> 6, d = i & 63;
        sm[tr][d] = vnew[((size_t)h * 1024 + t0 + tr) * 64 + d];
    }
    __syncthreads();
    for (int i = tid; i < 4096; i += 256) {
        int d = i >> 6, tr = i & 63;
        float x = sm[tr][d];
        __nv_bfloat16 hh = __float2bfloat16(x);
        size_t o = ((size_t)h * 64 + d) * 1024 + t0 + tr;
        vth[o] = hh;
        vtl[o] = __float2bfloat16(x - __bfloat162float(hh));
    }
}

// ------- fused flash attention on bf16 mma: y = softmax_causal(qk^T/8) @ v_new -------
// Block: 256 thr (8 warps), 128 q-rows x one head. Warp w: rows w*16..w*16+15, all 64 cols.
// smem: Qh/Ql [128][72], Kh/Kl [64][72] (s-major), Vh/Vl [64][72] (d-major, pre-split)
#define FLM_SMEM_BYTES ((128 * KAH * 2 + 64 * KAH * 2 + 64 * KAH * 2) * 2)

__global__ __launch_bounds__(256) void flash_mma_kernel(
    const __nv_bfloat16* __restrict__ qhg, const __nv_bfloat16* __restrict__ qlg,
    const __nv_bfloat16* __restrict__ khg, const __nv_bfloat16* __restrict__ klg,
    const __nv_bfloat16* __restrict__ vth, const __nv_bfloat16* __restrict__ vtl,
    float* __restrict__ y) {
    extern __shared__ char smc[];
    __nv_bfloat16* Qh = (__nv_bfloat16*)smc;          // [128][72]
    __nv_bfloat16* Ql = Qh + 128 * KAH;
    __nv_bfloat16* Kh = Ql + 128 * KAH;               // [64][72]
    __nv_bfloat16* Kl = Kh + 64 * KAH;
    __nv_bfloat16* Vh = Kl + 64 * KAH;                // [64][72]  (row = d, col = s)
    __nv_bfloat16* Vl = Vh + 64 * KAH;

    const int tid = threadIdx.x;
    const int qb = blockIdx.x, h = blockIdx.y;
    const int w = tid >> 5, lane = tid & 31;
    const int gid = lane >> 2, qid = lane & 3;
    const int rt = w * 16;
    const int t0 = qb * 128;

    // Q tiles (pre-scaled by 0.125 at split time)
    const __nv_bfloat16* Qhg = qhg + ((size_t)h * 1024 + t0) * 64;
    const __nv_bfloat16* Qlg = qlg + ((size_t)h * 1024 + t0) * 64;
    for (int i = tid; i < 1024; i += 256) {
        int r = i >> 3, c8 = (i & 7) * 8;
        *(uint4*)&Qh[r * KAH + c8] = *(const uint4*)(Qhg + (size_t)r * 64 + c8);
        *(uint4*)&Ql[r * KAH + c8] = *(const uint4*)(Qlg + (size_t)r * 64 + c8);
    }

    float m0 = -FLT_MAX, m1 = -FLT_MAX, l0 = 0.f, l1 = 0.f;
    float O[8][4];
#pragma unroll
    for (int nb = 0; nb < 8; nb++)
#pragma unroll
        for (int k = 0; k < 4; k++) O[nb][k] = 0.f;

    const int row0 = t0 + rt + gid, row1 = row0 + 8;
    const int nj = 2 * qb + 2;

    for (int j = 0; j < nj; j++) {
        const int s0 = j * 64;
        __syncthreads();  // prior PV reads done (and Q loads on first iter)
        const __nv_bfloat16* Khg = khg + ((size_t)h * 1024 + s0) * 64;
        const __nv_bfloat16* Klg = klg + ((size_t)h * 1024 + s0) * 64;
        for (int i = tid; i < 512; i += 256) {
            int r = i >> 3, c8 = (i & 7) * 8;
            *(uint4*)&Kh[r * KAH + c8] = *(const uint4*)(Khg + (size_t)r * 64 + c8);
            *(uint4*)&Kl[r * KAH + c8] = *(const uint4*)(Klg + (size_t)r * 64 + c8);
        }
        // V tile: pre-split bf16 [d][t], direct copy
        const __nv_bfloat16* Vhg = vth + (size_t)h * 64 * 1024 + s0;
        const __nv_bfloat16* Vlg = vtl + (size_t)h * 64 * 1024 + s0;
        for (int i = tid; i < 512; i += 256) {
            int r = i >> 3, c8 = (i & 7) * 8;
            *(uint4*)&Vh[r * KAH + c8] = *(const uint4*)(Vhg + (size_t)r * 1024 + c8);
            *(uint4*)&Vl[r * KAH + c8] = *(const uint4*)(Vlg + (size_t)r * 1024 + c8);
        }
        __syncthreads();

        // S = Q K^T (3xBF16): warp rows rt..rt+15, cols 0..63
        float c[8][4];
#pragma unroll
        for (int nb = 0; nb < 8; nb++)
#pragma unroll
            for (int k = 0; k < 4; k++) c[nb][k] = 0.f;

#pragma unroll
        for (int ks16 = 0; ks16 < 4; ks16++) {
            const int kk = ks16 * 16;
            const int ab = (rt + gid) * KAH + kk + 2 * qid;
            uint32_t ah0 = *(const uint32_t*)&Qh[ab];
            uint32_t ah1 = *(const uint32_t*)&Qh[ab + 8 * KAH];
            uint32_t ah2 = *(const uint32_t*)&Qh[ab + 8];
            uint32_t ah3 = *(const uint32_t*)&Qh[ab + 8 * KAH + 8];
            uint32_t al0 = *(const uint32_t*)&Ql[ab];
            uint32_t al1 = *(const uint32_t*)&Ql[ab + 8 * KAH];
            uint32_t al2 = *(const uint32_t*)&Ql[ab + 8];
            uint32_t al3 = *(const uint32_t*)&Ql[ab + 8 * KAH + 8];
#pragma unroll
            for (int nb = 0; nb < 8; nb++) {
                const int bb = (nb * 8 + gid) * KAH + kk + 2 * qid;
                uint32_t bh0 = *(const uint32_t*)&Kh[bb];
                uint32_t bh1 = *(const uint32_t*)&Kh[bb + 8];
                uint32_t bl0 = *(const uint32_t*)&Kl[bb];
                uint32_t bl1 = *(const uint32_t*)&Kl[bb + 8];
                mma_bf16(c[nb][0], c[nb][1], c[nb][2], c[nb][3],
                         ah0, ah1, ah2, ah3, bh0, bh1);
                mma_bf16(c[nb][0], c[nb][1], c[nb][2], c[nb][3],
                         ah0, ah1, ah2, ah3, bl0, bl1);
                mma_bf16(c[nb][0], c[nb][1], c[nb][2], c[nb][3],
                         al0, al1, al2, al3, bh0, bh1);
            }
        }

        // causal mask (only blocks that can cross the diagonal for this warp)
        if (s0 + 63 > t0 + rt) {
#pragma unroll
            for (int nb = 0; nb < 8; nb++) {
                int cb = s0 + nb * 8 + 2 * qid;
                if (cb > row0)     c[nb][0] = -FLT_MAX;
                if (cb + 1 > row0) c[nb][1] = -FLT_MAX;
                if (cb > row1)     c[nb][2] = -FLT_MAX;
                if (cb + 1 > row1) c[nb][3] = -FLT_MAX;
            }
        }

        // online softmax: row stats across this thread's 16 cols + 4 qid lanes
        float rm0 = -FLT_MAX, rm1 = -FLT_MAX;
#pragma unroll
        for (int nb = 0; nb < 8; nb++) {
            rm0 = fmaxf(rm0, fmaxf(c[nb][0], c[nb][1]));
            rm1 = fmaxf(rm1, fmaxf(c[nb][2], c[nb][3]));
        }
        rm0 = fmaxf(rm0, __shfl_xor_sync(0xffffffffu, rm0, 1));
        rm0 = fmaxf(rm0, __shfl_xor_sync(0xffffffffu, rm0, 2));
        rm1 = fmaxf(rm1, __shfl_xor_sync(0xffffffffu, rm1, 1));
        rm1 = fmaxf(rm1, __shfl_xor_sync(0xffffffffu, rm1, 2));

        float mn0 = fmaxf(m0, rm0), mn1 = fmaxf(m1, rm1);
        float alpha0 = __expf(m0 - mn0), alpha1 = __expf(m1 - mn1);
        float ps0 = 0.f, ps1 = 0.f;
#pragma unroll
        for (int nb = 0; nb < 8; nb++) {
            c[nb][0] = __expf(c[nb][0] - mn0); ps0 += c[nb][0];
            c[nb][1] = __expf(c[nb][1] - mn0); ps0 += c[nb][1];
            c[nb][2] = __expf(c[nb][2] - mn1); ps1 += c[nb][2];
            c[nb][3] = __expf(c[nb][3] - mn1); ps1 += c[nb][3];
        }
        ps0 += __shfl_xor_sync(0xffffffffu, ps0, 1);
        ps0 += __shfl_xor_sync(0xffffffffu, ps0, 2);
        ps1 += __shfl_xor_sync(0xffffffffu, ps1, 1);
        ps1 += __shfl_xor_sync(0xffffffffu, ps1, 2);
        l0 = l0 * alpha0 + ps0; m0 = mn0;
        l1 = l1 * alpha1 + ps1; m1 = mn1;
#pragma unroll
        for (int nb = 0; nb < 8; nb++) {
            O[nb][0] *= alpha0; O[nb][1] *= alpha0;
            O[nb][2] *= alpha1; O[nb][3] *= alpha1;
        }

        // P@V: P (C-frag) is bitwise the A-frag layout — register-only conversion
#pragma unroll
        for (int kb = 0; kb < 4; kb++) {
            float p00 = c[2 * kb][0],     p01 = c[2 * kb][1];
            float p02 = c[2 * kb][2],     p03 = c[2 * kb][3];
            float p10 = c[2 * kb + 1][0], p11 = c[2 * kb + 1][1];
            float p12 = c[2 * kb + 1][2], p13 = c[2 * kb + 1][3];
            __nv_bfloat16 h00 = __float2bfloat16(p00), h01 = __float2bfloat16(p01);
            __nv_bfloat16 h02 = __float2bfloat16(p02), h03 = __float2bfloat16(p03);
            __nv_bfloat16 h10 = __float2bfloat16(p10), h11 = __float2bfloat16(p11);
            __nv_bfloat16 h12 = __float2bfloat16(p12), h13 = __float2bfloat16(p13);
            uint32_t Ah0 = pack_bf16(h00, h01);
            uint32_t Ah1 = pack_bf16(h02, h03);
            uint32_t Ah2 = pack_bf16(h10, h11);
            uint32_t Ah3 = pack_bf16(h12, h13);
            uint32_t Al0 = pack_bf16(__float2bfloat16(p00 - __bfloat162float(h00)),
                                     __float2bfloat16(p01 - __bfloat162float(h01)));
            uint32_t Al1 = pack_bf16(__float2bfloat16(p02 - __bfloat162float(h02)),
                                     __float2bfloat16(p03 - __bfloat162float(h03)));
            uint32_t Al2 = pack_bf16(__float2bfloat16(p10 - __bfloat162float(h10)),
                                     __float2bfloat16(p11 - __bfloat162float(h11)));
            uint32_t Al3 = pack_bf16(__float2bfloat16(p12 - __bfloat162float(h12)),
                                     __float2bfloat16(p13 - __bfloat162float(h13)));
#pragma unroll
            for (int nb = 0; nb < 8; nb++) {
                const int bb = (nb * 8 + gid) * KAH + kb * 16 + 2 * qid;
                uint32_t bh0 = *(const uint32_t*)&Vh[bb];
                uint32_t bh1 = *(const uint32_t*)&Vh[bb + 8];
                uint32_t bl0 = *(const uint32_t*)&Vl[bb];
                uint32_t bl1 = *(const uint32_t*)&Vl[bb + 8];
                mma_bf16(O[nb][0], O[nb][1], O[nb][2], O[nb][3],
                         Ah0, Ah1, Ah2, Ah3, bh0, bh1);
                mma_bf16(O[nb][0], O[nb][1], O[nb][2], O[nb][3],
                         Ah0, Ah1, Ah2, Ah3, bl0, bl1);
                mma_bf16(O[nb][0], O[nb][1], O[nb][2], O[nb][3],
                         Al0, Al1, Al2, Al3, bh0, bh1);
            }
        }
    }

    // epilogue: y[t][h*64 + d] = O / l
    float inv0 = 1.f / l0, inv1 = 1.f / l1;
#pragma unroll
    for (int nb = 0; nb < 8; nb++) {
        int colb = h * 64 + nb * 8 + 2 * qid;
        y[(size_t)row0 * 1024 + colb]     = O[nb][0] * inv0;
        y[(size_t)row0 * 1024 + colb + 1] = O[nb][1] * inv0;
        y[(size_t)row1 * 1024 + colb]     = O[nb][2] * inv1;
        y[(size_t)row1 * 1024 + colb + 1] = O[nb][3] * inv1;
    }
}

// ---------------- launch ----------------
extern "C" void kernel_launch(void* const* d_in, const int* in_sizes, int n_in,
                              void* d_out, int out_size) {
    const float* x  = (const float*)d_in[0];
    const float* aw = (const float*)d_in[1];
    const float* ab = (const float*)d_in[2];
    const float* pw = (const float*)d_in[3];
    const float* pb = (const float*)d_in[4];
    const float* ks = (const float*)d_in[5];
    const float* vs = (const float*)d_in[6];
    float* out = (float*)d_out;

    float *qkv, *ksn, *lg, *vnw, *y;
    __nv_bfloat16 *kh, *kl, *qh, *ql, *mh, *ml, *xh, *xl, *awh, *awl, *pwh, *pwl, *yh, *yl;
    __nv_bfloat16 *vth, *vtl;
    int *idx, *sel;
    cudaGetSymbolAddress((void**)&qkv, g_qkv);
    cudaGetSymbolAddress((void**)&ksn, g_ksnorm);
    cudaGetSymbolAddress((void**)&kh,  g_kh);
    cudaGetSymbolAddress((void**)&kl,  g_kl);
    cudaGetSymbolAddress((void**)&qh,  g_qh);
    cudaGetSymbolAddress((void**)&ql,  g_ql);
    cudaGetSymbolAddress((void**)&mh,  g_mh);
    cudaGetSymbolAddress((void**)&ml,  g_ml);
    cudaGetSymbolAddress((void**)&xh,  g_xh);
    cudaGetSymbolAddress((void**)&xl,  g_xl);
    cudaGetSymbolAddress((void**)&awh, g_awh);
    cudaGetSymbolAddress((void**)&awl, g_awl);
    cudaGetSymbolAddress((void**)&pwh, g_pwh);
    cudaGetSymbolAddress((void**)&pwl, g_pwl);
    cudaGetSymbolAddress((void**)&yh,  g_yh);
    cudaGetSymbolAddress((void**)&yl,  g_yl);
    cudaGetSymbolAddress((void**)&vth, g_vth);
    cudaGetSymbolAddress((void**)&vtl, g_vtl);
    cudaGetSymbolAddress((void**)&lg,  g_lg);
    cudaGetSymbolAddress((void**)&idx, g_idx);
    cudaGetSymbolAddress((void**)&sel, g_sel);
    cudaGetSymbolAddress((void**)&vnw, g_vnew);
    cudaGetSymbolAddress((void**)&y,   g_y);

    cudaFuncSetAttribute(knn_mma_kernel,
                         cudaFuncAttributeMaxDynamicSharedMemorySize, KNN_SMEM_BYTES);
    cudaFuncSetAttribute(mma_gemm_bf16_kernel,
                         cudaFuncAttributeMaxDynamicSharedMemorySize, GM_SMEM_BYTES);
    cudaFuncSetAttribute(flash_mma_kernel,
                         cudaFuncAttributeMaxDynamicSharedMemorySize, FLM_SMEM_BYTES);

    // 0) bf16 hi/lo splits (vectorized, 4 floats/thread)
    split_bf16_v4<<<1024, 256>>>((const float4*)x,
                                 (__nv_bfloat162*)xh, (__nv_bfloat162*)xl);
    split_bf16_v4<<<3072, 256>>>((const float4*)aw,
                                 (__nv_bfloat162*)awh, (__nv_bfloat162*)awl);
    split_bf16_v4<<<1024, 256>>>((const float4*)pw,
                                 (__nv_bfloat162*)pwh, (__nv_bfloat162*)pwl);
    split_bf16_v4<<<8192, 256>>>((const float4*)ks,
                                 (__nv_bfloat162*)mh, (__nv_bfloat162*)ml);
    // 1) qkv = x @ c_attn_w^T + b   (3xBF16 mma)
    mma_gemm_bf16_kernel<<<dim3(24, 16), 256, GM_SMEM_BYTES>>>(
        xh, xl, awh, awl, qkv, 3072, 1024, ab);
    // 2) key_store norms + k/q split/relayout (bf16, q pre-scaled)
    ksnorm_kernel<<<512, 256>>>(ks, ksn);
    split_qk_bf16_kernel<<<2048, 1024>>>(qkv, kh, kl, qh, ql);
    // 3) fused kNN scores + top-4 (bf16 mma, 64-row blocks — round-10 known-good)
    knn_mma_kernel<<<dim3(16, 16), 256, KNN_SMEM_BYTES>>>(
        kh, kl, mh, ml, ksn, idx);
    // 4) sel from last-row softmax
    selA_kernel<<<dim3(128, 16), 256>>>(qkv, lg);
    selB_kernel<<<16, 1024>>>(lg, sel);
    // 5) 5-way softmax blend -> v_new
    vnew_kernel<<<2048, 256>>>(qkv, ks, vs, idx, sel, vnw);
    // 5b) transpose+split v_new for flash PV
    vtrans_kernel<<<dim3(16, 16), 256>>>(vnw, vth, vtl);
    // 6) fused flash attention on bf16 mma -> y (T,C)
    flash_mma_kernel<<<dim3(8, 16), 256, FLM_SMEM_BYTES>>>(qh, ql, kh, kl, vth, vtl, y);
    // 7) out = y @ c_proj_w^T + b   (3xBF16 mma)
    split_bf16_v4<<<1024, 256>>>((const float4*)y,
                                 (__nv_bfloat162*)yh, (__nv_bfloat162*)yl);
    mma_gemm_bf16_kernel<<<dim3(8, 16), 256, GM_SMEM_BYTES>>>(
        yh, yl, pwh, pwl, out, 1024, 1024, pb);
}

// round 13
// speedup vs baseline: 1.3592x; 1.0336x over previous
#include <cuda_runtime.h>
#include <cuda_bf16.h>
#include <cfloat>
#include <cstdint>

// ---------------- scratch (__device__ globals; no allocations) ----------------
__device__ float g_qkv[1024 * 3072];              // 12 MB  (T, 3C)
__device__ float g_ksnorm[16 * 8192];             // (H, M)
__device__ __nv_bfloat16 g_kh[16 * 1024 * 64];    // bf16-hi of k, [h][t][d]
__device__ __nv_bfloat16 g_kl[16 * 1024 * 64];    // bf16-lo of k
__device__ __nv_bfloat16 g_qh[16 * 1024 * 64];    // bf16-hi of q*0.125, [h][t][d]
__device__ __nv_bfloat16 g_ql[16 * 1024 * 64];    // bf16-lo
__device__ __nv_bfloat16 g_mh[16 * 8192 * 64];    // bf16-hi of key_store
__device__ __nv_bfloat16 g_ml[16 * 8192 * 64];    // bf16-lo of key_store
__device__ __nv_bfloat16 g_xh[1024 * 1024];       // bf16-hi of x
__device__ __nv_bfloat16 g_xl[1024 * 1024];
__device__ __nv_bfloat16 g_awh[3072 * 1024];      // bf16-hi of c_attn_w
__device__ __nv_bfloat16 g_awl[3072 * 1024];
__device__ __nv_bfloat16 g_pwh[1024 * 1024];      // bf16-hi of c_proj_w
__device__ __nv_bfloat16 g_pwl[1024 * 1024];
__device__ __nv_bfloat16 g_yh[1024 * 1024];       // bf16-hi of y
__device__ __nv_bfloat16 g_yl[1024 * 1024];
__device__ __nv_bfloat16 g_vth[16 * 64 * 1024];   // bf16-hi of v_new^T, [h][d][t]
__device__ __nv_bfloat16 g_vtl[16 * 64 * 1024];   // bf16-lo
__device__ float g_pO[2 * 16 * 1024 * 64];        // flash partial O [half][h][t][d]
__device__ float g_pm[2 * 16 * 1024];             // flash partial row max
__device__ float g_pl[2 * 16 * 1024];             // flash partial row sum
__device__ float g_lg[16 * 1024];                 // last-row logits
__device__ int   g_idx[16 * 1024 * 4];            // (H, T, 4)
__device__ int   g_sel[16 * 1024];                // (H, T)
__device__ float g_vnew[16 * 1024 * 64];          // (H, T, d)
__device__ float g_y[1024 * 1024];                // (T, C)

// ---------------- helpers ----------------
__device__ __forceinline__ void mma_bf16(float& c0, float& c1, float& c2, float& c3,
                                         uint32_t a0, uint32_t a1, uint32_t a2, uint32_t a3,
                                         uint32_t b0, uint32_t b1) {
    asm volatile(
        "mma.sync.aligned.m16n8k16.row.col.f32.bf16.bf16.f32 "
        "{%0,%1,%2,%3}, {%4,%5,%6,%7}, {%8,%9}, {%0,%1,%2,%3};"
        : "+f"(c0), "+f"(c1), "+f"(c2), "+f"(c3)
        : "r"(a0), "r"(a1), "r"(a2), "r"(a3), "r"(b0), "r"(b1));
}

__device__ __forceinline__ uint32_t pack_bf16(__nv_bfloat16 lo, __nv_bfloat16 hi) {
    __nv_bfloat162 t;
    t.x = lo; t.y = hi;
    return *(uint32_t*)&t;
}

// ---------- vectorized contiguous bf16 hi/lo split (4 floats / thread) ----------
__global__ void split_bf16_v4(const float4* __restrict__ src,
                              __nv_bfloat162* __restrict__ hi,
                              __nv_bfloat162* __restrict__ lo) {
    size_t i = (size_t)blockIdx.x * 256 + threadIdx.x;
    float4 v = src[i];
    __nv_bfloat16 h0 = __float2bfloat16(v.x), h1 = __float2bfloat16(v.y);
    __nv_bfloat16 h2 = __float2bfloat16(v.z), h3 = __float2bfloat16(v.w);
    __nv_bfloat16 l0 = __float2bfloat16(v.x - __bfloat162float(h0));
    __nv_bfloat16 l1 = __float2bfloat16(v.y - __bfloat162float(h1));
    __nv_bfloat16 l2 = __float2bfloat16(v.z - __bfloat162float(h2));
    __nv_bfloat16 l3 = __float2bfloat16(v.w - __bfloat162float(h3));
    hi[i * 2 + 0] = __nv_bfloat162{h0, h1};
    hi[i * 2 + 1] = __nv_bfloat162{h2, h3};
    lo[i * 2 + 0] = __nv_bfloat162{l0, l1};
    lo[i * 2 + 1] = __nv_bfloat162{l2, l3};
}

// -- bf16 hi/lo split of k AND q (scaled 0.125) from qkv, relayout to [h][t][d] --
__global__ void split_qk_bf16_kernel(const float* __restrict__ qkv,
                                     __nv_bfloat16* __restrict__ khi,
                                     __nv_bfloat16* __restrict__ klo,
                                     __nv_bfloat16* __restrict__ qhi,
                                     __nv_bfloat16* __restrict__ qlo) {
    int i = blockIdx.x * 1024 + threadIdx.x;  // 2M
    int which = i >> 20;                      // 0: k, 1: q
    int r = i & 0xFFFFF;
    int d = r & 63, t = (r >> 6) & 1023, h = r >> 16;
    float x = qkv[(size_t)t * 3072 + (which ? 0 : 1024) + h * 64 + d];
    if (which) x *= 0.125f;
    __nv_bfloat16 hf = __float2bfloat16(x);
    __nv_bfloat16 lf = __float2bfloat16(x - __bfloat162float(hf));
    if (which) { qhi[r] = hf; qlo[r] = lf; }
    else       { khi[r] = hf; klo[r] = lf; }
}

// ---- generic 3xBF16 mma GEMM: C = A * B^T + bias  (round-9 validated) ----
#define KAH 72
#define GM_SMEM_BYTES ((64 * KAH * 2 + 128 * KAH * 2) * 2)

__global__ __launch_bounds__(256) void mma_gemm_bf16_kernel(
    const __nv_bfloat16* __restrict__ Ahg, const __nv_bfloat16* __restrict__ Alg,
    const __nv_bfloat16* __restrict__ Bhg, const __nv_bfloat16* __restrict__ Blg,
    float* __restrict__ C, int ldc, int K, const float* __restrict__ bias) {
    extern __shared__ char smc[];
    __nv_bfloat16* Ah = (__nv_bfloat16*)smc;          // [64][72]
    __nv_bfloat16* Al = Ah + 64 * KAH;
    __nv_bfloat16* Bh = Al + 64 * KAH;                // [128][72]
    __nv_bfloat16* Bl = Bh + 128 * KAH;

    const int tid = threadIdx.x;
    const int bx = blockIdx.x, by = blockIdx.y;
    const int w = tid >> 5, lane = tid & 31;
    const int gid = lane >> 2, qid = lane & 3;
    const int rt = (w & 3) * 16;
    const int ch = (w >> 2) * 64;

    const __nv_bfloat16* Ahb = Ahg + (size_t)(by * 64) * K;
    const __nv_bfloat16* Alb = Alg + (size_t)(by * 64) * K;
    const __nv_bfloat16* Bhb = Bhg + (size_t)(bx * 128) * K;
    const __nv_bfloat16* Blb = Blg + (size_t)(bx * 128) * K;

    float c[8][4];
#pragma unroll
    for (int nb = 0; nb < 8; nb++)
#pragma unroll
        for (int k = 0; k < 4; k++) c[nb][k] = 0.f;

    for (int k0 = 0; k0 < K; k0 += 64) {
        __syncthreads();
        for (int i = tid; i < 512; i += 256) {
            int r = i >> 3, c8 = (i & 7) * 8;
            *(uint4*)&Ah[r * KAH + c8] = *(const uint4*)(Ahb + (size_t)r * K + k0 + c8);
            *(uint4*)&Al[r * KAH + c8] = *(const uint4*)(Alb + (size_t)r * K + k0 + c8);
        }
        for (int i = tid; i < 1024; i += 256) {
            int r = i >> 3, c8 = (i & 7) * 8;
            *(uint4*)&Bh[r * KAH + c8] = *(const uint4*)(Bhb + (size_t)r * K + k0 + c8);
            *(uint4*)&Bl[r * KAH + c8] = *(const uint4*)(Blb + (size_t)r * K + k0 + c8);
        }
        __syncthreads();

#pragma unroll
        for (int ks16 = 0; ks16 < 4; ks16++) {
            const int kk = ks16 * 16;
            const int ab = (rt + gid) * KAH + kk + 2 * qid;
            uint32_t ah0 = *(const uint32_t*)&Ah[ab];
            uint32_t ah1 = *(const uint32_t*)&Ah[ab + 8 * KAH];
            uint32_t ah2 = *(const uint32_t*)&Ah[ab + 8];
            uint32_t ah3 = *(const uint32_t*)&Ah[ab + 8 * KAH + 8];
            uint32_t al0 = *(const uint32_t*)&Al[ab];
            uint32_t al1 = *(const uint32_t*)&Al[ab + 8 * KAH];
            uint32_t al2 = *(const uint32_t*)&Al[ab + 8];
            uint32_t al3 = *(const uint32_t*)&Al[ab + 8 * KAH + 8];
#pragma unroll
            for (int nb = 0; nb < 8; nb++) {
                const int bb = (ch + nb * 8 + gid) * KAH + kk + 2 * qid;
                uint32_t bh0 = *(const uint32_t*)&Bh[bb];
                uint32_t bh1 = *(const uint32_t*)&Bh[bb + 8];
                uint32_t bl0 = *(const uint32_t*)&Bl[bb];
                uint32_t bl1 = *(const uint32_t*)&Bl[bb + 8];
                mma_bf16(c[nb][0], c[nb][1], c[nb][2], c[nb][3],
                         ah0, ah1, ah2, ah3, bh0, bh1);
                mma_bf16(c[nb][0], c[nb][1], c[nb][2], c[nb][3],
                         ah0, ah1, ah2, ah3, bl0, bl1);
                mma_bf16(c[nb][0], c[nb][1], c[nb][2], c[nb][3],
                         al0, al1, al2, al3, bh0, bh1);
            }
        }
    }

#pragma unroll
    for (int nb = 0; nb < 8; nb++) {
#pragma unroll
        for (int k = 0; k < 4; k++) {
            int row = by * 64 + rt + gid + (k >> 1) * 8;
            int col = bx * 128 + ch + nb * 8 + 2 * qid + (k & 1);
            C[(size_t)row * ldc + col] = c[nb][k] + bias[col];
        }
    }
}

// ---------------- ||key_store[h,m]||^2 (exact fp32) ----------------
__global__ void ksnorm_kernel(const float* __restrict__ ks, float* __restrict__ nrm) {
    int r = blockIdx.x * blockDim.x + threadIdx.x;
    if (r >= 16 * 8192) return;
    const float4* p = (const float4*)(ks + (size_t)r * 64);
    float s = 0.f;
#pragma unroll
    for (int i = 0; i < 16; i++) {
        float4 f = p[i];
        s += f.x * f.x + f.y * f.y + f.z * f.z + f.w * f.w;
    }
    nrm[r] = s;
}

// ------------- lexicographic (score, idx) compare: stable top-k --------------
__device__ __forceinline__ bool lex_lt(float sa, int ia, float sb, int ib) {
    return sa < sb || (sa == sb && ia < ib);
}

#define TOP4_INSERT(v, m, s0, x0, s1, x1, s2, x2, s3, x3)              \
    if (lex_lt(v, m, s3, x3)) {                                        \
        if (lex_lt(v, m, s2, x2)) {                                    \
            s3 = s2; x3 = x2;                                          \
            if (lex_lt(v, m, s1, x1)) {                                \
                s2 = s1; x2 = x1;                                      \
                if (lex_lt(v, m, s0, x0)) {                            \
                    s1 = s0; x1 = x0; s0 = v; x0 = m;                  \
                } else { s1 = v; x1 = m; }                             \
            } else { s2 = v; x2 = m; }                                 \
        } else { s3 = v; x3 = m; }                                     \
    }

// ---- fused kNN scores + top-4 via bf16 tensor cores (round-10 validated, 64-row) ----
#define KNN_SMEM_BYTES ((64 * KAH * 2 + 128 * KAH * 2) * 2 + 128 * 4)

__global__ __launch_bounds__(256) void knn_mma_kernel(
    const __nv_bfloat16* __restrict__ kh, const __nv_bfloat16* __restrict__ kl,
    const __nv_bfloat16* __restrict__ mh, const __nv_bfloat16* __restrict__ ml,
    const float* __restrict__ ksn, int* __restrict__ idx_out) {
    extern __shared__ char smc[];
    __nv_bfloat16* Ah = (__nv_bfloat16*)smc;          // [64][72]
    __nv_bfloat16* Al = Ah + 64 * KAH;
    __nv_bfloat16* Bh = Al + 64 * KAH;                // [128][72]
    __nv_bfloat16* Bl = Bh + 128 * KAH;
    float* Ns = (float*)(Bl + 128 * KAH);             // [128]

    const int tid = threadIdx.x;
    const int t0 = blockIdx.x * 64;
    const int h = blockIdx.y;
    const int w = tid >> 5, lane = tid & 31;
    const int gid = lane >> 2, qid = lane & 3;
    const int rt = (w & 3) * 16;
    const int ch = (w >> 2) * 64;

    const __nv_bfloat16* Ahg = kh + ((size_t)h * 1024 + t0) * 64;
    const __nv_bfloat16* Alg = kl + ((size_t)h * 1024 + t0) * 64;
    for (int i = tid; i < 512; i += 256) {
        int r = i >> 3, c8 = (i & 7) * 8;
        *(uint4*)&Ah[r * KAH + c8] = *(const uint4*)(Ahg + (size_t)r * 64 + c8);
        *(uint4*)&Al[r * KAH + c8] = *(const uint4*)(Alg + (size_t)r * 64 + c8);
    }

    float S[2][4];
    int I[2][4];
#pragma unroll
    for (int r = 0; r < 2; r++)
#pragma unroll
        for (int k = 0; k < 4; k++) { S[r][k] = FLT_MAX; I[r][k] = 0x7fffffff; }

    const __nv_bfloat16* Bhg = mh + (size_t)h * 8192 * 64;
    const __nv_bfloat16* Blg = ml + (size_t)h * 8192 * 64;
    const float* Nbase = ksn + h * 8192;

    for (int chunk = 0; chunk < 64; chunk++) {
        const int m0 = chunk << 7;
        __syncthreads();
        if (tid < 128) Ns[tid] = Nbase[m0 + tid];
        for (int i = tid; i < 1024; i += 256) {
            int r = i >> 3, c8 = (i & 7) * 8;
            *(uint4*)&Bh[r * KAH + c8] = *(const uint4*)(Bhg + (size_t)(m0 + r) * 64 + c8);
            *(uint4*)&Bl[r * KAH + c8] = *(const uint4*)(Blg + (size_t)(m0 + r) * 64 + c8);
        }
        __syncthreads();

        float c[8][4];
#pragma unroll
        for (int nb = 0; nb < 8; nb++)
#pragma unroll
            for (int k = 0; k < 4; k++) c[nb][k] = 0.f;

#pragma unroll
        for (int ks16 = 0; ks16 < 4; ks16++) {
            const int k0 = ks16 * 16;
            const int ab = (rt + gid) * KAH + k0 + 2 * qid;
            uint32_t ah0 = *(const uint32_t*)&Ah[ab];
            uint32_t ah1 = *(const uint32_t*)&Ah[ab + 8 * KAH];
            uint32_t ah2 = *(const uint32_t*)&Ah[ab + 8];
            uint32_t ah3 = *(const uint32_t*)&Ah[ab + 8 * KAH + 8];
            uint32_t al0 = *(const uint32_t*)&Al[ab];
            uint32_t al1 = *(const uint32_t*)&Al[ab + 8 * KAH];
            uint32_t al2 = *(const uint32_t*)&Al[ab + 8];
            uint32_t al3 = *(const uint32_t*)&Al[ab + 8 * KAH + 8];
#pragma unroll
            for (int nb = 0; nb < 8; nb++) {
                const int bb = (ch + nb * 8 + gid) * KAH + k0 + 2 * qid;
                uint32_t bh0 = *(const uint32_t*)&Bh[bb];
                uint32_t bh1 = *(const uint32_t*)&Bh[bb + 8];
                uint32_t bl0 = *(const uint32_t*)&Bl[bb];
                uint32_t bl1 = *(const uint32_t*)&Bl[bb + 8];
                mma_bf16(c[nb][0], c[nb][1], c[nb][2], c[nb][3],
                         ah0, ah1, ah2, ah3, bh0, bh1);
                mma_bf16(c[nb][0], c[nb][1], c[nb][2], c[nb][3],
                         ah0, ah1, ah2, ah3, bl0, bl1);
                mma_bf16(c[nb][0], c[nb][1], c[nb][2], c[nb][3],
                         al0, al1, al2, al3, bh0, bh1);
            }
        }

#pragma unroll
        for (int nb = 0; nb < 8; nb++) {
#pragma unroll
            for (int k = 0; k < 4; k++) {
                int cl = ch + nb * 8 + 2 * qid + (k & 1);
                int r = k >> 1;
                float v = Ns[cl] - 2.0f * c[nb][k];
                int mg = m0 + cl;
                TOP4_INSERT(v, mg, S[r][0], I[r][0], S[r][1], I[r][1],
                            S[r][2], I[r][2], S[r][3], I[r][3]);
            }
        }
    }

    __syncthreads();
    float* msc = (float*)smc;                 // [64][32]
    int* mix = (int*)(smc + 16384);
    const int slot = (w >> 2) * 4 + qid;
#pragma unroll
    for (int r = 0; r < 2; r++) {
        int row = rt + gid + r * 8;
#pragma unroll
        for (int k = 0; k < 4; k++) {
            msc[(row * 8 + slot) * 4 + k] = S[r][k];
            mix[(row * 8 + slot) * 4 + k] = I[r][k];
        }
    }
    __syncthreads();
    if (tid < 64) {
        float f0 = FLT_MAX, f1 = FLT_MAX, f2 = FLT_MAX, f3 = FLT_MAX;
        int g0 = 0x7fffffff, g1 = 0x7fffffff, g2 = 0x7fffffff, g3 = 0x7fffffff;
        for (int c2 = 0; c2 < 32; c2++) {
            float v = msc[tid * 32 + c2];
            int m = mix[tid * 32 + c2];
            TOP4_INSERT(v, m, f0, g0, f1, g1, f2, g2, f3, g3);
        }
        size_t row = (size_t)h * 1024 + t0 + tid;
        idx_out[row * 4 + 0] = g0;
        idx_out[row * 4 + 1] = g1;
        idx_out[row * 4 + 2] = g2;
        idx_out[row * 4 + 3] = g3;
    }
}

// ---------------- warp-per-token last-row logits ----------------
__global__ void selA_kernel(const float* __restrict__ qkv, float* __restrict__ lg) {
    int h = blockIdx.y;
    int t = blockIdx.x * 8 + (threadIdx.x >> 5);
    int lane = threadIdx.x & 31;
    int d0 = lane * 2;
    const float* q = qkv + (size_t)1023 * 3072 + h * 64;
    const float* k = qkv + (size_t)t * 3072 + 1024 + h * 64;
    float s = q[d0] * k[d0] + q[d0 + 1] * k[d0 + 1];
#pragma unroll
    for (int o = 16; o > 0; o >>= 1) s += __shfl_xor_sync(0xffffffffu, s, o);
    if (lane == 0) lg[h * 1024 + t] = s * 0.125f;
}

// ---------------- per-head softmax of logits row -> sel ----------------
__global__ void selB_kernel(const float* __restrict__ lg, int* __restrict__ sel) {
    int h = blockIdx.x;
    int tid = threadIdx.x;
    int lane = tid & 31, warp = tid >> 5;
    __shared__ float red[8];
    __shared__ float bcast;

    float v[4];
#pragma unroll
    for (int u = 0; u < 4; u++) v[u] = lg[h * 1024 + tid + u * 256];
    float m = fmaxf(fmaxf(v[0], v[1]), fmaxf(v[2], v[3]));
#pragma unroll
    for (int o = 16; o > 0; o >>= 1) m = fmaxf(m, __shfl_xor_sync(0xffffffffu, m, o));
    if (lane == 0) red[warp] = m;
    __syncthreads();
    if (tid == 0) {
        float x = red[0];
#pragma unroll
        for (int w = 1; w < 8; w++) x = fmaxf(x, red[w]);
        bcast = x;
    }
    __syncthreads();
    m = bcast;
    float e[4], s = 0.f;
#pragma unroll
    for (int u = 0; u < 4; u++) { e[u] = __expf(v[u] - m); s += e[u]; }
#pragma unroll
    for (int o = 16; o > 0; o >>= 1) s += __shfl_xor_sync(0xffffffffu, s, o);
    if (lane == 0) red[warp] = s;
    __syncthreads();
    if (tid == 0) {
        float x = 0.f;
#pragma unroll
        for (int w = 0; w < 8; w++) x += red[w];
        bcast = x;
    }
    __syncthreads();
    float inv = 1.f / bcast;
#pragma unroll
    for (int u = 0; u < 4; u++)
        sel[h * 1024 + tid + u * 256] = (e[u] * inv >= (1.0f / 8192.0f)) ? 1 : 0;
}

// ---------------- per-token 5-way memory softmax & blend -> v_new ----------------
__device__ __forceinline__ float warp_sum(float v) {
#pragma unroll
    for (int o = 16; o > 0; o >>= 1) v += __shfl_xor_sync(0xffffffffu, v, o);
    return v;
}

__global__ void vnew_kernel(const float* __restrict__ qkv, const float* __restrict__ kstore,
                            const float* __restrict__ vstore, const int* __restrict__ idx,
                            const int* __restrict__ sel, float* __restrict__ vnew) {
    int gw = (blockIdx.x * blockDim.x + threadIdx.x) >> 5;
    int lane = threadIdx.x & 31;
    if (gw >= 16 * 1024) return;
    int h = gw >> 10, t = gw & 1023;

    const float* base = qkv + (size_t)t * 3072 + h * 64;
    int d0 = lane * 2;
    float q0 = base[d0],        q1 = base[d0 + 1];
    float k0 = base[1024 + d0], k1 = base[1024 + d0 + 1];
    float v0 = base[2048 + d0], v1 = base[2048 + d0 + 1];
    const float scale = 0.125f;

    float attf[5];
    attf[0] = warp_sum(q0 * k0 + q1 * k1) * scale;

    int ids[4];
#pragma unroll
    for (int s2 = 0; s2 < 4; s2++) ids[s2] = idx[(size_t)gw * 4 + s2];

    float fv0[4], fv1[4];
#pragma unroll
    for (int s2 = 0; s2 < 4; s2++) {
        const float* kp = kstore + ((size_t)h * 8192 + ids[s2]) * 64;
        attf[s2 + 1] = warp_sum(q0 * kp[d0] + q1 * kp[d0 + 1]) * scale;
        const float* vp = vstore + ((size_t)h * 8192 + ids[s2]) * 64;
        fv0[s2] = vp[d0]; fv1[s2] = vp[d0 + 1];
    }

    float mx = attf[0];
#pragma unroll
    for (int s2 = 1; s2 < 5; s2++) mx = fmaxf(mx, attf[s2]);
    float e[5], sum = 0.f;
#pragma unroll
    for (int s2 = 0; s2 < 5; s2++) { e[s2] = expf(attf[s2] - mx); sum += e[s2]; }
    float inv = 1.f / sum;

    float o0 = e[0] * v0, o1 = e[0] * v1;
#pragma unroll
    for (int s2 = 0; s2 < 4; s2++) { o0 += e[s2 + 1] * fv0[s2]; o1 += e[s2 + 1] * fv1[s2]; }
    o0 = o0 * inv * 0.5f + v0 * 0.5f;
    o1 = o1 * inv * 0.5f + v1 * 0.5f;

    bool sl = sel[gw] != 0;
    vnew[(size_t)gw * 64 + d0]     = sl ? o0 : v0;
    vnew[(size_t)gw * 64 + d0 + 1] = sl ? o1 : v1;
}

// ------- transpose+split v_new to bf16 hi/lo, [h][d][t] layout (for flash PV) -------
__global__ void vtrans_kernel(const float* __restrict__ vnew,
                              __nv_bfloat16* __restrict__ vth,
                              __nv_bfloat16* __restrict__ vtl) {
    __shared__ float sm[64][65];
    const int tid = threadIdx.x;
    const int t0 = blockIdx.x * 64, h = blockIdx.y;
    for (int i = tid; i < 4096; i += 256) {
        int tr = i >> 6, d = i & 63;
        sm[tr][d] = vnew[((size_t)h * 1024 + t0 + tr) * 64 + d];
    }
    __syncthreads();
    for (int i = tid; i < 4096; i += 256) {
        int d = i >> 6, tr = i & 63;
        float x = sm[tr][d];
        __nv_bfloat16 hh = __float2bfloat16(x);
        size_t o = ((size_t)h * 64 + d) * 1024 + t0 + tr;
        vth[o] = hh;
        vtl[o] = __float2bfloat16(x - __bfloat162float(hh));
    }
}

// -- fused flash attention, split-KV: each block does HALF the s-range of one q-tile --
// Block (bx, h): qb = bx>>1, half = bx&1; chunks j in [half*(qb+1), half*(qb+1)+qb+1).
// Produces unnormalized partial (m, l, O) -> merged by flash_merge_kernel.
#define FLM_SMEM_BYTES ((128 * KAH * 2 + 64 * KAH * 2 + 64 * KAH * 2) * 2)

__global__ __launch_bounds__(256) void flash_mma_kernel(
    const __nv_bfloat16* __restrict__ qhg, const __nv_bfloat16* __restrict__ qlg,
    const __nv_bfloat16* __restrict__ khg, const __nv_bfloat16* __restrict__ klg,
    const __nv_bfloat16* __restrict__ vth, const __nv_bfloat16* __restrict__ vtl,
    float* __restrict__ pO, float* __restrict__ pm, float* __restrict__ pl) {
    extern __shared__ char smc[];
    __nv_bfloat16* Qh = (__nv_bfloat16*)smc;          // [128][72]
    __nv_bfloat16* Ql = Qh + 128 * KAH;
    __nv_bfloat16* Kh = Ql + 128 * KAH;               // [64][72]
    __nv_bfloat16* Kl = Kh + 64 * KAH;
    __nv_bfloat16* Vh = Kl + 64 * KAH;                // [64][72]  (row = d, col = s)
    __nv_bfloat16* Vl = Vh + 64 * KAH;

    const int tid = threadIdx.x;
    const int bx = blockIdx.x, h = blockIdx.y;
    const int qb = bx >> 1, half = bx & 1;
    const int w = tid >> 5, lane = tid & 31;
    const int gid = lane >> 2, qid = lane & 3;
    const int rt = w * 16;
    const int t0 = qb * 128;

    const __nv_bfloat16* Qhg = qhg + ((size_t)h * 1024 + t0) * 64;
    const __nv_bfloat16* Qlg = qlg + ((size_t)h * 1024 + t0) * 64;
    for (int i = tid; i < 1024; i += 256) {
        int r = i >> 3, c8 = (i & 7) * 8;
        *(uint4*)&Qh[r * KAH + c8] = *(const uint4*)(Qhg + (size_t)r * 64 + c8);
        *(uint4*)&Ql[r * KAH + c8] = *(const uint4*)(Qlg + (size_t)r * 64 + c8);
    }

    float m0 = -FLT_MAX, m1 = -FLT_MAX, l0 = 0.f, l1 = 0.f;
    float O[8][4];
#pragma unroll
    for (int nb = 0; nb < 8; nb++)
#pragma unroll
        for (int k = 0; k < 4; k++) O[nb][k] = 0.f;

    const int row0 = t0 + rt + gid, row1 = row0 + 8;
    const int jlo = half * (qb + 1);
    const int jhi = jlo + qb + 1;

    for (int j = jlo; j < jhi; j++) {
        const int s0 = j * 64;
        __syncthreads();  // prior PV reads done (and Q loads on first iter)
        const __nv_bfloat16* Khg = khg + ((size_t)h * 1024 + s0) * 64;
        const __nv_bfloat16* Klg = klg + ((size_t)h * 1024 + s0) * 64;
        for (int i = tid; i < 512; i += 256) {
            int r = i >> 3, c8 = (i & 7) * 8;
            *(uint4*)&Kh[r * KAH + c8] = *(const uint4*)(Khg + (size_t)r * 64 + c8);
            *(uint4*)&Kl[r * KAH + c8] = *(const uint4*)(Klg + (size_t)r * 64 + c8);
        }
        const __nv_bfloat16* Vhg = vth + (size_t)h * 64 * 1024 + s0;
        const __nv_bfloat16* Vlg = vtl + (size_t)h * 64 * 1024 + s0;
        for (int i = tid; i < 512; i += 256) {
            int r = i >> 3, c8 = (i & 7) * 8;
            *(uint4*)&Vh[r * KAH + c8] = *(const uint4*)(Vhg + (size_t)r * 1024 + c8);
            *(uint4*)&Vl[r * KAH + c8] = *(const uint4*)(Vlg + (size_t)r * 1024 + c8);
        }
        __syncthreads();

        // S = Q K^T (3xBF16)
        float c[8][4];
#pragma unroll
        for (int nb = 0; nb < 8; nb++)
#pragma unroll
            for (int k = 0; k < 4; k++) c[nb][k] = 0.f;

#pragma unroll
        for (int ks16 = 0; ks16 < 4; ks16++) {
            const int kk = ks16 * 16;
            const int ab = (rt + gid) * KAH + kk + 2 * qid;
            uint32_t ah0 = *(const uint32_t*)&Qh[ab];
            uint32_t ah1 = *(const uint32_t*)&Qh[ab + 8 * KAH];
            uint32_t ah2 = *(const uint32_t*)&Qh[ab + 8];
            uint32_t ah3 = *(const uint32_t*)&Qh[ab + 8 * KAH + 8];
            uint32_t al0 = *(const uint32_t*)&Ql[ab];
            uint32_t al1 = *(const uint32_t*)&Ql[ab + 8 * KAH];
            uint32_t al2 = *(const uint32_t*)&Ql[ab + 8];
            uint32_t al3 = *(const uint32_t*)&Ql[ab + 8 * KAH + 8];
#pragma unroll
            for (int nb = 0; nb < 8; nb++) {
                const int bb = (nb * 8 + gid) * KAH + kk + 2 * qid;
                uint32_t bh0 = *(const uint32_t*)&Kh[bb];
                uint32_t bh1 = *(const uint32_t*)&Kh[bb + 8];
                uint32_t bl0 = *(const uint32_t*)&Kl[bb];
                uint32_t bl1 = *(const uint32_t*)&Kl[bb + 8];
                mma_bf16(c[nb][0], c[nb][1], c[nb][2], c[nb][3],
                         ah0, ah1, ah2, ah3, bh0, bh1);
                mma_bf16(c[nb][0], c[nb][1], c[nb][2], c[nb][3],
                         ah0, ah1, ah2, ah3, bl0, bl1);
                mma_bf16(c[nb][0], c[nb][1], c[nb][2], c[nb][3],
                         al0, al1, al2, al3, bh0, bh1);
            }
        }

        // causal mask
        if (s0 + 63 > t0 + rt) {
#pragma unroll
            for (int nb = 0; nb < 8; nb++) {
                int cb = s0 + nb * 8 + 2 * qid;
                if (cb > row0)     c[nb][0] = -FLT_MAX;
                if (cb + 1 > row0) c[nb][1] = -FLT_MAX;
                if (cb > row1)     c[nb][2] = -FLT_MAX;
                if (cb + 1 > row1) c[nb][3] = -FLT_MAX;
            }
        }

        // online softmax across this thread's 16 cols + 4 qid lanes
        float rm0 = -FLT_MAX, rm1 = -FLT_MAX;
#pragma unroll
        for (int nb = 0; nb < 8; nb++) {
            rm0 = fmaxf(rm0, fmaxf(c[nb][0], c[nb][1]));
            rm1 = fmaxf(rm1, fmaxf(c[nb][2], c[nb][3]));
        }
        rm0 = fmaxf(rm0, __shfl_xor_sync(0xffffffffu, rm0, 1));
        rm0 = fmaxf(rm0, __shfl_xor_sync(0xffffffffu, rm0, 2));
        rm1 = fmaxf(rm1, __shfl_xor_sync(0xffffffffu, rm1, 1));
        rm1 = fmaxf(rm1, __shfl_xor_sync(0xffffffffu, rm1, 2));

        float mn0 = fmaxf(m0, rm0), mn1 = fmaxf(m1, rm1);
        float alpha0 = __expf(m0 - mn0), alpha1 = __expf(m1 - mn1);
        float ps0 = 0.f, ps1 = 0.f;
#pragma unroll
        for (int nb = 0; nb < 8; nb++) {
            c[nb][0] = __expf(c[nb][0] - mn0); ps0 += c[nb][0];
            c[nb][1] = __expf(c[nb][1] - mn0); ps0 += c[nb][1];
            c[nb][2] = __expf(c[nb][2] - mn1); ps1 += c[nb][2];
            c[nb][3] = __expf(c[nb][3] - mn1); ps1 += c[nb][3];
        }
        ps0 += __shfl_xor_sync(0xffffffffu, ps0, 1);
        ps0 += __shfl_xor_sync(0xffffffffu, ps0, 2);
        ps1 += __shfl_xor_sync(0xffffffffu, ps1, 1);
        ps1 += __shfl_xor_sync(0xffffffffu, ps1, 2);
        l0 = l0 * alpha0 + ps0; m0 = mn0;
        l1 = l1 * alpha1 + ps1; m1 = mn1;
#pragma unroll
        for (int nb = 0; nb < 8; nb++) {
            O[nb][0] *= alpha0; O[nb][1] *= alpha0;
            O[nb][2] *= alpha1; O[nb][3] *= alpha1;
        }

        // P@V: C-frag of S is bitwise the A-frag layout — register-only conversion
#pragma unroll
        for (int kb = 0; kb < 4; kb++) {
            float p00 = c[2 * kb][0],     p01 = c[2 * kb][1];
            float p02 = c[2 * kb][2],     p03 = c[2 * kb][3];
            float p10 = c[2 * kb + 1][0], p11 = c[2 * kb + 1][1];
            float p12 = c[2 * kb + 1][2], p13 = c[2 * kb + 1][3];
            __nv_bfloat16 h00 = __float2bfloat16(p00), h01 = __float2bfloat16(p01);
            __nv_bfloat16 h02 = __float2bfloat16(p02), h03 = __float2bfloat16(p03);
            __nv_bfloat16 h10 = __float2bfloat16(p10), h11 = __float2bfloat16(p11);
            __nv_bfloat16 h12 = __float2bfloat16(p12), h13 = __float2bfloat16(p13);
            uint32_t Ah0 = pack_bf16(h00, h01);
            uint32_t Ah1 = pack_bf16(h02, h03);
            uint32_t Ah2 = pack_bf16(h10, h11);
            uint32_t Ah3 = pack_bf16(h12, h13);
            uint32_t Al0 = pack_bf16(__float2bfloat16(p00 - __bfloat162float(h00)),
                                     __float2bfloat16(p01 - __bfloat162float(h01)));
            uint32_t Al1 = pack_bf16(__float2bfloat16(p02 - __bfloat162float(h02)),
                                     __float2bfloat16(p03 - __bfloat162float(h03)));
            uint32_t Al2 = pack_bf16(__float2bfloat16(p10 - __bfloat162float(h10)),
                                     __float2bfloat16(p11 - __bfloat162float(h11)));
            uint32_t Al3 = pack_bf16(__float2bfloat16(p12 - __bfloat162float(h12)),
                                     __float2bfloat16(p13 - __bfloat162float(h13)));
#pragma unroll
            for (int nb = 0; nb < 8; nb++) {
                const int bb = (nb * 8 + gid) * KAH + kb * 16 + 2 * qid;
                uint32_t bh0 = *(const uint32_t*)&Vh[bb];
                uint32_t bh1 = *(const uint32_t*)&Vh[bb + 8];
                uint32_t bl0 = *(const uint32_t*)&Vl[bb];
                uint32_t bl1 = *(const uint32_t*)&Vl[bb + 8];
                mma_bf16(O[nb][0], O[nb][1], O[nb][2], O[nb][3],
                         Ah0, Ah1, Ah2, Ah3, bh0, bh1);
                mma_bf16(O[nb][0], O[nb][1], O[nb][2], O[nb][3],
                         Ah0, Ah1, Ah2, Ah3, bl0, bl1);
                mma_bf16(O[nb][0], O[nb][1], O[nb][2], O[nb][3],
                         Al0, Al1, Al2, Al3, bh0, bh1);
            }
        }
    }

    // epilogue: store unnormalized partial (m, l, O)
    const size_t base = ((size_t)half * 16 + h) * 1024;
    if (qid == 0) {
        pm[base + row0] = m0; pl[base + row0] = l0;
        pm[base + row1] = m1; pl[base + row1] = l1;
    }
#pragma unroll
    for (int nb = 0; nb < 8; nb++) {
        int colb = nb * 8 + 2 * qid;
        pO[(base + row0) * 64 + colb]     = O[nb][0];
        pO[(base + row0) * 64 + colb + 1] = O[nb][1];
        pO[(base + row1) * 64 + colb]     = O[nb][2];
        pO[(base + row1) * 64 + colb + 1] = O[nb][3];
    }
}

// ---------------- merge the two flash partials per (h, t) row -> y ----------------
__global__ void flash_merge_kernel(const float* __restrict__ pO,
                                   const float* __restrict__ pm,
                                   const float* __restrict__ pl,
                                   float* __restrict__ y) {
    int i = blockIdx.x * 256 + threadIdx.x;   // < 16*1024*64 = 1M
    int d = i & 63, t = (i >> 6) & 1023, h = i >> 16;
    size_t r0 = (size_t)h * 1024 + t;
    size_t r1 = (size_t)16 * 1024 + r0;
    float ma = pm[r0], mb = pm[r1];
    float mm = fmaxf(ma, mb);
    float ea = __expf(ma - mm), eb = __expf(mb - mm);
    float l = pl[r0] * ea + pl[r1] * eb;
    float o = pO[r0 * 64 + d] * ea + pO[r1 * 64 + d] * eb;
    y[(size_t)t * 1024 + h * 64 + d] = o / l;
}

// ---------------- launch ----------------
extern "C" void kernel_launch(void* const* d_in, const int* in_sizes, int n_in,
                              void* d_out, int out_size) {
    const float* x  = (const float*)d_in[0];
    const float* aw = (const float*)d_in[1];
    const float* ab = (const float*)d_in[2];
    const float* pw = (const float*)d_in[3];
    const float* pb = (const float*)d_in[4];
    const float* ks = (const float*)d_in[5];
    const float* vs = (const float*)d_in[6];
    float* out = (float*)d_out;

    float *qkv, *ksn, *lg, *vnw, *y, *pO, *pm, *pl;
    __nv_bfloat16 *kh, *kl, *qh, *ql, *mh, *ml, *xh, *xl, *awh, *awl, *pwh, *pwl, *yh, *yl;
    __nv_bfloat16 *vth, *vtl;
    int *idx, *sel;
    cudaGetSymbolAddress((void**)&qkv, g_qkv);
    cudaGetSymbolAddress((void**)&ksn, g_ksnorm);
    cudaGetSymbolAddress((void**)&kh,  g_kh);
    cudaGetSymbolAddress((void**)&kl,  g_kl);
    cudaGetSymbolAddress((void**)&qh,  g_qh);
    cudaGetSymbolAddress((void**)&ql,  g_ql);
    cudaGetSymbolAddress((void**)&mh,  g_mh);
    cudaGetSymbolAddress((void**)&ml,  g_ml);
    cudaGetSymbolAddress((void**)&xh,  g_xh);
    cudaGetSymbolAddress((void**)&xl,  g_xl);
    cudaGetSymbolAddress((void**)&awh, g_awh);
    cudaGetSymbolAddress((void**)&awl, g_awl);
    cudaGetSymbolAddress((void**)&pwh, g_pwh);
    cudaGetSymbolAddress((void**)&pwl, g_pwl);
    cudaGetSymbolAddress((void**)&yh,  g_yh);
    cudaGetSymbolAddress((void**)&yl,  g_yl);
    cudaGetSymbolAddress((void**)&vth, g_vth);
    cudaGetSymbolAddress((void**)&vtl, g_vtl);
    cudaGetSymbolAddress((void**)&pO,  g_pO);
    cudaGetSymbolAddress((void**)&pm,  g_pm);
    cudaGetSymbolAddress((void**)&pl,  g_pl);
    cudaGetSymbolAddress((void**)&lg,  g_lg);
    cudaGetSymbolAddress((void**)&idx, g_idx);
    cudaGetSymbolAddress((void**)&sel, g_sel);
    cudaGetSymbolAddress((void**)&vnw, g_vnew);
    cudaGetSymbolAddress((void**)&y,   g_y);

    cudaFuncSetAttribute(knn_mma_kernel,
                         cudaFuncAttributeMaxDynamicSharedMemorySize, KNN_SMEM_BYTES);
    cudaFuncSetAttribute(mma_gemm_bf16_kernel,
                         cudaFuncAttributeMaxDynamicSharedMemorySize, GM_SMEM_BYTES);
    cudaFuncSetAttribute(flash_mma_kernel,
                         cudaFuncAttributeMaxDynamicSharedMemorySize, FLM_SMEM_BYTES);

    // 0) bf16 hi/lo splits (vectorized, 4 floats/thread)
    split_bf16_v4<<<1024, 256>>>((const float4*)x,
                                 (__nv_bfloat162*)xh, (__nv_bfloat162*)xl);
    split_bf16_v4<<<3072, 256>>>((const float4*)aw,
                                 (__nv_bfloat162*)awh, (__nv_bfloat162*)awl);
    split_bf16_v4<<<1024, 256>>>((const float4*)pw,
                                 (__nv_bfloat162*)pwh, (__nv_bfloat162*)pwl);
    split_bf16_v4<<<8192, 256>>>((const float4*)ks,
                                 (__nv_bfloat162*)mh, (__nv_bfloat162*)ml);
    // 1) qkv = x @ c_attn_w^T + b   (3xBF16 mma)
    mma_gemm_bf16_kernel<<<dim3(24, 16), 256, GM_SMEM_BYTES>>>(
        xh, xl, awh, awl, qkv, 3072, 1024, ab);
    // 2) key_store norms + k/q split/relayout (bf16, q pre-scaled)
    ksnorm_kernel<<<512, 256>>>(ks, ksn);
    split_qk_bf16_kernel<<<2048, 1024>>>(qkv, kh, kl, qh, ql);
    // 3) fused kNN scores + top-4 (bf16 mma, 64-row blocks — known-good)
    knn_mma_kernel<<<dim3(16, 16), 256, KNN_SMEM_BYTES>>>(
        kh, kl, mh, ml, ksn, idx);
    // 4) sel from last-row softmax
    selA_kernel<<<dim3(128, 16), 256>>>(qkv, lg);
    selB_kernel<<<16, 1024>>>(lg, sel);
    // 5) 5-way softmax blend -> v_new
    vnew_kernel<<<2048, 256>>>(qkv, ks, vs, idx, sel, vnw);
    // 5b) transpose+split v_new for flash PV
    vtrans_kernel<<<dim3(16, 16), 256>>>(vnw, vth, vtl);
    // 6) split-KV flash attention (partials) + merge -> y (T,C)
    flash_mma_kernel<<<dim3(16, 16), 256, FLM_SMEM_BYTES>>>(
        qh, ql, kh, kl, vth, vtl, pO, pm, pl);
    flash_merge_kernel<<<4096, 256>>>(pO, pm, pl, y);
    // 7) out = y @ c_proj_w^T + b   (3xBF16 mma)
    split_bf16_v4<<<1024, 256>>>((const float4*)y,
                                 (__nv_bfloat162*)yh, (__nv_bfloat162*)yl);
    mma_gemm_bf16_kernel<<<dim3(8, 16), 256, GM_SMEM_BYTES>>>(
        yh, yl, pwh, pwl, out, 1024, 1024, pb);
}

// round 14
// speedup vs baseline: 1.4091x; 1.0368x over previous
#include <cuda_runtime.h>
#include <cuda_bf16.h>
#include <cfloat>
#include <cstdint>

// ---------------- scratch (__device__ globals; no allocations) ----------------
__device__ float g_qkv[1024 * 3072];              // 12 MB  (T, 3C)
__device__ float g_ksnorm[16 * 8192];             // (H, M)
__device__ __nv_bfloat16 g_kh[16 * 1024 * 64];    // bf16-hi of k, [h][t][d]
__device__ __nv_bfloat16 g_kl[16 * 1024 * 64];    // bf16-lo of k
__device__ __nv_bfloat16 g_qh[16 * 1024 * 64];    // bf16-hi of q*0.125, [h][t][d]
__device__ __nv_bfloat16 g_ql[16 * 1024 * 64];    // bf16-lo
__device__ __nv_bfloat16 g_mh[16 * 8192 * 64];    // bf16-hi of key_store
__device__ __nv_bfloat16 g_ml[16 * 8192 * 64];    // bf16-lo of key_store
__device__ __nv_bfloat16 g_xh[1024 * 1024];       // bf16-hi of x
__device__ __nv_bfloat16 g_xl[1024 * 1024];
__device__ __nv_bfloat16 g_awh[3072 * 1024];      // bf16-hi of c_attn_w
__device__ __nv_bfloat16 g_awl[3072 * 1024];
__device__ __nv_bfloat16 g_pwh[1024 * 1024];      // bf16-hi of c_proj_w
__device__ __nv_bfloat16 g_pwl[1024 * 1024];
__device__ __nv_bfloat16 g_yh[1024 * 1024];       // bf16-hi of y (written by merge)
__device__ __nv_bfloat16 g_yl[1024 * 1024];
__device__ __nv_bfloat16 g_vth[16 * 64 * 1024];   // bf16-hi of v_new^T, [h][d][t]
__device__ __nv_bfloat16 g_vtl[16 * 64 * 1024];   // bf16-lo
__device__ float g_pO[2 * 16 * 1024 * 64];        // flash partial O [half][h][t][d]
__device__ float g_pm[2 * 16 * 1024];             // flash partial row max
__device__ float g_pl[2 * 16 * 1024];             // flash partial row sum
__device__ float g_lg[16 * 1024];                 // last-row logits
__device__ int   g_idx[16 * 1024 * 4];            // (H, T, 4)
__device__ int   g_sel[16 * 1024];                // (H, T)
__device__ float g_vnew[16 * 1024 * 64];          // (H, T, d)

// ---------------- helpers ----------------
__device__ __forceinline__ void mma_bf16(float& c0, float& c1, float& c2, float& c3,
                                         uint32_t a0, uint32_t a1, uint32_t a2, uint32_t a3,
                                         uint32_t b0, uint32_t b1) {
    asm volatile(
        "mma.sync.aligned.m16n8k16.row.col.f32.bf16.bf16.f32 "
        "{%0,%1,%2,%3}, {%4,%5,%6,%7}, {%8,%9}, {%0,%1,%2,%3};"
        : "+f"(c0), "+f"(c1), "+f"(c2), "+f"(c3)
        : "r"(a0), "r"(a1), "r"(a2), "r"(a3), "r"(b0), "r"(b1));
}

__device__ __forceinline__ void ldsm_x4(uint32_t& r0, uint32_t& r1,
                                        uint32_t& r2, uint32_t& r3, uint32_t addr) {
    asm volatile("ldmatrix.sync.aligned.m8n8.x4.shared.b16 {%0,%1,%2,%3}, [%4];"
                 : "=r"(r0), "=r"(r1), "=r"(r2), "=r"(r3) : "r"(addr));
}

__device__ __forceinline__ uint32_t smem_u32(const void* p) {
    return (uint32_t)__cvta_generic_to_shared(p);
}

__device__ __forceinline__ uint32_t pack_bf16(__nv_bfloat16 lo, __nv_bfloat16 hi) {
    __nv_bfloat162 t;
    t.x = lo; t.y = hi;
    return *(uint32_t*)&t;
}

// ---------- vectorized contiguous bf16 hi/lo split (4 floats / thread) ----------
__global__ void split_bf16_v4(const float4* __restrict__ src,
                              __nv_bfloat162* __restrict__ hi,
                              __nv_bfloat162* __restrict__ lo) {
    size_t i = (size_t)blockIdx.x * 256 + threadIdx.x;
    float4 v = src[i];
    __nv_bfloat16 h0 = __float2bfloat16(v.x), h1 = __float2bfloat16(v.y);
    __nv_bfloat16 h2 = __float2bfloat16(v.z), h3 = __float2bfloat16(v.w);
    __nv_bfloat16 l0 = __float2bfloat16(v.x - __bfloat162float(h0));
    __nv_bfloat16 l1 = __float2bfloat16(v.y - __bfloat162float(h1));
    __nv_bfloat16 l2 = __float2bfloat16(v.z - __bfloat162float(h2));
    __nv_bfloat16 l3 = __float2bfloat16(v.w - __bfloat162float(h3));
    hi[i * 2 + 0] = __nv_bfloat162{h0, h1};
    hi[i * 2 + 1] = __nv_bfloat162{h2, h3};
    lo[i * 2 + 0] = __nv_bfloat162{l0, l1};
    lo[i * 2 + 1] = __nv_bfloat162{l2, l3};
}

// -- bf16 hi/lo split of k AND q (scaled 0.125) from qkv, relayout to [h][t][d] --
__global__ void split_qk_bf16_kernel(const float* __restrict__ qkv,
                                     __nv_bfloat16* __restrict__ khi,
                                     __nv_bfloat16* __restrict__ klo,
                                     __nv_bfloat16* __restrict__ qhi,
                                     __nv_bfloat16* __restrict__ qlo) {
    int i = blockIdx.x * 1024 + threadIdx.x;  // 2M
    int which = i >> 20;                      // 0: k, 1: q
    int r = i & 0xFFFFF;
    int d = r & 63, t = (r >> 6) & 1023, h = r >> 16;
    float x = qkv[(size_t)t * 3072 + (which ? 0 : 1024) + h * 64 + d];
    if (which) x *= 0.125f;
    __nv_bfloat16 hf = __float2bfloat16(x);
    __nv_bfloat16 lf = __float2bfloat16(x - __bfloat162float(hf));
    if (which) { qhi[r] = hf; qlo[r] = lf; }
    else       { khi[r] = hf; klo[r] = lf; }
}

// ---- generic 3xBF16 mma GEMM: C = A * B^T + bias  (ldmatrix fragment loads) ----
#define KAH 72
#define GM_SMEM_BYTES ((64 * KAH * 2 + 128 * KAH * 2) * 2)

__global__ __launch_bounds__(256) void mma_gemm_bf16_kernel(
    const __nv_bfloat16* __restrict__ Ahg, const __nv_bfloat16* __restrict__ Alg,
    const __nv_bfloat16* __restrict__ Bhg, const __nv_bfloat16* __restrict__ Blg,
    float* __restrict__ C, int ldc, int K, const float* __restrict__ bias) {
    extern __shared__ char smc[];
    __nv_bfloat16* Ah = (__nv_bfloat16*)smc;          // [64][72]
    __nv_bfloat16* Al = Ah + 64 * KAH;
    __nv_bfloat16* Bh = Al + 64 * KAH;                // [128][72]
    __nv_bfloat16* Bl = Bh + 128 * KAH;

    const int tid = threadIdx.x;
    const int bx = blockIdx.x, by = blockIdx.y;
    const int w = tid >> 5, lane = tid & 31;
    const int gid = lane >> 2, qid = lane & 3;
    const int rt = (w & 3) * 16;
    const int ch = (w >> 2) * 64;

    // ldmatrix per-thread row addresses (A: 16-row tile; B: paired 8-row tiles)
    const int lrow = lane & 7;
    const int a_row = rt + ((lane >> 3) & 1) * 8 + lrow;
    const int a_col = ((lane >> 4) & 1) * 8;
    const uint32_t aAddrH = smem_u32(Ah + a_row * KAH + a_col);
    const uint32_t aAddrL = smem_u32(Al + a_row * KAH + a_col);
    const int b_row = ch + ((lane >> 4) & 1) * 8 + lrow;
    const int b_col = ((lane >> 3) & 1) * 8;
    const uint32_t bAddrH = smem_u32(Bh + b_row * KAH + b_col);
    const uint32_t bAddrL = smem_u32(Bl + b_row * KAH + b_col);

    const __nv_bfloat16* Ahb = Ahg + (size_t)(by * 64) * K;
    const __nv_bfloat16* Alb = Alg + (size_t)(by * 64) * K;
    const __nv_bfloat16* Bhb = Bhg + (size_t)(bx * 128) * K;
    const __nv_bfloat16* Blb = Blg + (size_t)(bx * 128) * K;

    float c[8][4];
#pragma unroll
    for (int nb = 0; nb < 8; nb++)
#pragma unroll
        for (int k = 0; k < 4; k++) c[nb][k] = 0.f;

    for (int k0 = 0; k0 < K; k0 += 64) {
        __syncthreads();
        for (int i = tid; i < 512; i += 256) {
            int r = i >> 3, c8 = (i & 7) * 8;
            *(uint4*)&Ah[r * KAH + c8] = *(const uint4*)(Ahb + (size_t)r * K + k0 + c8);
            *(uint4*)&Al[r * KAH + c8] = *(const uint4*)(Alb + (size_t)r * K + k0 + c8);
        }
        for (int i = tid; i < 1024; i += 256) {
            int r = i >> 3, c8 = (i & 7) * 8;
            *(uint4*)&Bh[r * KAH + c8] = *(const uint4*)(Bhb + (size_t)r * K + k0 + c8);
            *(uint4*)&Bl[r * KAH + c8] = *(const uint4*)(Blb + (size_t)r * K + k0 + c8);
        }
        __syncthreads();

#pragma unroll
        for (int ks16 = 0; ks16 < 4; ks16++) {
            const uint32_t koff = ks16 * 32;   // 16 bf16 = 32 bytes
            uint32_t ah0, ah1, ah2, ah3, al0, al1, al2, al3;
            ldsm_x4(ah0, ah1, ah2, ah3, aAddrH + koff);
            ldsm_x4(al0, al1, al2, al3, aAddrL + koff);
#pragma unroll
            for (int nbp = 0; nbp < 4; nbp++) {
                const uint32_t boff = nbp * (16 * KAH * 2) + koff;
                uint32_t bh0a, bh1a, bh0b, bh1b, bl0a, bl1a, bl0b, bl1b;
                ldsm_x4(bh0a, bh1a, bh0b, bh1b, bAddrH + boff);
                ldsm_x4(bl0a, bl1a, bl0b, bl1b, bAddrL + boff);
                const int nA = 2 * nbp, nB = 2 * nbp + 1;
                mma_bf16(c[nA][0], c[nA][1], c[nA][2], c[nA][3],
                         ah0, ah1, ah2, ah3, bh0a, bh1a);
                mma_bf16(c[nA][0], c[nA][1], c[nA][2], c[nA][3],
                         ah0, ah1, ah2, ah3, bl0a, bl1a);
                mma_bf16(c[nA][0], c[nA][1], c[nA][2], c[nA][3],
                         al0, al1, al2, al3, bh0a, bh1a);
                mma_bf16(c[nB][0], c[nB][1], c[nB][2], c[nB][3],
                         ah0, ah1, ah2, ah3, bh0b, bh1b);
                mma_bf16(c[nB][0], c[nB][1], c[nB][2], c[nB][3],
                         ah0, ah1, ah2, ah3, bl0b, bl1b);
                mma_bf16(c[nB][0], c[nB][1], c[nB][2], c[nB][3],
                         al0, al1, al2, al3, bh0b, bh1b);
            }
        }
    }

#pragma unroll
    for (int nb = 0; nb < 8; nb++) {
#pragma unroll
        for (int k = 0; k < 4; k++) {
            int row = by * 64 + rt + gid + (k >> 1) * 8;
            int col = bx * 128 + ch + nb * 8 + 2 * qid + (k & 1);
            C[(size_t)row * ldc + col] = c[nb][k] + bias[col];
        }
    }
}

// ---------------- ||key_store[h,m]||^2 (exact fp32) ----------------
__global__ void ksnorm_kernel(const float* __restrict__ ks, float* __restrict__ nrm) {
    int r = blockIdx.x * blockDim.x + threadIdx.x;
    if (r >= 16 * 8192) return;
    const float4* p = (const float4*)(ks + (size_t)r * 64);
    float s = 0.f;
#pragma unroll
    for (int i = 0; i < 16; i++) {
        float4 f = p[i];
        s += f.x * f.x + f.y * f.y + f.z * f.z + f.w * f.w;
    }
    nrm[r] = s;
}

// ------------- lexicographic (score, idx) compare: stable top-k --------------
__device__ __forceinline__ bool lex_lt(float sa, int ia, float sb, int ib) {
    return sa < sb || (sa == sb && ia < ib);
}

#define TOP4_INSERT(v, m, s0, x0, s1, x1, s2, x2, s3, x3)              \
    if (lex_lt(v, m, s3, x3)) {                                        \
        if (lex_lt(v, m, s2, x2)) {                                    \
            s3 = s2; x3 = x2;                                          \
            if (lex_lt(v, m, s1, x1)) {                                \
                s2 = s1; x2 = x1;                                      \
                if (lex_lt(v, m, s0, x0)) {                            \
                    s1 = s0; x1 = x0; s0 = v; x0 = m;                  \
                } else { s1 = v; x1 = m; }                             \
            } else { s2 = v; x2 = m; }                                 \
        } else { s3 = v; x3 = m; }                                     \
    }

// ---- fused kNN scores + top-4, bf16 mma + ldmatrix (64-row blocks) ----
#define KNN_SMEM_BYTES ((64 * KAH * 2 + 128 * KAH * 2) * 2 + 128 * 4)

__global__ __launch_bounds__(256) void knn_mma_kernel(
    const __nv_bfloat16* __restrict__ kh, const __nv_bfloat16* __restrict__ kl,
    const __nv_bfloat16* __restrict__ mh, const __nv_bfloat16* __restrict__ ml,
    const float* __restrict__ ksn, int* __restrict__ idx_out) {
    extern __shared__ char smc[];
    __nv_bfloat16* Ah = (__nv_bfloat16*)smc;          // [64][72]
    __nv_bfloat16* Al = Ah + 64 * KAH;
    __nv_bfloat16* Bh = Al + 64 * KAH;                // [128][72]
    __nv_bfloat16* Bl = Bh + 128 * KAH;
    float* Ns = (float*)(Bl + 128 * KAH);             // [128]

    const int tid = threadIdx.x;
    const int t0 = blockIdx.x * 64;
    const int h = blockIdx.y;
    const int w = tid >> 5, lane = tid & 31;
    const int gid = lane >> 2, qid = lane & 3;
    const int rt = (w & 3) * 16;
    const int ch = (w >> 2) * 64;

    const int lrow = lane & 7;
    const int a_row = rt + ((lane >> 3) & 1) * 8 + lrow;
    const int a_col = ((lane >> 4) & 1) * 8;
    const uint32_t aAddrH = smem_u32(Ah + a_row * KAH + a_col);
    const uint32_t aAddrL = smem_u32(Al + a_row * KAH + a_col);
    const int b_row = ch + ((lane >> 4) & 1) * 8 + lrow;
    const int b_col = ((lane >> 3) & 1) * 8;
    const uint32_t bAddrH = smem_u32(Bh + b_row * KAH + b_col);
    const uint32_t bAddrL = smem_u32(Bl + b_row * KAH + b_col);

    const __nv_bfloat16* Ahg = kh + ((size_t)h * 1024 + t0) * 64;
    const __nv_bfloat16* Alg = kl + ((size_t)h * 1024 + t0) * 64;
    for (int i = tid; i < 512; i += 256) {
        int r = i >> 3, c8 = (i & 7) * 8;
        *(uint4*)&Ah[r * KAH + c8] = *(const uint4*)(Ahg + (size_t)r * 64 + c8);
        *(uint4*)&Al[r * KAH + c8] = *(const uint4*)(Alg + (size_t)r * 64 + c8);
    }

    float S[2][4];
    int I[2][4];
#pragma unroll
    for (int r = 0; r < 2; r++)
#pragma unroll
        for (int k = 0; k < 4; k++) { S[r][k] = FLT_MAX; I[r][k] = 0x7fffffff; }

    const __nv_bfloat16* Bhg = mh + (size_t)h * 8192 * 64;
    const __nv_bfloat16* Blg = ml + (size_t)h * 8192 * 64;
    const float* Nbase = ksn + h * 8192;

    for (int chunk = 0; chunk < 64; chunk++) {
        const int m0 = chunk << 7;
        __syncthreads();
        if (tid < 128) Ns[tid] = Nbase[m0 + tid];
        for (int i = tid; i < 1024; i += 256) {
            int r = i >> 3, c8 = (i & 7) * 8;
            *(uint4*)&Bh[r * KAH + c8] = *(const uint4*)(Bhg + (size_t)(m0 + r) * 64 + c8);
            *(uint4*)&Bl[r * KAH + c8] = *(const uint4*)(Blg + (size_t)(m0 + r) * 64 + c8);
        }
        __syncthreads();

        float c[8][4];
#pragma unroll
        for (int nb = 0; nb < 8; nb++)
#pragma unroll
            for (int k = 0; k < 4; k++) c[nb][k] = 0.f;

#pragma unroll
        for (int ks16 = 0; ks16 < 4; ks16++) {
            const uint32_t koff = ks16 * 32;
            uint32_t ah0, ah1, ah2, ah3, al0, al1, al2, al3;
            ldsm_x4(ah0, ah1, ah2, ah3, aAddrH + koff);
            ldsm_x4(al0, al1, al2, al3, aAddrL + koff);
#pragma unroll
            for (int nbp = 0; nbp < 4; nbp++) {
                const uint32_t boff = nbp * (16 * KAH * 2) + koff;
                uint32_t bh0a, bh1a, bh0b, bh1b, bl0a, bl1a, bl0b, bl1b;
                ldsm_x4(bh0a, bh1a, bh0b, bh1b, bAddrH + boff);
                ldsm_x4(bl0a, bl1a, bl0b, bl1b, bAddrL + boff);
                const int nA = 2 * nbp, nB = 2 * nbp + 1;
                mma_bf16(c[nA][0], c[nA][1], c[nA][2], c[nA][3],
                         ah0, ah1, ah2, ah3, bh0a, bh1a);
                mma_bf16(c[nA][0], c[nA][1], c[nA][2], c[nA][3],
                         ah0, ah1, ah2, ah3, bl0a, bl1a);
                mma_bf16(c[nA][0], c[nA][1], c[nA][2], c[nA][3],
                         al0, al1, al2, al3, bh0a, bh1a);
                mma_bf16(c[nB][0], c[nB][1], c[nB][2], c[nB][3],
                         ah0, ah1, ah2, ah3, bh0b, bh1b);
                mma_bf16(c[nB][0], c[nB][1], c[nB][2], c[nB][3],
                         ah0, ah1, ah2, ah3, bl0b, bl1b);
                mma_bf16(c[nB][0], c[nB][1], c[nB][2], c[nB][3],
                         al0, al1, al2, al3, bh0b, bh1b);
            }
        }

#pragma unroll
        for (int nb = 0; nb < 8; nb++) {
#pragma unroll
            for (int k = 0; k < 4; k++) {
                int cl = ch + nb * 8 + 2 * qid + (k & 1);
                int r = k >> 1;
                float v = Ns[cl] - 2.0f * c[nb][k];
                int mg = m0 + cl;
                TOP4_INSERT(v, mg, S[r][0], I[r][0], S[r][1], I[r][1],
                            S[r][2], I[r][2], S[r][3], I[r][3]);
            }
        }
    }

    __syncthreads();
    float* msc = (float*)smc;                 // [64][32]
    int* mix = (int*)(smc + 16384);
    const int slot = (w >> 2) * 4 + qid;
#pragma unroll
    for (int r = 0; r < 2; r++) {
        int row = rt + gid + r * 8;
#pragma unroll
        for (int k = 0; k < 4; k++) {
            msc[(row * 8 + slot) * 4 + k] = S[r][k];
            mix[(row * 8 + slot) * 4 + k] = I[r][k];
        }
    }
    __syncthreads();
    if (tid < 64) {
        float f0 = FLT_MAX, f1 = FLT_MAX, f2 = FLT_MAX, f3 = FLT_MAX;
        int g0 = 0x7fffffff, g1 = 0x7fffffff, g2 = 0x7fffffff, g3 = 0x7fffffff;
        for (int c2 = 0; c2 < 32; c2++) {
            float v = msc[tid * 32 + c2];
            int m = mix[tid * 32 + c2];
            TOP4_INSERT(v, m, f0, g0, f1, g1, f2, g2, f3, g3);
        }
        size_t row = (size_t)h * 1024 + t0 + tid;
        idx_out[row * 4 + 0] = g0;
        idx_out[row * 4 + 1] = g1;
        idx_out[row * 4 + 2] = g2;
        idx_out[row * 4 + 3] = g3;
    }
}

// ---------------- warp-per-token last-row logits ----------------
__global__ void selA_kernel(const float* __restrict__ qkv, float* __restrict__ lg) {
    int h = blockIdx.y;
    int t = blockIdx.x * 8 + (threadIdx.x >> 5);
    int lane = threadIdx.x & 31;
    int d0 = lane * 2;
    const float* q = qkv + (size_t)1023 * 3072 + h * 64;
    const float* k = qkv + (size_t)t * 3072 + 1024 + h * 64;
    float s = q[d0] * k[d0] + q[d0 + 1] * k[d0 + 1];
#pragma unroll
    for (int o = 16; o > 0; o >>= 1) s += __shfl_xor_sync(0xffffffffu, s, o);
    if (lane == 0) lg[h * 1024 + t] = s * 0.125f;
}

// ---------------- per-head softmax of logits row -> sel ----------------
__global__ void selB_kernel(const float* __restrict__ lg, int* __restrict__ sel) {
    int h = blockIdx.x;
    int tid = threadIdx.x;
    int lane = tid & 31, warp = tid >> 5;
    __shared__ float red[8];
    __shared__ float bcast;

    float v[4];
#pragma unroll
    for (int u = 0; u < 4; u++) v[u] = lg[h * 1024 + tid + u * 256];
    float m = fmaxf(fmaxf(v[0], v[1]), fmaxf(v[2], v[3]));
#pragma unroll
    for (int o = 16; o > 0; o >>= 1) m = fmaxf(m, __shfl_xor_sync(0xffffffffu, m, o));
    if (lane == 0) red[warp] = m;
    __syncthreads();
    if (tid == 0) {
        float x = red[0];
#pragma unroll
        for (int w = 1; w < 8; w++) x = fmaxf(x, red[w]);
        bcast = x;
    }
    __syncthreads();
    m = bcast;
    float e[4], s = 0.f;
#pragma unroll
    for (int u = 0; u < 4; u++) { e[u] = __expf(v[u] - m); s += e[u]; }
#pragma unroll
    for (int o = 16; o > 0; o >>= 1) s += __shfl_xor_sync(0xffffffffu, s, o);
    if (lane == 0) red[warp] = s;
    __syncthreads();
    if (tid == 0) {
        float x = 0.f;
#pragma unroll
        for (int w = 0; w < 8; w++) x += red[w];
        bcast = x;
    }
    __syncthreads();
    float inv = 1.f / bcast;
#pragma unroll
    for (int u = 0; u < 4; u++)
        sel[h * 1024 + tid + u * 256] = (e[u] * inv >= (1.0f / 8192.0f)) ? 1 : 0;
}

// ---------------- per-token 5-way memory softmax & blend -> v_new ----------------
__device__ __forceinline__ float warp_sum(float v) {
#pragma unroll
    for (int o = 16; o > 0; o >>= 1) v += __shfl_xor_sync(0xffffffffu, v, o);
    return v;
}

__global__ void vnew_kernel(const float* __restrict__ qkv, const float* __restrict__ kstore,
                            const float* __restrict__ vstore, const int* __restrict__ idx,
                            const int* __restrict__ sel, float* __restrict__ vnew) {
    int gw = (blockIdx.x * blockDim.x + threadIdx.x) >> 5;
    int lane = threadIdx.x & 31;
    if (gw >= 16 * 1024) return;
    int h = gw >> 10, t = gw & 1023;

    const float* base = qkv + (size_t)t * 3072 + h * 64;
    int d0 = lane * 2;
    float q0 = base[d0],        q1 = base[d0 + 1];
    float k0 = base[1024 + d0], k1 = base[1024 + d0 + 1];
    float v0 = base[2048 + d0], v1 = base[2048 + d0 + 1];
    const float scale = 0.125f;

    float attf[5];
    attf[0] = warp_sum(q0 * k0 + q1 * k1) * scale;

    int ids[4];
#pragma unroll
    for (int s2 = 0; s2 < 4; s2++) ids[s2] = idx[(size_t)gw * 4 + s2];

    float fv0[4], fv1[4];
#pragma unroll
    for (int s2 = 0; s2 < 4; s2++) {
        const float* kp = kstore + ((size_t)h * 8192 + ids[s2]) * 64;
        attf[s2 + 1] = warp_sum(q0 * kp[d0] + q1 * kp[d0 + 1]) * scale;
        const float* vp = vstore + ((size_t)h * 8192 + ids[s2]) * 64;
        fv0[s2] = vp[d0]; fv1[s2] = vp[d0 + 1];
    }

    float mx = attf[0];
#pragma unroll
    for (int s2 = 1; s2 < 5; s2++) mx = fmaxf(mx, attf[s2]);
    float e[5], sum = 0.f;
#pragma unroll
    for (int s2 = 0; s2 < 5; s2++) { e[s2] = expf(attf[s2] - mx); sum += e[s2]; }
    float inv = 1.f / sum;

    float o0 = e[0] * v0, o1 = e[0] * v1;
#pragma unroll
    for (int s2 = 0; s2 < 4; s2++) { o0 += e[s2 + 1] * fv0[s2]; o1 += e[s2 + 1] * fv1[s2]; }
    o0 = o0 * inv * 0.5f + v0 * 0.5f;
    o1 = o1 * inv * 0.5f + v1 * 0.5f;

    bool sl = sel[gw] != 0;
    vnew[(size_t)gw * 64 + d0]     = sl ? o0 : v0;
    vnew[(size_t)gw * 64 + d0 + 1] = sl ? o1 : v1;
}

// ------- transpose+split v_new to bf16 hi/lo, [h][d][t] layout (for flash PV) -------
__global__ void vtrans_kernel(const float* __restrict__ vnew,
                              __nv_bfloat16* __restrict__ vth,
                              __nv_bfloat16* __restrict__ vtl) {
    __shared__ float sm[64][65];
    const int tid = threadIdx.x;
    const int t0 = blockIdx.x * 64, h = blockIdx.y;
    for (int i = tid; i < 4096; i += 256) {
        int tr = i >> 6, d = i & 63;
        sm[tr][d] = vnew[((size_t)h * 1024 + t0 + tr) * 64 + d];
    }
    __syncthreads();
    for (int i = tid; i < 4096; i += 256) {
        int d = i >> 6, tr = i & 63;
        float x = sm[tr][d];
        __nv_bfloat16 hh = __float2bfloat16(x);
        size_t o = ((size_t)h * 64 + d) * 1024 + t0 + tr;
        vth[o] = hh;
        vtl[o] = __float2bfloat16(x - __bfloat162float(hh));
    }
}

// -- fused flash attention, split-KV + ldmatrix: half the s-range per block --
#define FLM_SMEM_BYTES ((128 * KAH * 2 + 64 * KAH * 2 + 64 * KAH * 2) * 2)

__global__ __launch_bounds__(256) void flash_mma_kernel(
    const __nv_bfloat16* __restrict__ qhg, const __nv_bfloat16* __restrict__ qlg,
    const __nv_bfloat16* __restrict__ khg, const __nv_bfloat16* __restrict__ klg,
    const __nv_bfloat16* __restrict__ vth, const __nv_bfloat16* __restrict__ vtl,
    float* __restrict__ pO, float* __restrict__ pm, float* __restrict__ pl) {
    extern __shared__ char smc[];
    __nv_bfloat16* Qh = (__nv_bfloat16*)smc;          // [128][72]
    __nv_bfloat16* Ql = Qh + 128 * KAH;
    __nv_bfloat16* Kh = Ql + 128 * KAH;               // [64][72]
    __nv_bfloat16* Kl = Kh + 64 * KAH;
    __nv_bfloat16* Vh = Kl + 64 * KAH;                // [64][72]  (row = d, col = s)
    __nv_bfloat16* Vl = Vh + 64 * KAH;

    const int tid = threadIdx.x;
    const int bx = blockIdx.x, h = blockIdx.y;
    const int qb = bx >> 1, half = bx & 1;
    const int w = tid >> 5, lane = tid & 31;
    const int gid = lane >> 2, qid = lane & 3;
    const int rt = w * 16;
    const int t0 = qb * 128;

    const int lrow = lane & 7;
    const int a_row = rt + ((lane >> 3) & 1) * 8 + lrow;
    const int a_col = ((lane >> 4) & 1) * 8;
    const uint32_t qAddrH = smem_u32(Qh + a_row * KAH + a_col);
    const uint32_t qAddrL = smem_u32(Ql + a_row * KAH + a_col);
    const int b_row = ((lane >> 4) & 1) * 8 + lrow;
    const int b_col = ((lane >> 3) & 1) * 8;
    const uint32_t kAddrH = smem_u32(Kh + b_row * KAH + b_col);
    const uint32_t kAddrL = smem_u32(Kl + b_row * KAH + b_col);
    const uint32_t vAddrH = smem_u32(Vh + b_row * KAH + b_col);
    const uint32_t vAddrL = smem_u32(Vl + b_row * KAH + b_col);

    const __nv_bfloat16* Qhg = qhg + ((size_t)h * 1024 + t0) * 64;
    const __nv_bfloat16* Qlg = qlg + ((size_t)h * 1024 + t0) * 64;
    for (int i = tid; i < 1024; i += 256) {
        int r = i >> 3, c8 = (i & 7) * 8;
        *(uint4*)&Qh[r * KAH + c8] = *(const uint4*)(Qhg + (size_t)r * 64 + c8);
        *(uint4*)&Ql[r * KAH + c8] = *(const uint4*)(Qlg + (size_t)r * 64 + c8);
    }

    float m0 = -FLT_MAX, m1 = -FLT_MAX, l0 = 0.f, l1 = 0.f;
    float O[8][4];
#pragma unroll
    for (int nb = 0; nb < 8; nb++)
#pragma unroll
        for (int k = 0; k < 4; k++) O[nb][k] = 0.f;

    const int row0 = t0 + rt + gid, row1 = row0 + 8;
    const int jlo = half * (qb + 1);
    const int jhi = jlo + qb + 1;

    for (int j = jlo; j < jhi; j++) {
        const int s0 = j * 64;
        __syncthreads();
        const __nv_bfloat16* Khg = khg + ((size_t)h * 1024 + s0) * 64;
        const __nv_bfloat16* Klg = klg + ((size_t)h * 1024 + s0) * 64;
        for (int i = tid; i < 512; i += 256) {
            int r = i >> 3, c8 = (i & 7) * 8;
            *(uint4*)&Kh[r * KAH + c8] = *(const uint4*)(Khg + (size_t)r * 64 + c8);
            *(uint4*)&Kl[r * KAH + c8] = *(const uint4*)(Klg + (size_t)r * 64 + c8);
        }
        const __nv_bfloat16* Vhg = vth + (size_t)h * 64 * 1024 + s0;
        const __nv_bfloat16* Vlg = vtl + (size_t)h * 64 * 1024 + s0;
        for (int i = tid; i < 512; i += 256) {
            int r = i >> 3, c8 = (i & 7) * 8;
            *(uint4*)&Vh[r * KAH + c8] = *(const uint4*)(Vhg + (size_t)r * 1024 + c8);
            *(uint4*)&Vl[r * KAH + c8] = *(const uint4*)(Vlg + (size_t)r * 1024 + c8);
        }
        __syncthreads();

        // S = Q K^T (3xBF16, ldmatrix frags)
        float c[8][4];
#pragma unroll
        for (int nb = 0; nb < 8; nb++)
#pragma unroll
            for (int k = 0; k < 4; k++) c[nb][k] = 0.f;

#pragma unroll
        for (int ks16 = 0; ks16 < 4; ks16++) {
            const uint32_t koff = ks16 * 32;
            uint32_t ah0, ah1, ah2, ah3, al0, al1, al2, al3;
            ldsm_x4(ah0, ah1, ah2, ah3, qAddrH + koff);
            ldsm_x4(al0, al1, al2, al3, qAddrL + koff);
#pragma unroll
            for (int nbp = 0; nbp < 4; nbp++) {
                const uint32_t boff = nbp * (16 * KAH * 2) + koff;
                uint32_t bh0a, bh1a, bh0b, bh1b, bl0a, bl1a, bl0b, bl1b;
                ldsm_x4(bh0a, bh1a, bh0b, bh1b, kAddrH + boff);
                ldsm_x4(bl0a, bl1a, bl0b, bl1b, kAddrL + boff);
                const int nA = 2 * nbp, nB = 2 * nbp + 1;
                mma_bf16(c[nA][0], c[nA][1], c[nA][2], c[nA][3],
                         ah0, ah1, ah2, ah3, bh0a, bh1a);
                mma_bf16(c[nA][0], c[nA][1], c[nA][2], c[nA][3],
                         ah0, ah1, ah2, ah3, bl0a, bl1a);
                mma_bf16(c[nA][0], c[nA][1], c[nA][2], c[nA][3],
                         al0, al1, al2, al3, bh0a, bh1a);
                mma_bf16(c[nB][0], c[nB][1], c[nB][2], c[nB][3],
                         ah0, ah1, ah2, ah3, bh0b, bh1b);
                mma_bf16(c[nB][0], c[nB][1], c[nB][2], c[nB][3],
                         ah0, ah1, ah2, ah3, bl0b, bl1b);
                mma_bf16(c[nB][0], c[nB][1], c[nB][2], c[nB][3],
                         al0, al1, al2, al3, bh0b, bh1b);
            }
        }

        // causal mask
        if (s0 + 63 > t0 + rt) {
#pragma unroll
            for (int nb = 0; nb < 8; nb++) {
                int cb = s0 + nb * 8 + 2 * qid;
                if (cb > row0)     c[nb][0] = -FLT_MAX;
                if (cb + 1 > row0) c[nb][1] = -FLT_MAX;
                if (cb > row1)     c[nb][2] = -FLT_MAX;
                if (cb + 1 > row1) c[nb][3] = -FLT_MAX;
            }
        }

        // online softmax
        float rm0 = -FLT_MAX, rm1 = -FLT_MAX;
#pragma unroll
        for (int nb = 0; nb < 8; nb++) {
            rm0 = fmaxf(rm0, fmaxf(c[nb][0], c[nb][1]));
            rm1 = fmaxf(rm1, fmaxf(c[nb][2], c[nb][3]));
        }
        rm0 = fmaxf(rm0, __shfl_xor_sync(0xffffffffu, rm0, 1));
        rm0 = fmaxf(rm0, __shfl_xor_sync(0xffffffffu, rm0, 2));
        rm1 = fmaxf(rm1, __shfl_xor_sync(0xffffffffu, rm1, 1));
        rm1 = fmaxf(rm1, __shfl_xor_sync(0xffffffffu, rm1, 2));

        float mn0 = fmaxf(m0, rm0), mn1 = fmaxf(m1, rm1);
        float alpha0 = __expf(m0 - mn0), alpha1 = __expf(m1 - mn1);
        float ps0 = 0.f, ps1 = 0.f;
#pragma unroll
        for (int nb = 0; nb < 8; nb++) {
            c[nb][0] = __expf(c[nb][0] - mn0); ps0 += c[nb][0];
            c[nb][1] = __expf(c[nb][1] - mn0); ps0 += c[nb][1];
            c[nb][2] = __expf(c[nb][2] - mn1); ps1 += c[nb][2];
            c[nb][3] = __expf(c[nb][3] - mn1); ps1 += c[nb][3];
        }
        ps0 += __shfl_xor_sync(0xffffffffu, ps0, 1);
        ps0 += __shfl_xor_sync(0xffffffffu, ps0, 2);
        ps1 += __shfl_xor_sync(0xffffffffu, ps1, 1);
        ps1 += __shfl_xor_sync(0xffffffffu, ps1, 2);
        l0 = l0 * alpha0 + ps0; m0 = mn0;
        l1 = l1 * alpha1 + ps1; m1 = mn1;
#pragma unroll
        for (int nb = 0; nb < 8; nb++) {
            O[nb][0] *= alpha0; O[nb][1] *= alpha0;
            O[nb][2] *= alpha1; O[nb][3] *= alpha1;
        }

        // P@V (ldmatrix V frags; P converted in registers)
#pragma unroll
        for (int kb = 0; kb < 4; kb++) {
            float p00 = c[2 * kb][0],     p01 = c[2 * kb][1];
            float p02 = c[2 * kb][2],     p03 = c[2 * kb][3];
            float p10 = c[2 * kb + 1][0], p11 = c[2 * kb + 1][1];
            float p12 = c[2 * kb + 1][2], p13 = c[2 * kb + 1][3];
            __nv_bfloat16 h00 = __float2bfloat16(p00), h01 = __float2bfloat16(p01);
            __nv_bfloat16 h02 = __float2bfloat16(p02), h03 = __float2bfloat16(p03);
            __nv_bfloat16 h10 = __float2bfloat16(p10), h11 = __float2bfloat16(p11);
            __nv_bfloat16 h12 = __float2bfloat16(p12), h13 = __float2bfloat16(p13);
            uint32_t Ah0 = pack_bf16(h00, h01);
            uint32_t Ah1 = pack_bf16(h02, h03);
            uint32_t Ah2 = pack_bf16(h10, h11);
            uint32_t Ah3 = pack_bf16(h12, h13);
            uint32_t Al0 = pack_bf16(__float2bfloat16(p00 - __bfloat162float(h00)),
                                     __float2bfloat16(p01 - __bfloat162float(h01)));
            uint32_t Al1 = pack_bf16(__float2bfloat16(p02 - __bfloat162float(h02)),
                                     __float2bfloat16(p03 - __bfloat162float(h03)));
            uint32_t Al2 = pack_bf16(__float2bfloat16(p10 - __bfloat162float(h10)),
                                     __float2bfloat16(p11 - __bfloat162float(h11)));
            uint32_t Al3 = pack_bf16(__float2bfloat16(p12 - __bfloat162float(h12)),
                                     __float2bfloat16(p13 - __bfloat162float(h13)));
            const uint32_t koff = kb * 32;
#pragma unroll
            for (int nbp = 0; nbp < 4; nbp++) {
                const uint32_t boff = nbp * (16 * KAH * 2) + koff;
                uint32_t bh0a, bh1a, bh0b, bh1b, bl0a, bl1a, bl0b, bl1b;
                ldsm_x4(bh0a, bh1a, bh0b, bh1b, vAddrH + boff);
                ldsm_x4(bl0a, bl1a, bl0b, bl1b, vAddrL + boff);
                const int nA = 2 * nbp, nB = 2 * nbp + 1;
                mma_bf16(O[nA][0], O[nA][1], O[nA][2], O[nA][3],
                         Ah0, Ah1, Ah2, Ah3, bh0a, bh1a);
                mma_bf16(O[nA][0], O[nA][1], O[nA][2], O[nA][3],
                         Ah0, Ah1, Ah2, Ah3, bl0a, bl1a);
                mma_bf16(O[nA][0], O[nA][1], O[nA][2], O[nA][3],
                         Al0, Al1, Al2, Al3, bh0a, bh1a);
                mma_bf16(O[nB][0], O[nB][1], O[nB][2], O[nB][3],
                         Ah0, Ah1, Ah2, Ah3, bh0b, bh1b);
                mma_bf16(O[nB][0], O[nB][1], O[nB][2], O[nB][3],
                         Ah0, Ah1, Ah2, Ah3, bl0b, bl1b);
                mma_bf16(O[nB][0], O[nB][1], O[nB][2], O[nB][3],
                         Al0, Al1, Al2, Al3, bh0b, bh1b);
            }
        }
    }

    // epilogue: store unnormalized partial (m, l, O)
    const size_t base = ((size_t)half * 16 + h) * 1024;
    if (qid == 0) {
        pm[base + row0] = m0; pl[base + row0] = l0;
        pm[base + row1] = m1; pl[base + row1] = l1;
    }
#pragma unroll
    for (int nb = 0; nb < 8; nb++) {
        int colb = nb * 8 + 2 * qid;
        pO[(base + row0) * 64 + colb]     = O[nb][0];
        pO[(base + row0) * 64 + colb + 1] = O[nb][1];
        pO[(base + row1) * 64 + colb]     = O[nb][2];
        pO[(base + row1) * 64 + colb + 1] = O[nb][3];
    }
}

// ---- merge the two flash partials per (h, t) row -> yh/yl bf16 split directly ----
__global__ void flash_merge_kernel(const float* __restrict__ pO,
                                   const float* __restrict__ pm,
                                   const float* __restrict__ pl,
                                   __nv_bfloat16* __restrict__ yh,
                                   __nv_bfloat16* __restrict__ yl) {
    int i = blockIdx.x * 256 + threadIdx.x;   // < 16*1024*64 = 1M
    int d = i & 63, t = (i >> 6) & 1023, h = i >> 16;
    size_t r0 = (size_t)h * 1024 + t;
    size_t r1 = (size_t)16 * 1024 + r0;
    float ma = pm[r0], mb = pm[r1];
    float mm = fmaxf(ma, mb);
    float ea = __expf(ma - mm), eb = __expf(mb - mm);
    float l = pl[r0] * ea + pl[r1] * eb;
    float o = pO[r0 * 64 + d] * ea + pO[r1 * 64 + d] * eb;
    float val = o / l;
    __nv_bfloat16 hh = __float2bfloat16(val);
    size_t oi = (size_t)t * 1024 + h * 64 + d;
    yh[oi] = hh;
    yl[oi] = __float2bfloat16(val - __bfloat162float(hh));
}

// ---------------- launch ----------------
extern "C" void kernel_launch(void* const* d_in, const int* in_sizes, int n_in,
                              void* d_out, int out_size) {
    const float* x  = (const float*)d_in[0];
    const float* aw = (const float*)d_in[1];
    const float* ab = (const float*)d_in[2];
    const float* pw = (const float*)d_in[3];
    const float* pb = (const float*)d_in[4];
    const float* ks = (const float*)d_in[5];
    const float* vs = (const float*)d_in[6];
    float* out = (float*)d_out;

    float *qkv, *ksn, *lg, *vnw, *pO, *pm, *pl;
    __nv_bfloat16 *kh, *kl, *qh, *ql, *mh, *ml, *xh, *xl, *awh, *awl, *pwh, *pwl, *yh, *yl;
    __nv_bfloat16 *vth, *vtl;
    int *idx, *sel;
    cudaGetSymbolAddress((void**)&qkv, g_qkv);
    cudaGetSymbolAddress((void**)&ksn, g_ksnorm);
    cudaGetSymbolAddress((void**)&kh,  g_kh);
    cudaGetSymbolAddress((void**)&kl,  g_kl);
    cudaGetSymbolAddress((void**)&qh,  g_qh);
    cudaGetSymbolAddress((void**)&ql,  g_ql);
    cudaGetSymbolAddress((void**)&mh,  g_mh);
    cudaGetSymbolAddress((void**)&ml,  g_ml);
    cudaGetSymbolAddress((void**)&xh,  g_xh);
    cudaGetSymbolAddress((void**)&xl,  g_xl);
    cudaGetSymbolAddress((void**)&awh, g_awh);
    cudaGetSymbolAddress((void**)&awl, g_awl);
    cudaGetSymbolAddress((void**)&pwh, g_pwh);
    cudaGetSymbolAddress((void**)&pwl, g_pwl);
    cudaGetSymbolAddress((void**)&yh,  g_yh);
    cudaGetSymbolAddress((void**)&yl,  g_yl);
    cudaGetSymbolAddress((void**)&vth, g_vth);
    cudaGetSymbolAddress((void**)&vtl, g_vtl);
    cudaGetSymbolAddress((void**)&pO,  g_pO);
    cudaGetSymbolAddress((void**)&pm,  g_pm);
    cudaGetSymbolAddress((void**)&pl,  g_pl);
    cudaGetSymbolAddress((void**)&lg,  g_lg);
    cudaGetSymbolAddress((void**)&idx, g_idx);
    cudaGetSymbolAddress((void**)&sel, g_sel);
    cudaGetSymbolAddress((void**)&vnw, g_vnew);

    cudaFuncSetAttribute(knn_mma_kernel,
                         cudaFuncAttributeMaxDynamicSharedMemorySize, KNN_SMEM_BYTES);
    cudaFuncSetAttribute(mma_gemm_bf16_kernel,
                         cudaFuncAttributeMaxDynamicSharedMemorySize, GM_SMEM_BYTES);
    cudaFuncSetAttribute(flash_mma_kernel,
                         cudaFuncAttributeMaxDynamicSharedMemorySize, FLM_SMEM_BYTES);

    // 0) bf16 hi/lo splits
    split_bf16_v4<<<1024, 256>>>((const float4*)x,
                                 (__nv_bfloat162*)xh, (__nv_bfloat162*)xl);
    split_bf16_v4<<<3072, 256>>>((const float4*)aw,
                                 (__nv_bfloat162*)awh, (__nv_bfloat162*)awl);
    split_bf16_v4<<<1024, 256>>>((const float4*)pw,
                                 (__nv_bfloat162*)pwh, (__nv_bfloat162*)pwl);
    split_bf16_v4<<<8192, 256>>>((const float4*)ks,
                                 (__nv_bfloat162*)mh, (__nv_bfloat162*)ml);
    // 1) qkv = x @ c_attn_w^T + b   (3xBF16 mma + ldmatrix)
    mma_gemm_bf16_kernel<<<dim3(24, 16), 256, GM_SMEM_BYTES>>>(
        xh, xl, awh, awl, qkv, 3072, 1024, ab);
    // 2) key_store norms + k/q split/relayout
    ksnorm_kernel<<<512, 256>>>(ks, ksn);
    split_qk_bf16_kernel<<<2048, 1024>>>(qkv, kh, kl, qh, ql);
    // 3) fused kNN scores + top-4 (bf16 mma + ldmatrix, 64-row blocks)
    knn_mma_kernel<<<dim3(16, 16), 256, KNN_SMEM_BYTES>>>(
        kh, kl, mh, ml, ksn, idx);
    // 4) sel from last-row softmax
    selA_kernel<<<dim3(128, 16), 256>>>(qkv, lg);
    selB_kernel<<<16, 1024>>>(lg, sel);
    // 5) 5-way softmax blend -> v_new
    vnew_kernel<<<2048, 256>>>(qkv, ks, vs, idx, sel, vnw);
    // 5b) transpose+split v_new for flash PV
    vtrans_kernel<<<dim3(16, 16), 256>>>(vnw, vth, vtl);
    // 6) split-KV flash attention (partials) + fused merge/split -> yh/yl
    flash_mma_kernel<<<dim3(16, 16), 256, FLM_SMEM_BYTES>>>(
        qh, ql, kh, kl, vth, vtl, pO, pm, pl);
    flash_merge_kernel<<<4096, 256>>>(pO, pm, pl, yh, yl);
    // 7) out = y @ c_proj_w^T + b   (3xBF16 mma + ldmatrix)
    mma_gemm_bf16_kernel<<<dim3(8, 16), 256, GM_SMEM_BYTES>>>(
        yh, yl, pwh, pwl, out, 1024, 1024, pb);
}

// round 15
// speedup vs baseline: 1.6251x; 1.1533x over previous
#include <cuda_runtime.h>
#include <cuda_bf16.h>
#include <cfloat>
#include <cstdint>

// ---------------- scratch (__device__ globals; no allocations) ----------------
__device__ float g_qkv[1024 * 3072];              // 12 MB  (T, 3C)
__device__ float g_ksnorm[16 * 8192];             // (H, M)
__device__ __nv_bfloat16 g_kh[16 * 1024 * 64];    // bf16-hi of k, [h][t][d]
__device__ __nv_bfloat16 g_kl[16 * 1024 * 64];    // bf16-lo of k
__device__ __nv_bfloat16 g_qh[16 * 1024 * 64];    // bf16-hi of q*0.125, [h][t][d]
__device__ __nv_bfloat16 g_ql[16 * 1024 * 64];    // bf16-lo
__device__ __nv_bfloat16 g_mh[16 * 8192 * 64];    // bf16-hi of key_store
__device__ __nv_bfloat16 g_ml[16 * 8192 * 64];    // bf16-lo of key_store
__device__ __nv_bfloat16 g_xh[1024 * 1024];       // bf16-hi of x
__device__ __nv_bfloat16 g_xl[1024 * 1024];
__device__ __nv_bfloat16 g_awh[3072 * 1024];      // bf16-hi of c_attn_w
__device__ __nv_bfloat16 g_awl[3072 * 1024];
__device__ __nv_bfloat16 g_pwh[1024 * 1024];      // bf16-hi of c_proj_w
__device__ __nv_bfloat16 g_pwl[1024 * 1024];
__device__ __nv_bfloat16 g_yh[1024 * 1024];       // bf16-hi of y (written by merge)
__device__ __nv_bfloat16 g_yl[1024 * 1024];
__device__ __nv_bfloat16 g_vth[16 * 64 * 1024];   // bf16-hi of v_new^T, [h][d][t]
__device__ __nv_bfloat16 g_vtl[16 * 64 * 1024];   // bf16-lo
__device__ float g_pO[2 * 16 * 1024 * 64];        // flash partial O [half][h][t][d]
__device__ float g_pm[2 * 16 * 1024];             // flash partial row max
__device__ float g_pl[2 * 16 * 1024];             // flash partial row sum
__device__ float g_lg[16 * 1024];                 // last-row logits
__device__ int   g_idx[16 * 1024 * 4];            // (H, T, 4)
__device__ int   g_sel[16 * 1024];                // (H, T)
__device__ float g_vnew[16 * 1024 * 64];          // (H, T, d)

// ---------------- helpers ----------------
__device__ __forceinline__ void mma_bf16(float& c0, float& c1, float& c2, float& c3,
                                         uint32_t a0, uint32_t a1, uint32_t a2, uint32_t a3,
                                         uint32_t b0, uint32_t b1) {
    asm volatile(
        "mma.sync.aligned.m16n8k16.row.col.f32.bf16.bf16.f32 "
        "{%0,%1,%2,%3}, {%4,%5,%6,%7}, {%8,%9}, {%0,%1,%2,%3};"
        : "+f"(c0), "+f"(c1), "+f"(c2), "+f"(c3)
        : "r"(a0), "r"(a1), "r"(a2), "r"(a3), "r"(b0), "r"(b1));
}

__device__ __forceinline__ void ldsm_x4(uint32_t& r0, uint32_t& r1,
                                        uint32_t& r2, uint32_t& r3, uint32_t addr) {
    asm volatile("ldmatrix.sync.aligned.m8n8.x4.shared.b16 {%0,%1,%2,%3}, [%4];"
                 : "=r"(r0), "=r"(r1), "=r"(r2), "=r"(r3) : "r"(addr));
}

__device__ __forceinline__ uint32_t smem_u32(const void* p) {
    return (uint32_t)__cvta_generic_to_shared(p);
}

__device__ __forceinline__ void cp_async16(uint32_t dst, const void* src) {
    asm volatile("cp.async.cg.shared.global [%0], [%1], 16;" :: "r"(dst), "l"(src));
}

__device__ __forceinline__ void cp_async4(uint32_t dst, const void* src) {
    asm volatile("cp.async.ca.shared.global [%0], [%1], 4;" :: "r"(dst), "l"(src));
}

__device__ __forceinline__ uint32_t pack_bf16(__nv_bfloat16 lo, __nv_bfloat16 hi) {
    __nv_bfloat162 t;
    t.x = lo; t.y = hi;
    return *(uint32_t*)&t;
}

// ---------- vectorized contiguous bf16 hi/lo split (4 floats / thread) ----------
__global__ void split_bf16_v4(const float4* __restrict__ src,
                              __nv_bfloat162* __restrict__ hi,
                              __nv_bfloat162* __restrict__ lo) {
    size_t i = (size_t)blockIdx.x * 256 + threadIdx.x;
    float4 v = src[i];
    __nv_bfloat16 h0 = __float2bfloat16(v.x), h1 = __float2bfloat16(v.y);
    __nv_bfloat16 h2 = __float2bfloat16(v.z), h3 = __float2bfloat16(v.w);
    __nv_bfloat16 l0 = __float2bfloat16(v.x - __bfloat162float(h0));
    __nv_bfloat16 l1 = __float2bfloat16(v.y - __bfloat162float(h1));
    __nv_bfloat16 l2 = __float2bfloat16(v.z - __bfloat162float(h2));
    __nv_bfloat16 l3 = __float2bfloat16(v.w - __bfloat162float(h3));
    hi[i * 2 + 0] = __nv_bfloat162{h0, h1};
    hi[i * 2 + 1] = __nv_bfloat162{h2, h3};
    lo[i * 2 + 0] = __nv_bfloat162{l0, l1};
    lo[i * 2 + 1] = __nv_bfloat162{l2, l3};
}

// -- bf16 hi/lo split of k AND q (scaled 0.125) from qkv, relayout to [h][t][d] --
__global__ void split_qk_bf16_kernel(const float* __restrict__ qkv,
                                     __nv_bfloat16* __restrict__ khi,
                                     __nv_bfloat16* __restrict__ klo,
                                     __nv_bfloat16* __restrict__ qhi,
                                     __nv_bfloat16* __restrict__ qlo) {
    int i = blockIdx.x * 1024 + threadIdx.x;  // 2M
    int which = i >> 20;                      // 0: k, 1: q
    int r = i & 0xFFFFF;
    int d = r & 63, t = (r >> 6) & 1023, h = r >> 16;
    float x = qkv[(size_t)t * 3072 + (which ? 0 : 1024) + h * 64 + d];
    if (which) x *= 0.125f;
    __nv_bfloat16 hf = __float2bfloat16(x);
    __nv_bfloat16 lf = __float2bfloat16(x - __bfloat162float(hf));
    if (which) { qhi[r] = hf; qlo[r] = lf; }
    else       { khi[r] = hf; klo[r] = lf; }
}

// ---- generic 3xBF16 mma GEMM: C = A * B^T + bias  (ldmatrix fragment loads) ----
#define KAH 72
#define GM_SMEM_BYTES ((64 * KAH * 2 + 128 * KAH * 2) * 2)

__global__ __launch_bounds__(256) void mma_gemm_bf16_kernel(
    const __nv_bfloat16* __restrict__ Ahg, const __nv_bfloat16* __restrict__ Alg,
    const __nv_bfloat16* __restrict__ Bhg, const __nv_bfloat16* __restrict__ Blg,
    float* __restrict__ C, int ldc, int K, const float* __restrict__ bias) {
    extern __shared__ char smc[];
    __nv_bfloat16* Ah = (__nv_bfloat16*)smc;          // [64][72]
    __nv_bfloat16* Al = Ah + 64 * KAH;
    __nv_bfloat16* Bh = Al + 64 * KAH;                // [128][72]
    __nv_bfloat16* Bl = Bh + 128 * KAH;

    const int tid = threadIdx.x;
    const int bx = blockIdx.x, by = blockIdx.y;
    const int w = tid >> 5, lane = tid & 31;
    const int gid = lane >> 2, qid = lane & 3;
    const int rt = (w & 3) * 16;
    const int ch = (w >> 2) * 64;

    const int lrow = lane & 7;
    const int a_row = rt + ((lane >> 3) & 1) * 8 + lrow;
    const int a_col = ((lane >> 4) & 1) * 8;
    const uint32_t aAddrH = smem_u32(Ah + a_row * KAH + a_col);
    const uint32_t aAddrL = smem_u32(Al + a_row * KAH + a_col);
    const int b_row = ch + ((lane >> 4) & 1) * 8 + lrow;
    const int b_col = ((lane >> 3) & 1) * 8;
    const uint32_t bAddrH = smem_u32(Bh + b_row * KAH + b_col);
    const uint32_t bAddrL = smem_u32(Bl + b_row * KAH + b_col);

    const __nv_bfloat16* Ahb = Ahg + (size_t)(by * 64) * K;
    const __nv_bfloat16* Alb = Alg + (size_t)(by * 64) * K;
    const __nv_bfloat16* Bhb = Bhg + (size_t)(bx * 128) * K;
    const __nv_bfloat16* Blb = Blg + (size_t)(bx * 128) * K;

    float c[8][4];
#pragma unroll
    for (int nb = 0; nb < 8; nb++)
#pragma unroll
        for (int k = 0; k < 4; k++) c[nb][k] = 0.f;

    for (int k0 = 0; k0 < K; k0 += 64) {
        __syncthreads();
        for (int i = tid; i < 512; i += 256) {
            int r = i >> 3, c8 = (i & 7) * 8;
            *(uint4*)&Ah[r * KAH + c8] = *(const uint4*)(Ahb + (size_t)r * K + k0 + c8);
            *(uint4*)&Al[r * KAH + c8] = *(const uint4*)(Alb + (size_t)r * K + k0 + c8);
        }
        for (int i = tid; i < 1024; i += 256) {
            int r = i >> 3, c8 = (i & 7) * 8;
            *(uint4*)&Bh[r * KAH + c8] = *(const uint4*)(Bhb + (size_t)r * K + k0 + c8);
            *(uint4*)&Bl[r * KAH + c8] = *(const uint4*)(Blb + (size_t)r * K + k0 + c8);
        }
        __syncthreads();

#pragma unroll
        for (int ks16 = 0; ks16 < 4; ks16++) {
            const uint32_t koff = ks16 * 32;   // 16 bf16 = 32 bytes
            uint32_t ah0, ah1, ah2, ah3, al0, al1, al2, al3;
            ldsm_x4(ah0, ah1, ah2, ah3, aAddrH + koff);
            ldsm_x4(al0, al1, al2, al3, aAddrL + koff);
#pragma unroll
            for (int nbp = 0; nbp < 4; nbp++) {
                const uint32_t boff = nbp * (16 * KAH * 2) + koff;
                uint32_t bh0a, bh1a, bh0b, bh1b, bl0a, bl1a, bl0b, bl1b;
                ldsm_x4(bh0a, bh1a, bh0b, bh1b, bAddrH + boff);
                ldsm_x4(bl0a, bl1a, bl0b, bl1b, bAddrL + boff);
                const int nA = 2 * nbp, nB = 2 * nbp + 1;
                mma_bf16(c[nA][0], c[nA][1], c[nA][2], c[nA][3],
                         ah0, ah1, ah2, ah3, bh0a, bh1a);
                mma_bf16(c[nA][0], c[nA][1], c[nA][2], c[nA][3],
                         ah0, ah1, ah2, ah3, bl0a, bl1a);
                mma_bf16(c[nA][0], c[nA][1], c[nA][2], c[nA][3],
                         al0, al1, al2, al3, bh0a, bh1a);
                mma_bf16(c[nB][0], c[nB][1], c[nB][2], c[nB][3],
                         ah0, ah1, ah2, ah3, bh0b, bh1b);
                mma_bf16(c[nB][0], c[nB][1], c[nB][2], c[nB][3],
                         ah0, ah1, ah2, ah3, bl0b, bl1b);
                mma_bf16(c[nB][0], c[nB][1], c[nB][2], c[nB][3],
                         al0, al1, al2, al3, bh0b, bh1b);
            }
        }
    }

#pragma unroll
    for (int nb = 0; nb < 8; nb++) {
#pragma unroll
        for (int k = 0; k < 4; k++) {
            int row = by * 64 + rt + gid + (k >> 1) * 8;
            int col = bx * 128 + ch + nb * 8 + 2 * qid + (k & 1);
            C[(size_t)row * ldc + col] = c[nb][k] + bias[col];
        }
    }
}

// ---------------- ||key_store[h,m]||^2 (exact fp32) ----------------
__global__ void ksnorm_kernel(const float* __restrict__ ks, float* __restrict__ nrm) {
    int r = blockIdx.x * blockDim.x + threadIdx.x;
    if (r >= 16 * 8192) return;
    const float4* p = (const float4*)(ks + (size_t)r * 64);
    float s = 0.f;
#pragma unroll
    for (int i = 0; i < 16; i++) {
        float4 f = p[i];
        s += f.x * f.x + f.y * f.y + f.z * f.z + f.w * f.w;
    }
    nrm[r] = s;
}

// ------------- lexicographic (score, idx) compare: stable top-k --------------
__device__ __forceinline__ bool lex_lt(float sa, int ia, float sb, int ib) {
    return sa < sb || (sa == sb && ia < ib);
}

#define TOP4_INSERT(v, m, s0, x0, s1, x1, s2, x2, s3, x3)              \
    if (lex_lt(v, m, s3, x3)) {                                        \
        if (lex_lt(v, m, s2, x2)) {                                    \
            s3 = s2; x3 = x2;                                          \
            if (lex_lt(v, m, s1, x1)) {                                \
                s2 = s1; x2 = x1;                                      \
                if (lex_lt(v, m, s0, x0)) {                            \
                    s1 = s0; x1 = x0; s0 = v; x0 = m;                  \
                } else { s1 = v; x1 = m; }                             \
            } else { s2 = v; x2 = m; }                                 \
        } else { s3 = v; x3 = m; }                                     \
    }

// ---- fused kNN scores + top-4, bf16 mma + ldmatrix + cp.async double buffer ----
// smem: Ah/Al [64][72], 2x (Bh/Bl [128][72]), 2x Ns[128]
#define KNN_SMEM_BYTES (18432 + 73728 + 1024)

__global__ __launch_bounds__(256) void knn_mma_kernel(
    const __nv_bfloat16* __restrict__ kh, const __nv_bfloat16* __restrict__ kl,
    const __nv_bfloat16* __restrict__ mh, const __nv_bfloat16* __restrict__ ml,
    const float* __restrict__ ksn, int* __restrict__ idx_out) {
    extern __shared__ char smc[];
    __nv_bfloat16* Ah = (__nv_bfloat16*)smc;          // [64][72]
    __nv_bfloat16* Al = Ah + 64 * KAH;
    __nv_bfloat16* Bbuf = Al + 64 * KAH;              // 2 x (Bh, Bl) [128][72]
    float* NsBase = (float*)(Bbuf + 4 * 128 * KAH);   // 2 x [128]

    const int tid = threadIdx.x;
    const int t0 = blockIdx.x * 64;
    const int h = blockIdx.y;
    const int w = tid >> 5, lane = tid & 31;
    const int gid = lane >> 2, qid = lane & 3;
    const int rt = (w & 3) * 16;
    const int ch = (w >> 2) * 64;

    const int lrow = lane & 7;
    const int a_row = rt + ((lane >> 3) & 1) * 8 + lrow;
    const int a_col = ((lane >> 4) & 1) * 8;
    const uint32_t aAddrH = smem_u32(Ah + a_row * KAH + a_col);
    const uint32_t aAddrL = smem_u32(Al + a_row * KAH + a_col);
    const int b_row = ch + ((lane >> 4) & 1) * 8 + lrow;
    const int b_col = ((lane >> 3) & 1) * 8;
    uint32_t bAddrH[2], bAddrL[2];
#pragma unroll
    for (int b = 0; b < 2; b++) {
        __nv_bfloat16* BhB = Bbuf + b * (2 * 128 * KAH);
        __nv_bfloat16* BlB = BhB + 128 * KAH;
        bAddrH[b] = smem_u32(BhB + b_row * KAH + b_col);
        bAddrL[b] = smem_u32(BlB + b_row * KAH + b_col);
    }

    const __nv_bfloat16* Ahg = kh + ((size_t)h * 1024 + t0) * 64;
    const __nv_bfloat16* Alg = kl + ((size_t)h * 1024 + t0) * 64;
    for (int i = tid; i < 512; i += 256) {
        int r = i >> 3, c8 = (i & 7) * 8;
        *(uint4*)&Ah[r * KAH + c8] = *(const uint4*)(Ahg + (size_t)r * 64 + c8);
        *(uint4*)&Al[r * KAH + c8] = *(const uint4*)(Alg + (size_t)r * 64 + c8);
    }

    float S[2][4];
    int I[2][4];
#pragma unroll
    for (int r = 0; r < 2; r++)
#pragma unroll
        for (int k = 0; k < 4; k++) { S[r][k] = FLT_MAX; I[r][k] = 0x7fffffff; }

    const __nv_bfloat16* Bhg = mh + (size_t)h * 8192 * 64;
    const __nv_bfloat16* Blg = ml + (size_t)h * 8192 * 64;
    const float* Nbase = ksn + h * 8192;

    auto issue = [&](int chunk, int b) {
        const int m0 = chunk << 7;
        __nv_bfloat16* BhB = Bbuf + b * (2 * 128 * KAH);
        __nv_bfloat16* BlB = BhB + 128 * KAH;
        for (int i = tid; i < 1024; i += 256) {
            int r = i >> 3, c8 = (i & 7) * 8;
            cp_async16(smem_u32(BhB + r * KAH + c8), Bhg + (size_t)(m0 + r) * 64 + c8);
            cp_async16(smem_u32(BlB + r * KAH + c8), Blg + (size_t)(m0 + r) * 64 + c8);
        }
        if (tid < 128) cp_async4(smem_u32(NsBase + b * 128 + tid), Nbase + m0 + tid);
        asm volatile("cp.async.commit_group;" ::: "memory");
    };

    issue(0, 0);

    for (int chunk = 0; chunk < 64; chunk++) {
        const int b = chunk & 1;
        asm volatile("cp.async.wait_group 0;" ::: "memory");
        __syncthreads();                       // buf b visible to all threads
        if (chunk + 1 < 64) issue(chunk + 1, b ^ 1);   // overlaps with compute below
        const float* Ns = NsBase + b * 128;

        float c[8][4];
#pragma unroll
        for (int nb = 0; nb < 8; nb++)
#pragma unroll
            for (int k = 0; k < 4; k++) c[nb][k] = 0.f;

#pragma unroll
        for (int ks16 = 0; ks16 < 4; ks16++) {
            const uint32_t koff = ks16 * 32;
            uint32_t ah0, ah1, ah2, ah3, al0, al1, al2, al3;
            ldsm_x4(ah0, ah1, ah2, ah3, aAddrH + koff);
            ldsm_x4(al0, al1, al2, al3, aAddrL + koff);
#pragma unroll
            for (int nbp = 0; nbp < 4; nbp++) {
                const uint32_t boff = nbp * (16 * KAH * 2) + koff;
                uint32_t bh0a, bh1a, bh0b, bh1b, bl0a, bl1a, bl0b, bl1b;
                ldsm_x4(bh0a, bh1a, bh0b, bh1b, bAddrH[b] + boff);
                ldsm_x4(bl0a, bl1a, bl0b, bl1b, bAddrL[b] + boff);
                const int nA = 2 * nbp, nB = 2 * nbp + 1;
                mma_bf16(c[nA][0], c[nA][1], c[nA][2], c[nA][3],
                         ah0, ah1, ah2, ah3, bh0a, bh1a);
                mma_bf16(c[nA][0], c[nA][1], c[nA][2], c[nA][3],
                         ah0, ah1, ah2, ah3, bl0a, bl1a);
                mma_bf16(c[nA][0], c[nA][1], c[nA][2], c[nA][3],
                         al0, al1, al2, al3, bh0a, bh1a);
                mma_bf16(c[nB][0], c[nB][1], c[nB][2], c[nB][3],
                         ah0, ah1, ah2, ah3, bh0b, bh1b);
                mma_bf16(c[nB][0], c[nB][1], c[nB][2], c[nB][3],
                         ah0, ah1, ah2, ah3, bl0b, bl1b);
                mma_bf16(c[nB][0], c[nB][1], c[nB][2], c[nB][3],
                         al0, al1, al2, al3, bh0b, bh1b);
            }
        }

        const int m0 = chunk << 7;
#pragma unroll
        for (int nb = 0; nb < 8; nb++) {
#pragma unroll
            for (int k = 0; k < 4; k++) {
                int cl = ch + nb * 8 + 2 * qid + (k & 1);
                int r = k >> 1;
                float v = Ns[cl] - 2.0f * c[nb][k];
                int mg = m0 + cl;
                TOP4_INSERT(v, mg, S[r][0], I[r][0], S[r][1], I[r][1],
                            S[r][2], I[r][2], S[r][3], I[r][3]);
            }
        }
        __syncthreads();    // all warps done with buf b before its next overwrite
    }

    float* msc = (float*)smc;                 // [64][32]
    int* mix = (int*)(smc + 16384);
    const int slot = (w >> 2) * 4 + qid;
#pragma unroll
    for (int r = 0; r < 2; r++) {
        int row = rt + gid + r * 8;
#pragma unroll
        for (int k = 0; k < 4; k++) {
            msc[(row * 8 + slot) * 4 + k] = S[r][k];
            mix[(row * 8 + slot) * 4 + k] = I[r][k];
        }
    }
    __syncthreads();
    if (tid < 64) {
        float f0 = FLT_MAX, f1 = FLT_MAX, f2 = FLT_MAX, f3 = FLT_MAX;
        int g0 = 0x7fffffff, g1 = 0x7fffffff, g2 = 0x7fffffff, g3 = 0x7fffffff;
        for (int c2 = 0; c2 < 32; c2++) {
            float v = msc[tid * 32 + c2];
            int m = mix[tid * 32 + c2];
            TOP4_INSERT(v, m, f0, g0, f1, g1, f2, g2, f3, g3);
        }
        size_t row = (size_t)h * 1024 + t0 + tid;
        idx_out[row * 4 + 0] = g0;
        idx_out[row * 4 + 1] = g1;
        idx_out[row * 4 + 2] = g2;
        idx_out[row * 4 + 3] = g3;
    }
}

// ---------------- warp-per-token last-row logits ----------------
__global__ void selA_kernel(const float* __restrict__ qkv, float* __restrict__ lg) {
    int h = blockIdx.y;
    int t = blockIdx.x * 8 + (threadIdx.x >> 5);
    int lane = threadIdx.x & 31;
    int d0 = lane * 2;
    const float* q = qkv + (size_t)1023 * 3072 + h * 64;
    const float* k = qkv + (size_t)t * 3072 + 1024 + h * 64;
    float s = q[d0] * k[d0] + q[d0 + 1] * k[d0 + 1];
#pragma unroll
    for (int o = 16; o > 0; o >>= 1) s += __shfl_xor_sync(0xffffffffu, s, o);
    if (lane == 0) lg[h * 1024 + t] = s * 0.125f;
}

// ---------------- per-head softmax of logits row -> sel ----------------
__global__ void selB_kernel(const float* __restrict__ lg, int* __restrict__ sel) {
    int h = blockIdx.x;
    int tid = threadIdx.x;
    int lane = tid & 31, warp = tid >> 5;
    __shared__ float red[8];
    __shared__ float bcast;

    float v[4];
#pragma unroll
    for (int u = 0; u < 4; u++) v[u] = lg[h * 1024 + tid + u * 256];
    float m = fmaxf(fmaxf(v[0], v[1]), fmaxf(v[2], v[3]));
#pragma unroll
    for (int o = 16; o > 0; o >>= 1) m = fmaxf(m, __shfl_xor_sync(0xffffffffu, m, o));
    if (lane == 0) red[warp] = m;
    __syncthreads();
    if (tid == 0) {
        float x = red[0];
#pragma unroll
        for (int w = 1; w < 8; w++) x = fmaxf(x, red[w]);
        bcast = x;
    }
    __syncthreads();
    m = bcast;
    float e[4], s = 0.f;
#pragma unroll
    for (int u = 0; u < 4; u++) { e[u] = __expf(v[u] - m); s += e[u]; }
#pragma unroll
    for (int o = 16; o > 0; o >>= 1) s += __shfl_xor_sync(0xffffffffu, s, o);
    if (lane == 0) red[warp] = s;
    __syncthreads();
    if (tid == 0) {
        float x = 0.f;
#pragma unroll
        for (int w = 0; w < 8; w++) x += red[w];
        bcast = x;
    }
    __syncthreads();
    float inv = 1.f / bcast;
#pragma unroll
    for (int u = 0; u < 4; u++)
        sel[h * 1024 + tid + u * 256] = (e[u] * inv >= (1.0f / 8192.0f)) ? 1 : 0;
}

// ---------------- per-token 5-way memory softmax & blend -> v_new ----------------
__device__ __forceinline__ float warp_sum(float v) {
#pragma unroll
    for (int o = 16; o > 0; o >>= 1) v += __shfl_xor_sync(0xffffffffu, v, o);
    return v;
}

__global__ void vnew_kernel(const float* __restrict__ qkv, const float* __restrict__ kstore,
                            const float* __restrict__ vstore, const int* __restrict__ idx,
                            const int* __restrict__ sel, float* __restrict__ vnew) {
    int gw = (blockIdx.x * blockDim.x + threadIdx.x) >> 5;
    int lane = threadIdx.x & 31;
    if (gw >= 16 * 1024) return;
    int h = gw >> 10, t = gw & 1023;

    const float* base = qkv + (size_t)t * 3072 + h * 64;
    int d0 = lane * 2;
    float q0 = base[d0],        q1 = base[d0 + 1];
    float k0 = base[1024 + d0], k1 = base[1024 + d0 + 1];
    float v0 = base[2048 + d0], v1 = base[2048 + d0 + 1];
    const float scale = 0.125f;

    float attf[5];
    attf[0] = warp_sum(q0 * k0 + q1 * k1) * scale;

    int ids[4];
#pragma unroll
    for (int s2 = 0; s2 < 4; s2++) ids[s2] = idx[(size_t)gw * 4 + s2];

    float fv0[4], fv1[4];
#pragma unroll
    for (int s2 = 0; s2 < 4; s2++) {
        const float* kp = kstore + ((size_t)h * 8192 + ids[s2]) * 64;
        attf[s2 + 1] = warp_sum(q0 * kp[d0] + q1 * kp[d0 + 1]) * scale;
        const float* vp = vstore + ((size_t)h * 8192 + ids[s2]) * 64;
        fv0[s2] = vp[d0]; fv1[s2] = vp[d0 + 1];
    }

    float mx = attf[0];
#pragma unroll
    for (int s2 = 1; s2 < 5; s2++) mx = fmaxf(mx, attf[s2]);
    float e[5], sum = 0.f;
#pragma unroll
    for (int s2 = 0; s2 < 5; s2++) { e[s2] = expf(attf[s2] - mx); sum += e[s2]; }
    float inv = 1.f / sum;

    float o0 = e[0] * v0, o1 = e[0] * v1;
#pragma unroll
    for (int s2 = 0; s2 < 4; s2++) { o0 += e[s2 + 1] * fv0[s2]; o1 += e[s2 + 1] * fv1[s2]; }
    o0 = o0 * inv * 0.5f + v0 * 0.5f;
    o1 = o1 * inv * 0.5f + v1 * 0.5f;

    bool sl = sel[gw] != 0;
    vnew[(size_t)gw * 64 + d0]     = sl ? o0 : v0;
    vnew[(size_t)gw * 64 + d0 + 1] = sl ? o1 : v1;
}

// ------- transpose+split v_new to bf16 hi/lo, [h][d][t] layout (for flash PV) -------
__global__ void vtrans_kernel(const float* __restrict__ vnew,
                              __nv_bfloat16* __restrict__ vth,
                              __nv_bfloat16* __restrict__ vtl) {
    __shared__ float sm[64][65];
    const int tid = threadIdx.x;
    const int t0 = blockIdx.x * 64, h = blockIdx.y;
    for (int i = tid; i < 4096; i += 256) {
        int tr = i >> 6, d = i & 63;
        sm[tr][d] = vnew[((size_t)h * 1024 + t0 + tr) * 64 + d];
    }
    __syncthreads();
    for (int i = tid; i < 4096; i += 256) {
        int d = i >> 6, tr = i & 63;
        float x = sm[tr][d];
        __nv_bfloat16 hh = __float2bfloat16(x);
        size_t o = ((size_t)h * 64 + d) * 1024 + t0 + tr;
        vth[o] = hh;
        vtl[o] = __float2bfloat16(x - __bfloat162float(hh));
    }
}

// -- fused flash attention, split-KV + ldmatrix: half the s-range per block --
#define FLM_SMEM_BYTES ((128 * KAH * 2 + 64 * KAH * 2 + 64 * KAH * 2) * 2)

__global__ __launch_bounds__(256) void flash_mma_kernel(
    const __nv_bfloat16* __restrict__ qhg, const __nv_bfloat16* __restrict__ qlg,
    const __nv_bfloat16* __restrict__ khg, const __nv_bfloat16* __restrict__ klg,
    const __nv_bfloat16* __restrict__ vth, const __nv_bfloat16* __restrict__ vtl,
    float* __restrict__ pO, float* __restrict__ pm, float* __restrict__ pl) {
    extern __shared__ char smc[];
    __nv_bfloat16* Qh = (__nv_bfloat16*)smc;          // [128][72]
    __nv_bfloat16* Ql = Qh + 128 * KAH;
    __nv_bfloat16* Kh = Ql + 128 * KAH;               // [64][72]
    __nv_bfloat16* Kl = Kh + 64 * KAH;
    __nv_bfloat16* Vh = Kl + 64 * KAH;                // [64][72]  (row = d, col = s)
    __nv_bfloat16* Vl = Vh + 64 * KAH;

    const int tid = threadIdx.x;
    const int bx = blockIdx.x, h = blockIdx.y;
    const int qb = bx >> 1, half = bx & 1;
    const int w = tid >> 5, lane = tid & 31;
    const int gid = lane >> 2, qid = lane & 3;
    const int rt = w * 16;
    const int t0 = qb * 128;

    const int lrow = lane & 7;
    const int a_row = rt + ((lane >> 3) & 1) * 8 + lrow;
    const int a_col = ((lane >> 4) & 1) * 8;
    const uint32_t qAddrH = smem_u32(Qh + a_row * KAH + a_col);
    const uint32_t qAddrL = smem_u32(Ql + a_row * KAH + a_col);
    const int b_row = ((lane >> 4) & 1) * 8 + lrow;
    const int b_col = ((lane >> 3) & 1) * 8;
    const uint32_t kAddrH = smem_u32(Kh + b_row * KAH + b_col);
    const uint32_t kAddrL = smem_u32(Kl + b_row * KAH + b_col);
    const uint32_t vAddrH = smem_u32(Vh + b_row * KAH + b_col);
    const uint32_t vAddrL = smem_u32(Vl + b_row * KAH + b_col);

    const __nv_bfloat16* Qhg = qhg + ((size_t)h * 1024 + t0) * 64;
    const __nv_bfloat16* Qlg = qlg + ((size_t)h * 1024 + t0) * 64;
    for (int i = tid; i < 1024; i += 256) {
        int r = i >> 3, c8 = (i & 7) * 8;
        *(uint4*)&Qh[r * KAH + c8] = *(const uint4*)(Qhg + (size_t)r * 64 + c8);
        *(uint4*)&Ql[r * KAH + c8] = *(const uint4*)(Qlg + (size_t)r * 64 + c8);
    }

    float m0 = -FLT_MAX, m1 = -FLT_MAX, l0 = 0.f, l1 = 0.f;
    float O[8][4];
#pragma unroll
    for (int nb = 0; nb < 8; nb++)
#pragma unroll
        for (int k = 0; k < 4; k++) O[nb][k] = 0.f;

    const int row0 = t0 + rt + gid, row1 = row0 + 8;
    const int jlo = half * (qb + 1);
    const int jhi = jlo + qb + 1;

    for (int j = jlo; j < jhi; j++) {
        const int s0 = j * 64;
        __syncthreads();
        const __nv_bfloat16* Khg = khg + ((size_t)h * 1024 + s0) * 64;
        const __nv_bfloat16* Klg = klg + ((size_t)h * 1024 + s0) * 64;
        for (int i = tid; i < 512; i += 256) {
            int r = i >> 3, c8 = (i & 7) * 8;
            *(uint4*)&Kh[r * KAH + c8] = *(const uint4*)(Khg + (size_t)r * 64 + c8);
            *(uint4*)&Kl[r * KAH + c8] = *(const uint4*)(Klg + (size_t)r * 64 + c8);
        }
        const __nv_bfloat16* Vhg = vth + (size_t)h * 64 * 1024 + s0;
        const __nv_bfloat16* Vlg = vtl + (size_t)h * 64 * 1024 + s0;
        for (int i = tid; i < 512; i += 256) {
            int r = i >> 3, c8 = (i & 7) * 8;
            *(uint4*)&Vh[r * KAH + c8] = *(const uint4*)(Vhg + (size_t)r * 1024 + c8);
            *(uint4*)&Vl[r * KAH + c8] = *(const uint4*)(Vlg + (size_t)r * 1024 + c8);
        }
        __syncthreads();

        // S = Q K^T (3xBF16, ldmatrix frags)
        float c[8][4];
#pragma unroll
        for (int nb = 0; nb < 8; nb++)
#pragma unroll
            for (int k = 0; k < 4; k++) c[nb][k] = 0.f;

#pragma unroll
        for (int ks16 = 0; ks16 < 4; ks16++) {
            const uint32_t koff = ks16 * 32;
            uint32_t ah0, ah1, ah2, ah3, al0, al1, al2, al3;
            ldsm_x4(ah0, ah1, ah2, ah3, qAddrH + koff);
            ldsm_x4(al0, al1, al2, al3, qAddrL + koff);
#pragma unroll
            for (int nbp = 0; nbp < 4; nbp++) {
                const uint32_t boff = nbp * (16 * KAH * 2) + koff;
                uint32_t bh0a, bh1a, bh0b, bh1b, bl0a, bl1a, bl0b, bl1b;
                ldsm_x4(bh0a, bh1a, bh0b, bh1b, kAddrH + boff);
                ldsm_x4(bl0a, bl1a, bl0b, bl1b, kAddrL + boff);
                const int nA = 2 * nbp, nB = 2 * nbp + 1;
                mma_bf16(c[nA][0], c[nA][1], c[nA][2], c[nA][3],
                         ah0, ah1, ah2, ah3, bh0a, bh1a);
                mma_bf16(c[nA][0], c[nA][1], c[nA][2], c[nA][3],
                         ah0, ah1, ah2, ah3, bl0a, bl1a);
                mma_bf16(c[nA][0], c[nA][1], c[nA][2], c[nA][3],
                         al0, al1, al2, al3, bh0a, bh1a);
                mma_bf16(c[nB][0], c[nB][1], c[nB][2], c[nB][3],
                         ah0, ah1, ah2, ah3, bh0b, bh1b);
                mma_bf16(c[nB][0], c[nB][1], c[nB][2], c[nB][3],
                         ah0, ah1, ah2, ah3, bl0b, bl1b);
                mma_bf16(c[nB][0], c[nB][1], c[nB][2], c[nB][3],
                         al0, al1, al2, al3, bh0b, bh1b);
            }
        }

        // causal mask
        if (s0 + 63 > t0 + rt) {
#pragma unroll
            for (int nb = 0; nb < 8; nb++) {
                int cb = s0 + nb * 8 + 2 * qid;
                if (cb > row0)     c[nb][0] = -FLT_MAX;
                if (cb + 1 > row0) c[nb][1] = -FLT_MAX;
                if (cb > row1)     c[nb][2] = -FLT_MAX;
                if (cb + 1 > row1) c[nb][3] = -FLT_MAX;
            }
        }

        // online softmax
        float rm0 = -FLT_MAX, rm1 = -FLT_MAX;
#pragma unroll
        for (int nb = 0; nb < 8; nb++) {
            rm0 = fmaxf(rm0, fmaxf(c[nb][0], c[nb][1]));
            rm1 = fmaxf(rm1, fmaxf(c[nb][2], c[nb][3]));
        }
        rm0 = fmaxf(rm0, __shfl_xor_sync(0xffffffffu, rm0, 1));
        rm0 = fmaxf(rm0, __shfl_xor_sync(0xffffffffu, rm0, 2));
        rm1 = fmaxf(rm1, __shfl_xor_sync(0xffffffffu, rm1, 1));
        rm1 = fmaxf(rm1, __shfl_xor_sync(0xffffffffu, rm1, 2));

        float mn0 = fmaxf(m0, rm0), mn1 = fmaxf(m1, rm1);
        float alpha0 = __expf(m0 - mn0), alpha1 = __expf(m1 - mn1);
        float ps0 = 0.f, ps1 = 0.f;
#pragma unroll
        for (int nb = 0; nb < 8; nb++) {
            c[nb][0] = __expf(c[nb][0] - mn0); ps0 += c[nb][0];
            c[nb][1] = __expf(c[nb][1] - mn0); ps0 += c[nb][1];
            c[nb][2] = __expf(c[nb][2] - mn1); ps1 += c[nb][2];
            c[nb][3] = __expf(c[nb][3] - mn1); ps1 += c[nb][3];
        }
        ps0 += __shfl_xor_sync(0xffffffffu, ps0, 1);
        ps0 += __shfl_xor_sync(0xffffffffu, ps0, 2);
        ps1 += __shfl_xor_sync(0xffffffffu, ps1, 1);
        ps1 += __shfl_xor_sync(0xffffffffu, ps1, 2);
        l0 = l0 * alpha0 + ps0; m0 = mn0;
        l1 = l1 * alpha1 + ps1; m1 = mn1;
#pragma unroll
        for (int nb = 0; nb < 8; nb++) {
            O[nb][0] *= alpha0; O[nb][1] *= alpha0;
            O[nb][2] *= alpha1; O[nb][3] *= alpha1;
        }

        // P@V (ldmatrix V frags; P converted in registers)
#pragma unroll
        for (int kb = 0; kb < 4; kb++) {
            float p00 = c[2 * kb][0],     p01 = c[2 * kb][1];
            float p02 = c[2 * kb][2],     p03 = c[2 * kb][3];
            float p10 = c[2 * kb + 1][0], p11 = c[2 * kb + 1][1];
            float p12 = c[2 * kb + 1][2], p13 = c[2 * kb + 1][3];
            __nv_bfloat16 h00 = __float2bfloat16(p00), h01 = __float2bfloat16(p01);
            __nv_bfloat16 h02 = __float2bfloat16(p02), h03 = __float2bfloat16(p03);
            __nv_bfloat16 h10 = __float2bfloat16(p10), h11 = __float2bfloat16(p11);
            __nv_bfloat16 h12 = __float2bfloat16(p12), h13 = __float2bfloat16(p13);
            uint32_t Ah0 = pack_bf16(h00, h01);
            uint32_t Ah1 = pack_bf16(h02, h03);
            uint32_t Ah2 = pack_bf16(h10, h11);
            uint32_t Ah3 = pack_bf16(h12, h13);
            uint32_t Al0 = pack_bf16(__float2bfloat16(p00 - __bfloat162float(h00)),
                                     __float2bfloat16(p01 - __bfloat162float(h01)));
            uint32_t Al1 = pack_bf16(__float2bfloat16(p02 - __bfloat162float(h02)),
                                     __float2bfloat16(p03 - __bfloat162float(h03)));
            uint32_t Al2 = pack_bf16(__float2bfloat16(p10 - __bfloat162float(h10)),
                                     __float2bfloat16(p11 - __bfloat162float(h11)));
            uint32_t Al3 = pack_bf16(__float2bfloat16(p12 - __bfloat162float(h12)),
                                     __float2bfloat16(p13 - __bfloat162float(h13)));
            const uint32_t koff = kb * 32;
#pragma unroll
            for (int nbp = 0; nbp < 4; nbp++) {
                const uint32_t boff = nbp * (16 * KAH * 2) + koff;
                uint32_t bh0a, bh1a, bh0b, bh1b, bl0a, bl1a, bl0b, bl1b;
                ldsm_x4(bh0a, bh1a, bh0b, bh1b, vAddrH + boff);
                ldsm_x4(bl0a, bl1a, bl0b, bl1b, vAddrL + boff);
                const int nA = 2 * nbp, nB = 2 * nbp + 1;
                mma_bf16(O[nA][0], O[nA][1], O[nA][2], O[nA][3],
                         Ah0, Ah1, Ah2, Ah3, bh0a, bh1a);
                mma_bf16(O[nA][0], O[nA][1], O[nA][2], O[nA][3],
                         Ah0, Ah1, Ah2, Ah3, bl0a, bl1a);
                mma_bf16(O[nA][0], O[nA][1], O[nA][2], O[nA][3],
                         Al0, Al1, Al2, Al3, bh0a, bh1a);
                mma_bf16(O[nB][0], O[nB][1], O[nB][2], O[nB][3],
                         Ah0, Ah1, Ah2, Ah3, bh0b, bh1b);
                mma_bf16(O[nB][0], O[nB][1], O[nB][2], O[nB][3],
                         Ah0, Ah1, Ah2, Ah3, bl0b, bl1b);
                mma_bf16(O[nB][0], O[nB][1], O[nB][2], O[nB][3],
                         Al0, Al1, Al2, Al3, bh0b, bh1b);
            }
        }
    }

    // epilogue: store unnormalized partial (m, l, O)
    const size_t base = ((size_t)half * 16 + h) * 1024;
    if (qid == 0) {
        pm[base + row0] = m0; pl[base + row0] = l0;
        pm[base + row1] = m1; pl[base + row1] = l1;
    }
#pragma unroll
    for (int nb = 0; nb < 8; nb++) {
        int colb = nb * 8 + 2 * qid;
        pO[(base + row0) * 64 + colb]     = O[nb][0];
        pO[(base + row0) * 64 + colb + 1] = O[nb][1];
        pO[(base + row1) * 64 + colb]     = O[nb][2];
        pO[(base + row1) * 64 + colb + 1] = O[nb][3];
    }
}

// ---- merge the two flash partials per (h, t) row -> yh/yl bf16 split directly ----
__global__ void flash_merge_kernel(const float* __restrict__ pO,
                                   const float* __restrict__ pm,
                                   const float* __restrict__ pl,
                                   __nv_bfloat16* __restrict__ yh,
                                   __nv_bfloat16* __restrict__ yl) {
    int i = blockIdx.x * 256 + threadIdx.x;   // < 16*1024*64 = 1M
    int d = i & 63, t = (i >> 6) & 1023, h = i >> 16;
    size_t r0 = (size_t)h * 1024 + t;
    size_t r1 = (size_t)16 * 1024 + r0;
    float ma = pm[r0], mb = pm[r1];
    float mm = fmaxf(ma, mb);
    float ea = __expf(ma - mm), eb = __expf(mb - mm);
    float l = pl[r0] * ea + pl[r1] * eb;
    float o = pO[r0 * 64 + d] * ea + pO[r1 * 64 + d] * eb;
    float val = o / l;
    __nv_bfloat16 hh = __float2bfloat16(val);
    size_t oi = (size_t)t * 1024 + h * 64 + d;
    yh[oi] = hh;
    yl[oi] = __float2bfloat16(val - __bfloat162float(hh));
}

// ---------------- launch ----------------
extern "C" void kernel_launch(void* const* d_in, const int* in_sizes, int n_in,
                              void* d_out, int out_size) {
    const float* x  = (const float*)d_in[0];
    const float* aw = (const float*)d_in[1];
    const float* ab = (const float*)d_in[2];
    const float* pw = (const float*)d_in[3];
    const float* pb = (const float*)d_in[4];
    const float* ks = (const float*)d_in[5];
    const float* vs = (const float*)d_in[6];
    float* out = (float*)d_out;

    float *qkv, *ksn, *lg, *vnw, *pO, *pm, *pl;
    __nv_bfloat16 *kh, *kl, *qh, *ql, *mh, *ml, *xh, *xl, *awh, *awl, *pwh, *pwl, *yh, *yl;
    __nv_bfloat16 *vth, *vtl;
    int *idx, *sel;
    cudaGetSymbolAddress((void**)&qkv, g_qkv);
    cudaGetSymbolAddress((void**)&ksn, g_ksnorm);
    cudaGetSymbolAddress((void**)&kh,  g_kh);
    cudaGetSymbolAddress((void**)&kl,  g_kl);
    cudaGetSymbolAddress((void**)&qh,  g_qh);
    cudaGetSymbolAddress((void**)&ql,  g_ql);
    cudaGetSymbolAddress((void**)&mh,  g_mh);
    cudaGetSymbolAddress((void**)&ml,  g_ml);
    cudaGetSymbolAddress((void**)&xh,  g_xh);
    cudaGetSymbolAddress((void**)&xl,  g_xl);
    cudaGetSymbolAddress((void**)&awh, g_awh);
    cudaGetSymbolAddress((void**)&awl, g_awl);
    cudaGetSymbolAddress((void**)&pwh, g_pwh);
    cudaGetSymbolAddress((void**)&pwl, g_pwl);
    cudaGetSymbolAddress((void**)&yh,  g_yh);
    cudaGetSymbolAddress((void**)&yl,  g_yl);
    cudaGetSymbolAddress((void**)&vth, g_vth);
    cudaGetSymbolAddress((void**)&vtl, g_vtl);
    cudaGetSymbolAddress((void**)&pO,  g_pO);
    cudaGetSymbolAddress((void**)&pm,  g_pm);
    cudaGetSymbolAddress((void**)&pl,  g_pl);
    cudaGetSymbolAddress((void**)&lg,  g_lg);
    cudaGetSymbolAddress((void**)&idx, g_idx);
    cudaGetSymbolAddress((void**)&sel, g_sel);
    cudaGetSymbolAddress((void**)&vnw, g_vnew);

    cudaFuncSetAttribute(knn_mma_kernel,
                         cudaFuncAttributeMaxDynamicSharedMemorySize, KNN_SMEM_BYTES);
    cudaFuncSetAttribute(mma_gemm_bf16_kernel,
                         cudaFuncAttributeMaxDynamicSharedMemorySize, GM_SMEM_BYTES);
    cudaFuncSetAttribute(flash_mma_kernel,
                         cudaFuncAttributeMaxDynamicSharedMemorySize, FLM_SMEM_BYTES);

    // 0) bf16 hi/lo splits
    split_bf16_v4<<<1024, 256>>>((const float4*)x,
                                 (__nv_bfloat162*)xh, (__nv_bfloat162*)xl);
    split_bf16_v4<<<3072, 256>>>((const float4*)aw,
                                 (__nv_bfloat162*)awh, (__nv_bfloat162*)awl);
    split_bf16_v4<<<1024, 256>>>((const float4*)pw,
                                 (__nv_bfloat162*)pwh, (__nv_bfloat162*)pwl);
    split_bf16_v4<<<8192, 256>>>((const float4*)ks,
                                 (__nv_bfloat162*)mh, (__nv_bfloat162*)ml);
    // 1) qkv = x @ c_attn_w^T + b   (3xBF16 mma + ldmatrix)
    mma_gemm_bf16_kernel<<<dim3(24, 16), 256, GM_SMEM_BYTES>>>(
        xh, xl, awh, awl, qkv, 3072, 1024, ab);
    // 2) key_store norms + k/q split/relayout
    ksnorm_kernel<<<512, 256>>>(ks, ksn);
    split_qk_bf16_kernel<<<2048, 1024>>>(qkv, kh, kl, qh, ql);
    // 3) fused kNN scores + top-4 (bf16 mma + ldmatrix + cp.async double buffer)
    knn_mma_kernel<<<dim3(16, 16), 256, KNN_SMEM_BYTES>>>(
        kh, kl, mh, ml, ksn, idx);
    // 4) sel from last-row softmax
    selA_kernel<<<dim3(128, 16), 256>>>(qkv, lg);
    selB_kernel<<<16, 1024>>>(lg, sel);
    // 5) 5-way softmax blend -> v_new
    vnew_kernel<<<2048, 256>>>(qkv, ks, vs, idx, sel, vnw);
    // 5b) transpose+split v_new for flash PV
    vtrans_kernel<<<dim3(16, 16), 256>>>(vnw, vth, vtl);
    // 6) split-KV flash attention (partials) + fused merge/split -> yh/yl
    flash_mma_kernel<<<dim3(16, 16), 256, FLM_SMEM_BYTES>>>(
        qh, ql, kh, kl, vth, vtl, pO, pm, pl);
    flash_merge_kernel<<<4096, 256>>>(pO, pm, pl, yh, yl);
    // 7) out = y @ c_proj_w^T + b   (3xBF16 mma + ldmatrix)
    mma_gemm_bf16_kernel<<<dim3(8, 16), 256, GM_SMEM_BYTES>>>(
        yh, yl, pwh, pwl, out, 1024, 1024, pb);
}

// round 16
// speedup vs baseline: 1.7324x; 1.0660x over previous
#include <cuda_runtime.h>
#include <cuda_bf16.h>
#include <cfloat>
#include <cstdint>

// ---------------- scratch (__device__ globals; no allocations) ----------------
__device__ float g_qkv[1024 * 3072];              // 12 MB  (T, 3C)
__device__ float g_ksnorm[16 * 8192];             // (H, M)
__device__ __nv_bfloat16 g_kh[16 * 1024 * 64];    // bf16-hi of k, [h][t][d]
__device__ __nv_bfloat16 g_kl[16 * 1024 * 64];    // bf16-lo of k
__device__ __nv_bfloat16 g_qh[16 * 1024 * 64];    // bf16-hi of q*0.125, [h][t][d]
__device__ __nv_bfloat16 g_ql[16 * 1024 * 64];    // bf16-lo
__device__ __nv_bfloat16 g_mh[16 * 8192 * 64];    // bf16-hi of key_store
__device__ __nv_bfloat16 g_ml[16 * 8192 * 64];    // bf16-lo of key_store
__device__ __nv_bfloat16 g_xh[1024 * 1024];       // bf16-hi of x
__device__ __nv_bfloat16 g_xl[1024 * 1024];
__device__ __nv_bfloat16 g_awh[3072 * 1024];      // bf16-hi of c_attn_w
__device__ __nv_bfloat16 g_awl[3072 * 1024];
__device__ __nv_bfloat16 g_pwh[1024 * 1024];      // bf16-hi of c_proj_w
__device__ __nv_bfloat16 g_pwl[1024 * 1024];
__device__ __nv_bfloat16 g_yh[1024 * 1024];       // bf16-hi of y (written by merge)
__device__ __nv_bfloat16 g_yl[1024 * 1024];
__device__ __nv_bfloat16 g_vth[16 * 64 * 1024];   // bf16-hi of v_new^T, [h][d][t]
__device__ __nv_bfloat16 g_vtl[16 * 64 * 1024];   // bf16-lo
__device__ float g_pO[2 * 16 * 1024 * 64];        // flash partial O [half][h][t][d]
__device__ float g_pm[2 * 16 * 1024];             // flash partial row max
__device__ float g_pl[2 * 16 * 1024];             // flash partial row sum
__device__ float g_lg[16 * 1024];                 // last-row logits
__device__ int   g_idx[16 * 1024 * 4];            // (H, T, 4)
__device__ int   g_sel[16 * 1024];                // (H, T)
__device__ float g_vnew[16 * 1024 * 64];          // (H, T, d)

// ---------------- helpers ----------------
__device__ __forceinline__ void mma_bf16(float& c0, float& c1, float& c2, float& c3,
                                         uint32_t a0, uint32_t a1, uint32_t a2, uint32_t a3,
                                         uint32_t b0, uint32_t b1) {
    asm volatile(
        "mma.sync.aligned.m16n8k16.row.col.f32.bf16.bf16.f32 "
        "{%0,%1,%2,%3}, {%4,%5,%6,%7}, {%8,%9}, {%0,%1,%2,%3};"
        : "+f"(c0), "+f"(c1), "+f"(c2), "+f"(c3)
        : "r"(a0), "r"(a1), "r"(a2), "r"(a3), "r"(b0), "r"(b1));
}

__device__ __forceinline__ void ldsm_x4(uint32_t& r0, uint32_t& r1,
                                        uint32_t& r2, uint32_t& r3, uint32_t addr) {
    asm volatile("ldmatrix.sync.aligned.m8n8.x4.shared.b16 {%0,%1,%2,%3}, [%4];"
                 : "=r"(r0), "=r"(r1), "=r"(r2), "=r"(r3) : "r"(addr));
}

__device__ __forceinline__ uint32_t smem_u32(const void* p) {
    return (uint32_t)__cvta_generic_to_shared(p);
}

__device__ __forceinline__ void cp_async16(uint32_t dst, const void* src) {
    asm volatile("cp.async.cg.shared.global [%0], [%1], 16;" :: "r"(dst), "l"(src));
}

__device__ __forceinline__ void cp_async4(uint32_t dst, const void* src) {
    asm volatile("cp.async.ca.shared.global [%0], [%1], 4;" :: "r"(dst), "l"(src));
}

__device__ __forceinline__ uint32_t pack_bf16(__nv_bfloat16 lo, __nv_bfloat16 hi) {
    __nv_bfloat162 t;
    t.x = lo; t.y = hi;
    return *(uint32_t*)&t;
}

// ---------- vectorized contiguous bf16 hi/lo split (4 floats / thread) ----------
__global__ void split_bf16_v4(const float4* __restrict__ src,
                              __nv_bfloat162* __restrict__ hi,
                              __nv_bfloat162* __restrict__ lo) {
    size_t i = (size_t)blockIdx.x * 256 + threadIdx.x;
    float4 v = src[i];
    __nv_bfloat16 h0 = __float2bfloat16(v.x), h1 = __float2bfloat16(v.y);
    __nv_bfloat16 h2 = __float2bfloat16(v.z), h3 = __float2bfloat16(v.w);
    __nv_bfloat16 l0 = __float2bfloat16(v.x - __bfloat162float(h0));
    __nv_bfloat16 l1 = __float2bfloat16(v.y - __bfloat162float(h1));
    __nv_bfloat16 l2 = __float2bfloat16(v.z - __bfloat162float(h2));
    __nv_bfloat16 l3 = __float2bfloat16(v.w - __bfloat162float(h3));
    hi[i * 2 + 0] = __nv_bfloat162{h0, h1};
    hi[i * 2 + 1] = __nv_bfloat162{h2, h3};
    lo[i * 2 + 0] = __nv_bfloat162{l0, l1};
    lo[i * 2 + 1] = __nv_bfloat162{l2, l3};
}

// -- bf16 hi/lo split of k AND q (scaled 0.125) from qkv, relayout to [h][t][d] --
__global__ void split_qk_bf16_kernel(const float* __restrict__ qkv,
                                     __nv_bfloat16* __restrict__ khi,
                                     __nv_bfloat16* __restrict__ klo,
                                     __nv_bfloat16* __restrict__ qhi,
                                     __nv_bfloat16* __restrict__ qlo) {
    int i = blockIdx.x * 1024 + threadIdx.x;  // 2M
    int which = i >> 20;                      // 0: k, 1: q
    int r = i & 0xFFFFF;
    int d = r & 63, t = (r >> 6) & 1023, h = r >> 16;
    float x = qkv[(size_t)t * 3072 + (which ? 0 : 1024) + h * 64 + d];
    if (which) x *= 0.125f;
    __nv_bfloat16 hf = __float2bfloat16(x);
    __nv_bfloat16 lf = __float2bfloat16(x - __bfloat162float(hf));
    if (which) { qhi[r] = hf; qlo[r] = lf; }
    else       { khi[r] = hf; klo[r] = lf; }
}

// ---- generic 3xBF16 mma GEMM: C = A*B^T + bias  (ldmatrix + cp.async dbuf) ----
#define KAH 72
#define GM_SMEM_BYTES (2 * (64 * KAH * 2 + 128 * KAH * 2) * 2)

__global__ __launch_bounds__(256) void mma_gemm_bf16_kernel(
    const __nv_bfloat16* __restrict__ Ahg, const __nv_bfloat16* __restrict__ Alg,
    const __nv_bfloat16* __restrict__ Bhg, const __nv_bfloat16* __restrict__ Blg,
    float* __restrict__ C, int ldc, int K, const float* __restrict__ bias) {
    extern __shared__ char smc[];
    // per buffer: Ah[64][72], Al[64][72], Bh[128][72], Bl[128][72]
    const int BUFE = (64 + 64 + 128 + 128) * KAH;   // elements per buffer

    const int tid = threadIdx.x;
    const int bx = blockIdx.x, by = blockIdx.y;
    const int w = tid >> 5, lane = tid & 31;
    const int gid = lane >> 2, qid = lane & 3;
    const int rt = (w & 3) * 16;
    const int ch = (w >> 2) * 64;

    const int lrow = lane & 7;
    const int a_row = rt + ((lane >> 3) & 1) * 8 + lrow;
    const int a_col = ((lane >> 4) & 1) * 8;
    const int b_row = ch + ((lane >> 4) & 1) * 8 + lrow;
    const int b_col = ((lane >> 3) & 1) * 8;

    uint32_t aAddrH[2], aAddrL[2], bAddrH[2], bAddrL[2];
    __nv_bfloat16* Abase[2];
    __nv_bfloat16* Bbase[2];
#pragma unroll
    for (int b = 0; b < 2; b++) {
        __nv_bfloat16* Ah = (__nv_bfloat16*)smc + b * BUFE;
        __nv_bfloat16* Al = Ah + 64 * KAH;
        __nv_bfloat16* Bh = Al + 64 * KAH;
        __nv_bfloat16* Bl = Bh + 128 * KAH;
        Abase[b] = Ah;
        Bbase[b] = Bh;
        aAddrH[b] = smem_u32(Ah + a_row * KAH + a_col);
        aAddrL[b] = smem_u32(Al + a_row * KAH + a_col);
        bAddrH[b] = smem_u32(Bh + b_row * KAH + b_col);
        bAddrL[b] = smem_u32(Bl + b_row * KAH + b_col);
    }

    const __nv_bfloat16* Ahb = Ahg + (size_t)(by * 64) * K;
    const __nv_bfloat16* Alb = Alg + (size_t)(by * 64) * K;
    const __nv_bfloat16* Bhb = Bhg + (size_t)(bx * 128) * K;
    const __nv_bfloat16* Blb = Blg + (size_t)(bx * 128) * K;

    float c[8][4];
#pragma unroll
    for (int nb = 0; nb < 8; nb++)
#pragma unroll
        for (int k = 0; k < 4; k++) c[nb][k] = 0.f;

    const int nt = K >> 6;   // 64-wide k-tiles

    auto issue = [&](int kt, int b) {
        const int k0 = kt << 6;
        __nv_bfloat16* Ah = Abase[b];
        __nv_bfloat16* Al = Ah + 64 * KAH;
        __nv_bfloat16* Bh = Bbase[b];
        __nv_bfloat16* Bl = Bh + 128 * KAH;
        for (int i = tid; i < 512; i += 256) {
            int r = i >> 3, c8 = (i & 7) * 8;
            cp_async16(smem_u32(Ah + r * KAH + c8), Ahb + (size_t)r * K + k0 + c8);
            cp_async16(smem_u32(Al + r * KAH + c8), Alb + (size_t)r * K + k0 + c8);
        }
        for (int i = tid; i < 1024; i += 256) {
            int r = i >> 3, c8 = (i & 7) * 8;
            cp_async16(smem_u32(Bh + r * KAH + c8), Bhb + (size_t)r * K + k0 + c8);
            cp_async16(smem_u32(Bl + r * KAH + c8), Blb + (size_t)r * K + k0 + c8);
        }
        asm volatile("cp.async.commit_group;" ::: "memory");
    };

    issue(0, 0);

    for (int kt = 0; kt < nt; kt++) {
        const int b = kt & 1;
        asm volatile("cp.async.wait_group 0;" ::: "memory");
        __syncthreads();
        if (kt + 1 < nt) issue(kt + 1, b ^ 1);

#pragma unroll
        for (int ks16 = 0; ks16 < 4; ks16++) {
            const uint32_t koff = ks16 * 32;   // 16 bf16 = 32 bytes
            uint32_t ah0, ah1, ah2, ah3, al0, al1, al2, al3;
            ldsm_x4(ah0, ah1, ah2, ah3, aAddrH[b] + koff);
            ldsm_x4(al0, al1, al2, al3, aAddrL[b] + koff);
#pragma unroll
            for (int nbp = 0; nbp < 4; nbp++) {
                const uint32_t boff = nbp * (16 * KAH * 2) + koff;
                uint32_t bh0a, bh1a, bh0b, bh1b, bl0a, bl1a, bl0b, bl1b;
                ldsm_x4(bh0a, bh1a, bh0b, bh1b, bAddrH[b] + boff);
                ldsm_x4(bl0a, bl1a, bl0b, bl1b, bAddrL[b] + boff);
                const int nA = 2 * nbp, nB = 2 * nbp + 1;
                mma_bf16(c[nA][0], c[nA][1], c[nA][2], c[nA][3],
                         ah0, ah1, ah2, ah3, bh0a, bh1a);
                mma_bf16(c[nA][0], c[nA][1], c[nA][2], c[nA][3],
                         ah0, ah1, ah2, ah3, bl0a, bl1a);
                mma_bf16(c[nA][0], c[nA][1], c[nA][2], c[nA][3],
                         al0, al1, al2, al3, bh0a, bh1a);
                mma_bf16(c[nB][0], c[nB][1], c[nB][2], c[nB][3],
                         ah0, ah1, ah2, ah3, bh0b, bh1b);
                mma_bf16(c[nB][0], c[nB][1], c[nB][2], c[nB][3],
                         ah0, ah1, ah2, ah3, bl0b, bl1b);
                mma_bf16(c[nB][0], c[nB][1], c[nB][2], c[nB][3],
                         al0, al1, al2, al3, bh0b, bh1b);
            }
        }
        __syncthreads();
    }

#pragma unroll
    for (int nb = 0; nb < 8; nb++) {
#pragma unroll
        for (int k = 0; k < 4; k++) {
            int row = by * 64 + rt + gid + (k >> 1) * 8;
            int col = bx * 128 + ch + nb * 8 + 2 * qid + (k & 1);
            C[(size_t)row * ldc + col] = c[nb][k] + bias[col];
        }
    }
}

// ---------------- ||key_store[h,m]||^2 (exact fp32) ----------------
__global__ void ksnorm_kernel(const float* __restrict__ ks, float* __restrict__ nrm) {
    int r = blockIdx.x * blockDim.x + threadIdx.x;
    if (r >= 16 * 8192) return;
    const float4* p = (const float4*)(ks + (size_t)r * 64);
    float s = 0.f;
#pragma unroll
    for (int i = 0; i < 16; i++) {
        float4 f = p[i];
        s += f.x * f.x + f.y * f.y + f.z * f.z + f.w * f.w;
    }
    nrm[r] = s;
}

// ------------- lexicographic (score, idx) compare: stable top-k --------------
__device__ __forceinline__ bool lex_lt(float sa, int ia, float sb, int ib) {
    return sa < sb || (sa == sb && ia < ib);
}

#define TOP4_INSERT(v, m, s0, x0, s1, x1, s2, x2, s3, x3)              \
    if (lex_lt(v, m, s3, x3)) {                                        \
        if (lex_lt(v, m, s2, x2)) {                                    \
            s3 = s2; x3 = x2;                                          \
            if (lex_lt(v, m, s1, x1)) {                                \
                s2 = s1; x2 = x1;                                      \
                if (lex_lt(v, m, s0, x0)) {                            \
                    s1 = s0; x1 = x0; s0 = v; x0 = m;                  \
                } else { s1 = v; x1 = m; }                             \
            } else { s2 = v; x2 = m; }                                 \
        } else { s3 = v; x3 = m; }                                     \
    }

// ---- fused kNN scores + top-4, bf16 mma + ldmatrix + cp.async double buffer ----
#define KNN_SMEM_BYTES (18432 + 73728 + 1024)

__global__ __launch_bounds__(256) void knn_mma_kernel(
    const __nv_bfloat16* __restrict__ kh, const __nv_bfloat16* __restrict__ kl,
    const __nv_bfloat16* __restrict__ mh, const __nv_bfloat16* __restrict__ ml,
    const float* __restrict__ ksn, int* __restrict__ idx_out) {
    extern __shared__ char smc[];
    __nv_bfloat16* Ah = (__nv_bfloat16*)smc;          // [64][72]
    __nv_bfloat16* Al = Ah + 64 * KAH;
    __nv_bfloat16* Bbuf = Al + 64 * KAH;              // 2 x (Bh, Bl) [128][72]
    float* NsBase = (float*)(Bbuf + 4 * 128 * KAH);   // 2 x [128]

    const int tid = threadIdx.x;
    const int t0 = blockIdx.x * 64;
    const int h = blockIdx.y;
    const int w = tid >> 5, lane = tid & 31;
    const int gid = lane >> 2, qid = lane & 3;
    const int rt = (w & 3) * 16;
    const int ch = (w >> 2) * 64;

    const int lrow = lane & 7;
    const int a_row = rt + ((lane >> 3) & 1) * 8 + lrow;
    const int a_col = ((lane >> 4) & 1) * 8;
    const uint32_t aAddrH = smem_u32(Ah + a_row * KAH + a_col);
    const uint32_t aAddrL = smem_u32(Al + a_row * KAH + a_col);
    const int b_row = ch + ((lane >> 4) & 1) * 8 + lrow;
    const int b_col = ((lane >> 3) & 1) * 8;
    uint32_t bAddrH[2], bAddrL[2];
#pragma unroll
    for (int b = 0; b < 2; b++) {
        __nv_bfloat16* BhB = Bbuf + b * (2 * 128 * KAH);
        __nv_bfloat16* BlB = BhB + 128 * KAH;
        bAddrH[b] = smem_u32(BhB + b_row * KAH + b_col);
        bAddrL[b] = smem_u32(BlB + b_row * KAH + b_col);
    }

    const __nv_bfloat16* Ahg = kh + ((size_t)h * 1024 + t0) * 64;
    const __nv_bfloat16* Alg = kl + ((size_t)h * 1024 + t0) * 64;
    for (int i = tid; i < 512; i += 256) {
        int r = i >> 3, c8 = (i & 7) * 8;
        *(uint4*)&Ah[r * KAH + c8] = *(const uint4*)(Ahg + (size_t)r * 64 + c8);
        *(uint4*)&Al[r * KAH + c8] = *(const uint4*)(Alg + (size_t)r * 64 + c8);
    }

    float S[2][4];
    int I[2][4];
#pragma unroll
    for (int r = 0; r < 2; r++)
#pragma unroll
        for (int k = 0; k < 4; k++) { S[r][k] = FLT_MAX; I[r][k] = 0x7fffffff; }

    const __nv_bfloat16* Bhg = mh + (size_t)h * 8192 * 64;
    const __nv_bfloat16* Blg = ml + (size_t)h * 8192 * 64;
    const float* Nbase = ksn + h * 8192;

    auto issue = [&](int chunk, int b) {
        const int m0 = chunk << 7;
        __nv_bfloat16* BhB = Bbuf + b * (2 * 128 * KAH);
        __nv_bfloat16* BlB = BhB + 128 * KAH;
        for (int i = tid; i < 1024; i += 256) {
            int r = i >> 3, c8 = (i & 7) * 8;
            cp_async16(smem_u32(BhB + r * KAH + c8), Bhg + (size_t)(m0 + r) * 64 + c8);
            cp_async16(smem_u32(BlB + r * KAH + c8), Blg + (size_t)(m0 + r) * 64 + c8);
        }
        if (tid < 128) cp_async4(smem_u32(NsBase + b * 128 + tid), Nbase + m0 + tid);
        asm volatile("cp.async.commit_group;" ::: "memory");
    };

    issue(0, 0);

    for (int chunk = 0; chunk < 64; chunk++) {
        const int b = chunk & 1;
        asm volatile("cp.async.wait_group 0;" ::: "memory");
        __syncthreads();
        if (chunk + 1 < 64) issue(chunk + 1, b ^ 1);
        const float* Ns = NsBase + b * 128;

        float c[8][4];
#pragma unroll
        for (int nb = 0; nb < 8; nb++)
#pragma unroll
            for (int k = 0; k < 4; k++) c[nb][k] = 0.f;

#pragma unroll
        for (int ks16 = 0; ks16 < 4; ks16++) {
            const uint32_t koff = ks16 * 32;
            uint32_t ah0, ah1, ah2, ah3, al0, al1, al2, al3;
            ldsm_x4(ah0, ah1, ah2, ah3, aAddrH + koff);
            ldsm_x4(al0, al1, al2, al3, aAddrL + koff);
#pragma unroll
            for (int nbp = 0; nbp < 4; nbp++) {
                const uint32_t boff = nbp * (16 * KAH * 2) + koff;
                uint32_t bh0a, bh1a, bh0b, bh1b, bl0a, bl1a, bl0b, bl1b;
                ldsm_x4(bh0a, bh1a, bh0b, bh1b, bAddrH[b] + boff);
                ldsm_x4(bl0a, bl1a, bl0b, bl1b, bAddrL[b] + boff);
                const int nA = 2 * nbp, nB = 2 * nbp + 1;
                mma_bf16(c[nA][0], c[nA][1], c[nA][2], c[nA][3],
                         ah0, ah1, ah2, ah3, bh0a, bh1a);
                mma_bf16(c[nA][0], c[nA][1], c[nA][2], c[nA][3],
                         ah0, ah1, ah2, ah3, bl0a, bl1a);
                mma_bf16(c[nA][0], c[nA][1], c[nA][2], c[nA][3],
                         al0, al1, al2, al3, bh0a, bh1a);
                mma_bf16(c[nB][0], c[nB][1], c[nB][2], c[nB][3],
                         ah0, ah1, ah2, ah3, bh0b, bh1b);
                mma_bf16(c[nB][0], c[nB][1], c[nB][2], c[nB][3],
                         ah0, ah1, ah2, ah3, bl0b, bl1b);
                mma_bf16(c[nB][0], c[nB][1], c[nB][2], c[nB][3],
                         al0, al1, al2, al3, bh0b, bh1b);
            }
        }

        const int m0 = chunk << 7;
#pragma unroll
        for (int nb = 0; nb < 8; nb++) {
#pragma unroll
            for (int k = 0; k < 4; k++) {
                int cl = ch + nb * 8 + 2 * qid + (k & 1);
                int r = k >> 1;
                float v = Ns[cl] - 2.0f * c[nb][k];
                int mg = m0 + cl;
                TOP4_INSERT(v, mg, S[r][0], I[r][0], S[r][1], I[r][1],
                            S[r][2], I[r][2], S[r][3], I[r][3]);
            }
        }
        __syncthreads();
    }

    float* msc = (float*)smc;                 // [64][32]
    int* mix = (int*)(smc + 16384);
    const int slot = (w >> 2) * 4 + qid;
#pragma unroll
    for (int r = 0; r < 2; r++) {
        int row = rt + gid + r * 8;
#pragma unroll
        for (int k = 0; k < 4; k++) {
            msc[(row * 8 + slot) * 4 + k] = S[r][k];
            mix[(row * 8 + slot) * 4 + k] = I[r][k];
        }
    }
    __syncthreads();
    if (tid < 64) {
        float f0 = FLT_MAX, f1 = FLT_MAX, f2 = FLT_MAX, f3 = FLT_MAX;
        int g0 = 0x7fffffff, g1 = 0x7fffffff, g2 = 0x7fffffff, g3 = 0x7fffffff;
        for (int c2 = 0; c2 < 32; c2++) {
            float v = msc[tid * 32 + c2];
            int m = mix[tid * 32 + c2];
            TOP4_INSERT(v, m, f0, g0, f1, g1, f2, g2, f3, g3);
        }
        size_t row = (size_t)h * 1024 + t0 + tid;
        idx_out[row * 4 + 0] = g0;
        idx_out[row * 4 + 1] = g1;
        idx_out[row * 4 + 2] = g2;
        idx_out[row * 4 + 3] = g3;
    }
}

// ---------------- warp-per-token last-row logits ----------------
__global__ void selA_kernel(const float* __restrict__ qkv, float* __restrict__ lg) {
    int h = blockIdx.y;
    int t = blockIdx.x * 8 + (threadIdx.x >> 5);
    int lane = threadIdx.x & 31;
    int d0 = lane * 2;
    const float* q = qkv + (size_t)1023 * 3072 + h * 64;
    const float* k = qkv + (size_t)t * 3072 + 1024 + h * 64;
    float s = q[d0] * k[d0] + q[d0 + 1] * k[d0 + 1];
#pragma unroll
    for (int o = 16; o > 0; o >>= 1) s += __shfl_xor_sync(0xffffffffu, s, o);
    if (lane == 0) lg[h * 1024 + t] = s * 0.125f;
}

// ---------------- per-head softmax of logits row -> sel ----------------
__global__ void selB_kernel(const float* __restrict__ lg, int* __restrict__ sel) {
    int h = blockIdx.x;
    int tid = threadIdx.x;
    int lane = tid & 31, warp = tid >> 5;
    __shared__ float red[8];
    __shared__ float bcast;

    float v[4];
#pragma unroll
    for (int u = 0; u < 4; u++) v[u] = lg[h * 1024 + tid + u * 256];
    float m = fmaxf(fmaxf(v[0], v[1]), fmaxf(v[2], v[3]));
#pragma unroll
    for (int o = 16; o > 0; o >>= 1) m = fmaxf(m, __shfl_xor_sync(0xffffffffu, m, o));
    if (lane == 0) red[warp] = m;
    __syncthreads();
    if (tid == 0) {
        float x = red[0];
#pragma unroll
        for (int w = 1; w < 8; w++) x = fmaxf(x, red[w]);
        bcast = x;
    }
    __syncthreads();
    m = bcast;
    float e[4], s = 0.f;
#pragma unroll
    for (int u = 0; u < 4; u++) { e[u] = __expf(v[u] - m); s += e[u]; }
#pragma unroll
    for (int o = 16; o > 0; o >>= 1) s += __shfl_xor_sync(0xffffffffu, s, o);
    if (lane == 0) red[warp] = s;
    __syncthreads();
    if (tid == 0) {
        float x = 0.f;
#pragma unroll
        for (int w = 0; w < 8; w++) x += red[w];
        bcast = x;
    }
    __syncthreads();
    float inv = 1.f / bcast;
#pragma unroll
    for (int u = 0; u < 4; u++)
        sel[h * 1024 + tid + u * 256] = (e[u] * inv >= (1.0f / 8192.0f)) ? 1 : 0;
}

// ---------------- per-token 5-way memory softmax & blend -> v_new ----------------
__device__ __forceinline__ float warp_sum(float v) {
#pragma unroll
    for (int o = 16; o > 0; o >>= 1) v += __shfl_xor_sync(0xffffffffu, v, o);
    return v;
}

__global__ void vnew_kernel(const float* __restrict__ qkv, const float* __restrict__ kstore,
                            const float* __restrict__ vstore, const int* __restrict__ idx,
                            const int* __restrict__ sel, float* __restrict__ vnew) {
    int gw = (blockIdx.x * blockDim.x + threadIdx.x) >> 5;
    int lane = threadIdx.x & 31;
    if (gw >= 16 * 1024) return;
    int h = gw >> 10, t = gw & 1023;

    const float* base = qkv + (size_t)t * 3072 + h * 64;
    int d0 = lane * 2;
    float q0 = base[d0],        q1 = base[d0 + 1];
    float k0 = base[1024 + d0], k1 = base[1024 + d0 + 1];
    float v0 = base[2048 + d0], v1 = base[2048 + d0 + 1];
    const float scale = 0.125f;

    float attf[5];
    attf[0] = warp_sum(q0 * k0 + q1 * k1) * scale;

    int ids[4];
#pragma unroll
    for (int s2 = 0; s2 < 4; s2++) ids[s2] = idx[(size_t)gw * 4 + s2];

    float fv0[4], fv1[4];
#pragma unroll
    for (int s2 = 0; s2 < 4; s2++) {
        const float* kp = kstore + ((size_t)h * 8192 + ids[s2]) * 64;
        attf[s2 + 1] = warp_sum(q0 * kp[d0] + q1 * kp[d0 + 1]) * scale;
        const float* vp = vstore + ((size_t)h * 8192 + ids[s2]) * 64;
        fv0[s2] = vp[d0]; fv1[s2] = vp[d0 + 1];
    }

    float mx = attf[0];
#pragma unroll
    for (int s2 = 1; s2 < 5; s2++) mx = fmaxf(mx, attf[s2]);
    float e[5], sum = 0.f;
#pragma unroll
    for (int s2 = 0; s2 < 5; s2++) { e[s2] = expf(attf[s2] - mx); sum += e[s2]; }
    float inv = 1.f / sum;

    float o0 = e[0] * v0, o1 = e[0] * v1;
#pragma unroll
    for (int s2 = 0; s2 < 4; s2++) { o0 += e[s2 + 1] * fv0[s2]; o1 += e[s2 + 1] * fv1[s2]; }
    o0 = o0 * inv * 0.5f + v0 * 0.5f;
    o1 = o1 * inv * 0.5f + v1 * 0.5f;

    bool sl = sel[gw] != 0;
    vnew[(size_t)gw * 64 + d0]     = sl ? o0 : v0;
    vnew[(size_t)gw * 64 + d0 + 1] = sl ? o1 : v1;
}

// ------- transpose+split v_new to bf16 hi/lo, [h][d][t] layout (for flash PV) -------
__global__ void vtrans_kernel(const float* __restrict__ vnew,
                              __nv_bfloat16* __restrict__ vth,
                              __nv_bfloat16* __restrict__ vtl) {
    __shared__ float sm[64][65];
    const int tid = threadIdx.x;
    const int t0 = blockIdx.x * 64, h = blockIdx.y;
    for (int i = tid; i < 4096; i += 256) {
        int tr = i >> 6, d = i & 63;
        sm[tr][d] = vnew[((size_t)h * 1024 + t0 + tr) * 64 + d];
    }
    __syncthreads();
    for (int i = tid; i < 4096; i += 256) {
        int d = i >> 6, tr = i & 63;
        float x = sm[tr][d];
        __nv_bfloat16 hh = __float2bfloat16(x);
        size_t o = ((size_t)h * 64 + d) * 1024 + t0 + tr;
        vth[o] = hh;
        vtl[o] = __float2bfloat16(x - __bfloat162float(hh));
    }
}

// -- fused flash attention, split-KV + ldmatrix: half the s-range per block --
#define FLM_SMEM_BYTES ((128 * KAH * 2 + 64 * KAH * 2 + 64 * KAH * 2) * 2)

__global__ __launch_bounds__(256) void flash_mma_kernel(
    const __nv_bfloat16* __restrict__ qhg, const __nv_bfloat16* __restrict__ qlg,
    const __nv_bfloat16* __restrict__ khg, const __nv_bfloat16* __restrict__ klg,
    const __nv_bfloat16* __restrict__ vth, const __nv_bfloat16* __restrict__ vtl,
    float* __restrict__ pO, float* __restrict__ pm, float* __restrict__ pl) {
    extern __shared__ char smc[];
    __nv_bfloat16* Qh = (__nv_bfloat16*)smc;          // [128][72]
    __nv_bfloat16* Ql = Qh + 128 * KAH;
    __nv_bfloat16* Kh = Ql + 128 * KAH;               // [64][72]
    __nv_bfloat16* Kl = Kh + 64 * KAH;
    __nv_bfloat16* Vh = Kl + 64 * KAH;                // [64][72]  (row = d, col = s)
    __nv_bfloat16* Vl = Vh + 64 * KAH;

    const int tid = threadIdx.x;
    const int bx = blockIdx.x, h = blockIdx.y;
    const int qb = bx >> 1, half = bx & 1;
    const int w = tid >> 5, lane = tid & 31;
    const int gid = lane >> 2, qid = lane & 3;
    const int rt = w * 16;
    const int t0 = qb * 128;

    const int lrow = lane & 7;
    const int a_row = rt + ((lane >> 3) & 1) * 8 + lrow;
    const int a_col = ((lane >> 4) & 1) * 8;
    const uint32_t qAddrH = smem_u32(Qh + a_row * KAH + a_col);
    const uint32_t qAddrL = smem_u32(Ql + a_row * KAH + a_col);
    const int b_row = ((lane >> 4) & 1) * 8 + lrow;
    const int b_col = ((lane >> 3) & 1) * 8;
    const uint32_t kAddrH = smem_u32(Kh + b_row * KAH + b_col);
    const uint32_t kAddrL = smem_u32(Kl + b_row * KAH + b_col);
    const uint32_t vAddrH = smem_u32(Vh + b_row * KAH + b_col);
    const uint32_t vAddrL = smem_u32(Vl + b_row * KAH + b_col);

    const __nv_bfloat16* Qhg = qhg + ((size_t)h * 1024 + t0) * 64;
    const __nv_bfloat16* Qlg = qlg + ((size_t)h * 1024 + t0) * 64;
    for (int i = tid; i < 1024; i += 256) {
        int r = i >> 3, c8 = (i & 7) * 8;
        *(uint4*)&Qh[r * KAH + c8] = *(const uint4*)(Qhg + (size_t)r * 64 + c8);
        *(uint4*)&Ql[r * KAH + c8] = *(const uint4*)(Qlg + (size_t)r * 64 + c8);
    }

    float m0 = -FLT_MAX, m1 = -FLT_MAX, l0 = 0.f, l1 = 0.f;
    float O[8][4];
#pragma unroll
    for (int nb = 0; nb < 8; nb++)
#pragma unroll
        for (int k = 0; k < 4; k++) O[nb][k] = 0.f;

    const int row0 = t0 + rt + gid, row1 = row0 + 8;
    const int jlo = half * (qb + 1);
    const int jhi = jlo + qb + 1;

    for (int j = jlo; j < jhi; j++) {
        const int s0 = j * 64;
        __syncthreads();
        const __nv_bfloat16* Khg = khg + ((size_t)h * 1024 + s0) * 64;
        const __nv_bfloat16* Klg = klg + ((size_t)h * 1024 + s0) * 64;
        for (int i = tid; i < 512; i += 256) {
            int r = i >> 3, c8 = (i & 7) * 8;
            *(uint4*)&Kh[r * KAH + c8] = *(const uint4*)(Khg + (size_t)r * 64 + c8);
            *(uint4*)&Kl[r * KAH + c8] = *(const uint4*)(Klg + (size_t)r * 64 + c8);
        }
        const __nv_bfloat16* Vhg = vth + (size_t)h * 64 * 1024 + s0;
        const __nv_bfloat16* Vlg = vtl + (size_t)h * 64 * 1024 + s0;
        for (int i = tid; i < 512; i += 256) {
            int r = i >> 3, c8 = (i & 7) * 8;
            *(uint4*)&Vh[r * KAH + c8] = *(const uint4*)(Vhg + (size_t)r * 1024 + c8);
            *(uint4*)&Vl[r * KAH + c8] = *(const uint4*)(Vlg + (size_t)r * 1024 + c8);
        }
        __syncthreads();

        // S = Q K^T (3xBF16, ldmatrix frags)
        float c[8][4];
#pragma unroll
        for (int nb = 0; nb < 8; nb++)
#pragma unroll
            for (int k = 0; k < 4; k++) c[nb][k] = 0.f;

#pragma unroll
        for (int ks16 = 0; ks16 < 4; ks16++) {
            const uint32_t koff = ks16 * 32;
            uint32_t ah0, ah1, ah2, ah3, al0, al1, al2, al3;
            ldsm_x4(ah0, ah1, ah2, ah3, qAddrH + koff);
            ldsm_x4(al0, al1, al2, al3, qAddrL + koff);
#pragma unroll
            for (int nbp = 0; nbp < 4; nbp++) {
                const uint32_t boff = nbp * (16 * KAH * 2) + koff;
                uint32_t bh0a, bh1a, bh0b, bh1b, bl0a, bl1a, bl0b, bl1b;
                ldsm_x4(bh0a, bh1a, bh0b, bh1b, kAddrH + boff);
                ldsm_x4(bl0a, bl1a, bl0b, bl1b, kAddrL + boff);
                const int nA = 2 * nbp, nB = 2 * nbp + 1;
                mma_bf16(c[nA][0], c[nA][1], c[nA][2], c[nA][3],
                         ah0, ah1, ah2, ah3, bh0a, bh1a);
                mma_bf16(c[nA][0], c[nA][1], c[nA][2], c[nA][3],
                         ah0, ah1, ah2, ah3, bl0a, bl1a);
                mma_bf16(c[nA][0], c[nA][1], c[nA][2], c[nA][3],
                         al0, al1, al2, al3, bh0a, bh1a);
                mma_bf16(c[nB][0], c[nB][1], c[nB][2], c[nB][3],
                         ah0, ah1, ah2, ah3, bh0b, bh1b);
                mma_bf16(c[nB][0], c[nB][1], c[nB][2], c[nB][3],
                         ah0, ah1, ah2, ah3, bl0b, bl1b);
                mma_bf16(c[nB][0], c[nB][1], c[nB][2], c[nB][3],
                         al0, al1, al2, al3, bh0b, bh1b);
            }
        }

        // causal mask
        if (s0 + 63 > t0 + rt) {
#pragma unroll
            for (int nb = 0; nb < 8; nb++) {
                int cb = s0 + nb * 8 + 2 * qid;
                if (cb > row0)     c[nb][0] = -FLT_MAX;
                if (cb + 1 > row0) c[nb][1] = -FLT_MAX;
                if (cb > row1)     c[nb][2] = -FLT_MAX;
                if (cb + 1 > row1) c[nb][3] = -FLT_MAX;
            }
        }

        // online softmax
        float rm0 = -FLT_MAX, rm1 = -FLT_MAX;
#pragma unroll
        for (int nb = 0; nb < 8; nb++) {
            rm0 = fmaxf(rm0, fmaxf(c[nb][0], c[nb][1]));
            rm1 = fmaxf(rm1, fmaxf(c[nb][2], c[nb][3]));
        }
        rm0 = fmaxf(rm0, __shfl_xor_sync(0xffffffffu, rm0, 1));
        rm0 = fmaxf(rm0, __shfl_xor_sync(0xffffffffu, rm0, 2));
        rm1 = fmaxf(rm1, __shfl_xor_sync(0xffffffffu, rm1, 1));
        rm1 = fmaxf(rm1, __shfl_xor_sync(0xffffffffu, rm1, 2));

        float mn0 = fmaxf(m0, rm0), mn1 = fmaxf(m1, rm1);
        float alpha0 = __expf(m0 - mn0), alpha1 = __expf(m1 - mn1);
        float ps0 = 0.f, ps1 = 0.f;
#pragma unroll
        for (int nb = 0; nb < 8; nb++) {
            c[nb][0] = __expf(c[nb][0] - mn0); ps0 += c[nb][0];
            c[nb][1] = __expf(c[nb][1] - mn0); ps0 += c[nb][1];
            c[nb][2] = __expf(c[nb][2] - mn1); ps1 += c[nb][2];
            c[nb][3] = __expf(c[nb][3] - mn1); ps1 += c[nb][3];
        }
        ps0 += __shfl_xor_sync(0xffffffffu, ps0, 1);
        ps0 += __shfl_xor_sync(0xffffffffu, ps0, 2);
        ps1 += __shfl_xor_sync(0xffffffffu, ps1, 1);
        ps1 += __shfl_xor_sync(0xffffffffu, ps1, 2);
        l0 = l0 * alpha0 + ps0; m0 = mn0;
        l1 = l1 * alpha1 + ps1; m1 = mn1;
#pragma unroll
        for (int nb = 0; nb < 8; nb++) {
            O[nb][0] *= alpha0; O[nb][1] *= alpha0;
            O[nb][2] *= alpha1; O[nb][3] *= alpha1;
        }

        // P@V (ldmatrix V frags; P converted in registers)
#pragma unroll
        for (int kb = 0; kb < 4; kb++) {
            float p00 = c[2 * kb][0],     p01 = c[2 * kb][1];
            float p02 = c[2 * kb][2],     p03 = c[2 * kb][3];
            float p10 = c[2 * kb + 1][0], p11 = c[2 * kb + 1][1];
            float p12 = c[2 * kb + 1][2], p13 = c[2 * kb + 1][3];
            __nv_bfloat16 h00 = __float2bfloat16(p00), h01 = __float2bfloat16(p01);
            __nv_bfloat16 h02 = __float2bfloat16(p02), h03 = __float2bfloat16(p03);
            __nv_bfloat16 h10 = __float2bfloat16(p10), h11 = __float2bfloat16(p11);
            __nv_bfloat16 h12 = __float2bfloat16(p12), h13 = __float2bfloat16(p13);
            uint32_t Ah0 = pack_bf16(h00, h01);
            uint32_t Ah1 = pack_bf16(h02, h03);
            uint32_t Ah2 = pack_bf16(h10, h11);
            uint32_t Ah3 = pack_bf16(h12, h13);
            uint32_t Al0 = pack_bf16(__float2bfloat16(p00 - __bfloat162float(h00)),
                                     __float2bfloat16(p01 - __bfloat162float(h01)));
            uint32_t Al1 = pack_bf16(__float2bfloat16(p02 - __bfloat162float(h02)),
                                     __float2bfloat16(p03 - __bfloat162float(h03)));
            uint32_t Al2 = pack_bf16(__float2bfloat16(p10 - __bfloat162float(h10)),
                                     __float2bfloat16(p11 - __bfloat162float(h11)));
            uint32_t Al3 = pack_bf16(__float2bfloat16(p12 - __bfloat162float(h12)),
                                     __float2bfloat16(p13 - __bfloat162float(h13)));
            const uint32_t koff = kb * 32;
#pragma unroll
            for (int nbp = 0; nbp < 4; nbp++) {
                const uint32_t boff = nbp * (16 * KAH * 2) + koff;
                uint32_t bh0a, bh1a, bh0b, bh1b, bl0a, bl1a, bl0b, bl1b;
                ldsm_x4(bh0a, bh1a, bh0b, bh1b, vAddrH + boff);
                ldsm_x4(bl0a, bl1a, bl0b, bl1b, vAddrL + boff);
                const int nA = 2 * nbp, nB = 2 * nbp + 1;
                mma_bf16(O[nA][0], O[nA][1], O[nA][2], O[nA][3],
                         Ah0, Ah1, Ah2, Ah3, bh0a, bh1a);
                mma_bf16(O[nA][0], O[nA][1], O[nA][2], O[nA][3],
                         Ah0, Ah1, Ah2, Ah3, bl0a, bl1a);
                mma_bf16(O[nA][0], O[nA][1], O[nA][2], O[nA][3],
                         Al0, Al1, Al2, Al3, bh0a, bh1a);
                mma_bf16(O[nB][0], O[nB][1], O[nB][2], O[nB][3],
                         Ah0, Ah1, Ah2, Ah3, bh0b, bh1b);
                mma_bf16(O[nB][0], O[nB][1], O[nB][2], O[nB][3],
                         Ah0, Ah1, Ah2, Ah3, bl0b, bl1b);
                mma_bf16(O[nB][0], O[nB][1], O[nB][2], O[nB][3],
                         Al0, Al1, Al2, Al3, bh0b, bh1b);
            }
        }
    }

    // epilogue: store unnormalized partial (m, l, O)
    const size_t base = ((size_t)half * 16 + h) * 1024;
    if (qid == 0) {
        pm[base + row0] = m0; pl[base + row0] = l0;
        pm[base + row1] = m1; pl[base + row1] = l1;
    }
#pragma unroll
    for (int nb = 0; nb < 8; nb++) {
        int colb = nb * 8 + 2 * qid;
        pO[(base + row0) * 64 + colb]     = O[nb][0];
        pO[(base + row0) * 64 + colb + 1] = O[nb][1];
        pO[(base + row1) * 64 + colb]     = O[nb][2];
        pO[(base + row1) * 64 + colb + 1] = O[nb][3];
    }
}

// ---- merge the two flash partials per (h, t) row -> yh/yl bf16 split directly ----
__global__ void flash_merge_kernel(const float* __restrict__ pO,
                                   const float* __restrict__ pm,
                                   const float* __restrict__ pl,
                                   __nv_bfloat16* __restrict__ yh,
                                   __nv_bfloat16* __restrict__ yl) {
    int i = blockIdx.x * 256 + threadIdx.x;   // < 16*1024*64 = 1M
    int d = i & 63, t = (i >> 6) & 1023, h = i >> 16;
    size_t r0 = (size_t)h * 1024 + t;
    size_t r1 = (size_t)16 * 1024 + r0;
    float ma = pm[r0], mb = pm[r1];
    float mm = fmaxf(ma, mb);
    float ea = __expf(ma - mm), eb = __expf(mb - mm);
    float l = pl[r0] * ea + pl[r1] * eb;
    float o = pO[r0 * 64 + d] * ea + pO[r1 * 64 + d] * eb;
    float val = o / l;
    __nv_bfloat16 hh = __float2bfloat16(val);
    size_t oi = (size_t)t * 1024 + h * 64 + d;
    yh[oi] = hh;
    yl[oi] = __float2bfloat16(val - __bfloat162float(hh));
}

// ---------------- launch ----------------
extern "C" void kernel_launch(void* const* d_in, const int* in_sizes, int n_in,
                              void* d_out, int out_size) {
    const float* x  = (const float*)d_in[0];
    const float* aw = (const float*)d_in[1];
    const float* ab = (const float*)d_in[2];
    const float* pw = (const float*)d_in[3];
    const float* pb = (const float*)d_in[4];
    const float* ks = (const float*)d_in[5];
    const float* vs = (const float*)d_in[6];
    float* out = (float*)d_out;

    float *qkv, *ksn, *lg, *vnw, *pO, *pm, *pl;
    __nv_bfloat16 *kh, *kl, *qh, *ql, *mh, *ml, *xh, *xl, *awh, *awl, *pwh, *pwl, *yh, *yl;
    __nv_bfloat16 *vth, *vtl;
    int *idx, *sel;
    cudaGetSymbolAddress((void**)&qkv, g_qkv);
    cudaGetSymbolAddress((void**)&ksn, g_ksnorm);
    cudaGetSymbolAddress((void**)&kh,  g_kh);
    cudaGetSymbolAddress((void**)&kl,  g_kl);
    cudaGetSymbolAddress((void**)&qh,  g_qh);
    cudaGetSymbolAddress((void**)&ql,  g_ql);
    cudaGetSymbolAddress((void**)&mh,  g_mh);
    cudaGetSymbolAddress((void**)&ml,  g_ml);
    cudaGetSymbolAddress((void**)&xh,  g_xh);
    cudaGetSymbolAddress((void**)&xl,  g_xl);
    cudaGetSymbolAddress((void**)&awh, g_awh);
    cudaGetSymbolAddress((void**)&awl, g_awl);
    cudaGetSymbolAddress((void**)&pwh, g_pwh);
    cudaGetSymbolAddress((void**)&pwl, g_pwl);
    cudaGetSymbolAddress((void**)&yh,  g_yh);
    cudaGetSymbolAddress((void**)&yl,  g_yl);
    cudaGetSymbolAddress((void**)&vth, g_vth);
    cudaGetSymbolAddress((void**)&vtl, g_vtl);
    cudaGetSymbolAddress((void**)&pO,  g_pO);
    cudaGetSymbolAddress((void**)&pm,  g_pm);
    cudaGetSymbolAddress((void**)&pl,  g_pl);
    cudaGetSymbolAddress((void**)&lg,  g_lg);
    cudaGetSymbolAddress((void**)&idx, g_idx);
    cudaGetSymbolAddress((void**)&sel, g_sel);
    cudaGetSymbolAddress((void**)&vnw, g_vnew);

    cudaFuncSetAttribute(knn_mma_kernel,
                         cudaFuncAttributeMaxDynamicSharedMemorySize, KNN_SMEM_BYTES);
    cudaFuncSetAttribute(mma_gemm_bf16_kernel,
                         cudaFuncAttributeMaxDynamicSharedMemorySize, GM_SMEM_BYTES);
    cudaFuncSetAttribute(flash_mma_kernel,
                         cudaFuncAttributeMaxDynamicSharedMemorySize, FLM_SMEM_BYTES);

    // 0) bf16 hi/lo splits
    split_bf16_v4<<<1024, 256>>>((const float4*)x,
                                 (__nv_bfloat162*)xh, (__nv_bfloat162*)xl);
    split_bf16_v4<<<3072, 256>>>((const float4*)aw,
                                 (__nv_bfloat162*)awh, (__nv_bfloat162*)awl);
    split_bf16_v4<<<1024, 256>>>((const float4*)pw,
                                 (__nv_bfloat162*)pwh, (__nv_bfloat162*)pwl);
    split_bf16_v4<<<8192, 256>>>((const float4*)ks,
                                 (__nv_bfloat162*)mh, (__nv_bfloat162*)ml);
    // 1) qkv = x @ c_attn_w^T + b   (3xBF16 mma + ldmatrix + cp.async dbuf)
    mma_gemm_bf16_kernel<<<dim3(24, 16), 256, GM_SMEM_BYTES>>>(
        xh, xl, awh, awl, qkv, 3072, 1024, ab);
    // 2) key_store norms + k/q split/relayout
    ksnorm_kernel<<<512, 256>>>(ks, ksn);
    split_qk_bf16_kernel<<<2048, 1024>>>(qkv, kh, kl, qh, ql);
    // 3) fused kNN scores + top-4 (bf16 mma + ldmatrix + cp.async double buffer)
    knn_mma_kernel<<<dim3(16, 16), 256, KNN_SMEM_BYTES>>>(
        kh, kl, mh, ml, ksn, idx);
    // 4) sel from last-row softmax
    selA_kernel<<<dim3(128, 16), 256>>>(qkv, lg);
    selB_kernel<<<16, 1024>>>(lg, sel);
    // 5) 5-way softmax blend -> v_new
    vnew_kernel<<<2048, 256>>>(qkv, ks, vs, idx, sel, vnw);
    // 5b) transpose+split v_new for flash PV
    vtrans_kernel<<<dim3(16, 16), 256>>>(vnw, vth, vtl);
    // 6) split-KV flash attention (partials) + fused merge/split -> yh/yl
    flash_mma_kernel<<<dim3(16, 16), 256, FLM_SMEM_BYTES>>>(
        qh, ql, kh, kl, vth, vtl, pO, pm, pl);
    flash_merge_kernel<<<4096, 256>>>(pO, pm, pl, yh, yl);
    // 7) out = y @ c_proj_w^T + b   (3xBF16 mma + ldmatrix + cp.async dbuf)
    mma_gemm_bf16_kernel<<<dim3(8, 16), 256, GM_SMEM_BYTES>>>(
        yh, yl, pwh, pwl, out, 1024, 1024, pb);
}

// round 17
// speedup vs baseline: 1.7326x; 1.0001x over previous
#include <cuda_runtime.h>
#include <cuda_bf16.h>
#include <cfloat>
#include <cstdint>

// ---------------- scratch (__device__ globals; no allocations) ----------------
__device__ float g_qkv[1024 * 3072];              // 12 MB  (T, 3C)
__device__ float g_ksnorm[16 * 8192];             // (H, M)
__device__ __nv_bfloat16 g_kh[16 * 1024 * 64];    // bf16-hi of k, [h][t][d]
__device__ __nv_bfloat16 g_kl[16 * 1024 * 64];    // bf16-lo of k
__device__ __nv_bfloat16 g_qh[16 * 1024 * 64];    // bf16-hi of q*0.125, [h][t][d]
__device__ __nv_bfloat16 g_ql[16 * 1024 * 64];    // bf16-lo
__device__ __nv_bfloat16 g_mh[16 * 8192 * 64];    // bf16-hi of key_store
__device__ __nv_bfloat16 g_ml[16 * 8192 * 64];    // bf16-lo of key_store
__device__ __nv_bfloat16 g_xh[1024 * 1024];       // bf16-hi of x
__device__ __nv_bfloat16 g_xl[1024 * 1024];
__device__ __nv_bfloat16 g_awh[3072 * 1024];      // bf16-hi of c_attn_w
__device__ __nv_bfloat16 g_awl[3072 * 1024];
__device__ __nv_bfloat16 g_pwh[1024 * 1024];      // bf16-hi of c_proj_w
__device__ __nv_bfloat16 g_pwl[1024 * 1024];
__device__ __nv_bfloat16 g_yh[1024 * 1024];       // bf16-hi of y (written by merge)
__device__ __nv_bfloat16 g_yl[1024 * 1024];
__device__ __nv_bfloat16 g_vth[16 * 64 * 1024];   // bf16-hi of v_new^T, [h][d][t]
__device__ __nv_bfloat16 g_vtl[16 * 64 * 1024];   // bf16-lo
__device__ float g_pO[2 * 16 * 1024 * 64];        // flash partial O [half][h][t][d]
__device__ float g_pm[2 * 16 * 1024];             // flash partial row max
__device__ float g_pl[2 * 16 * 1024];             // flash partial row sum
__device__ float g_lg[16 * 1024];                 // last-row logits
__device__ int   g_idx[16 * 1024 * 4];            // (H, T, 4)
__device__ int   g_sel[16 * 1024];                // (H, T)
__device__ float g_vnew[16 * 1024 * 64];          // (H, T, d)

// ---------------- helpers ----------------
__device__ __forceinline__ void mma_bf16(float& c0, float& c1, float& c2, float& c3,
                                         uint32_t a0, uint32_t a1, uint32_t a2, uint32_t a3,
                                         uint32_t b0, uint32_t b1) {
    asm volatile(
        "mma.sync.aligned.m16n8k16.row.col.f32.bf16.bf16.f32 "
        "{%0,%1,%2,%3}, {%4,%5,%6,%7}, {%8,%9}, {%0,%1,%2,%3};"
        : "+f"(c0), "+f"(c1), "+f"(c2), "+f"(c3)
        : "r"(a0), "r"(a1), "r"(a2), "r"(a3), "r"(b0), "r"(b1));
}

__device__ __forceinline__ void ldsm_x4(uint32_t& r0, uint32_t& r1,
                                        uint32_t& r2, uint32_t& r3, uint32_t addr) {
    asm volatile("ldmatrix.sync.aligned.m8n8.x4.shared.b16 {%0,%1,%2,%3}, [%4];"
                 : "=r"(r0), "=r"(r1), "=r"(r2), "=r"(r3) : "r"(addr));
}

__device__ __forceinline__ uint32_t smem_u32(const void* p) {
    return (uint32_t)__cvta_generic_to_shared(p);
}

__device__ __forceinline__ void cp_async16(uint32_t dst, const void* src) {
    asm volatile("cp.async.cg.shared.global [%0], [%1], 16;" :: "r"(dst), "l"(src));
}

__device__ __forceinline__ void cp_async4(uint32_t dst, const void* src) {
    asm volatile("cp.async.ca.shared.global [%0], [%1], 4;" :: "r"(dst), "l"(src));
}

__device__ __forceinline__ uint32_t pack_bf16(__nv_bfloat16 lo, __nv_bfloat16 hi) {
    __nv_bfloat162 t;
    t.x = lo; t.y = hi;
    return *(uint32_t*)&t;
}

// ---------- vectorized contiguous bf16 hi/lo split (4 floats / thread) ----------
__global__ void split_bf16_v4(const float4* __restrict__ src,
                              __nv_bfloat162* __restrict__ hi,
                              __nv_bfloat162* __restrict__ lo) {
    size_t i = (size_t)blockIdx.x * 256 + threadIdx.x;
    float4 v = src[i];
    __nv_bfloat16 h0 = __float2bfloat16(v.x), h1 = __float2bfloat16(v.y);
    __nv_bfloat16 h2 = __float2bfloat16(v.z), h3 = __float2bfloat16(v.w);
    __nv_bfloat16 l0 = __float2bfloat16(v.x - __bfloat162float(h0));
    __nv_bfloat16 l1 = __float2bfloat16(v.y - __bfloat162float(h1));
    __nv_bfloat16 l2 = __float2bfloat16(v.z - __bfloat162float(h2));
    __nv_bfloat16 l3 = __float2bfloat16(v.w - __bfloat162float(h3));
    hi[i * 2 + 0] = __nv_bfloat162{h0, h1};
    hi[i * 2 + 1] = __nv_bfloat162{h2, h3};
    lo[i * 2 + 0] = __nv_bfloat162{l0, l1};
    lo[i * 2 + 1] = __nv_bfloat162{l2, l3};
}

// -- bf16 hi/lo split of k AND q (scaled 0.125) from qkv, relayout to [h][t][d] --
__global__ void split_qk_bf16_kernel(const float* __restrict__ qkv,
                                     __nv_bfloat16* __restrict__ khi,
                                     __nv_bfloat16* __restrict__ klo,
                                     __nv_bfloat16* __restrict__ qhi,
                                     __nv_bfloat16* __restrict__ qlo) {
    int i = blockIdx.x * 1024 + threadIdx.x;  // 2M
    int which = i >> 20;                      // 0: k, 1: q
    int r = i & 0xFFFFF;
    int d = r & 63, t = (r >> 6) & 1023, h = r >> 16;
    float x = qkv[(size_t)t * 3072 + (which ? 0 : 1024) + h * 64 + d];
    if (which) x *= 0.125f;
    __nv_bfloat16 hf = __float2bfloat16(x);
    __nv_bfloat16 lf = __float2bfloat16(x - __bfloat162float(hf));
    if (which) { qhi[r] = hf; qlo[r] = lf; }
    else       { khi[r] = hf; klo[r] = lf; }
}

// ---- generic 3xBF16 mma GEMM: C = A*B^T + bias  (ldmatrix + cp.async dbuf) ----
#define KAH 72
#define GM_SMEM_BYTES (2 * (64 * KAH * 2 + 128 * KAH * 2) * 2)

__global__ __launch_bounds__(256) void mma_gemm_bf16_kernel(
    const __nv_bfloat16* __restrict__ Ahg, const __nv_bfloat16* __restrict__ Alg,
    const __nv_bfloat16* __restrict__ Bhg, const __nv_bfloat16* __restrict__ Blg,
    float* __restrict__ C, int ldc, int K, const float* __restrict__ bias) {
    extern __shared__ char smc[];
    const int BUFE = (64 + 64 + 128 + 128) * KAH;   // elements per buffer

    const int tid = threadIdx.x;
    const int bx = blockIdx.x, by = blockIdx.y;
    const int w = tid >> 5, lane = tid & 31;
    const int gid = lane >> 2, qid = lane & 3;
    const int rt = (w & 3) * 16;
    const int ch = (w >> 2) * 64;

    const int lrow = lane & 7;
    const int a_row = rt + ((lane >> 3) & 1) * 8 + lrow;
    const int a_col = ((lane >> 4) & 1) * 8;
    const int b_row = ch + ((lane >> 4) & 1) * 8 + lrow;
    const int b_col = ((lane >> 3) & 1) * 8;

    uint32_t aAddrH[2], aAddrL[2], bAddrH[2], bAddrL[2];
    __nv_bfloat16* Abase[2];
    __nv_bfloat16* Bbase[2];
#pragma unroll
    for (int b = 0; b < 2; b++) {
        __nv_bfloat16* Ah = (__nv_bfloat16*)smc + b * BUFE;
        __nv_bfloat16* Al = Ah + 64 * KAH;
        __nv_bfloat16* Bh = Al + 64 * KAH;
        __nv_bfloat16* Bl = Bh + 128 * KAH;
        Abase[b] = Ah;
        Bbase[b] = Bh;
        aAddrH[b] = smem_u32(Ah + a_row * KAH + a_col);
        aAddrL[b] = smem_u32(Al + a_row * KAH + a_col);
        bAddrH[b] = smem_u32(Bh + b_row * KAH + b_col);
        bAddrL[b] = smem_u32(Bl + b_row * KAH + b_col);
    }

    const __nv_bfloat16* Ahb = Ahg + (size_t)(by * 64) * K;
    const __nv_bfloat16* Alb = Alg + (size_t)(by * 64) * K;
    const __nv_bfloat16* Bhb = Bhg + (size_t)(bx * 128) * K;
    const __nv_bfloat16* Blb = Blg + (size_t)(bx * 128) * K;

    float c[8][4];
#pragma unroll
    for (int nb = 0; nb < 8; nb++)
#pragma unroll
        for (int k = 0; k < 4; k++) c[nb][k] = 0.f;

    const int nt = K >> 6;

    auto issue = [&](int kt, int b) {
        const int k0 = kt << 6;
        __nv_bfloat16* Ah = Abase[b];
        __nv_bfloat16* Al = Ah + 64 * KAH;
        __nv_bfloat16* Bh = Bbase[b];
        __nv_bfloat16* Bl = Bh + 128 * KAH;
        for (int i = tid; i < 512; i += 256) {
            int r = i >> 3, c8 = (i & 7) * 8;
            cp_async16(smem_u32(Ah + r * KAH + c8), Ahb + (size_t)r * K + k0 + c8);
            cp_async16(smem_u32(Al + r * KAH + c8), Alb + (size_t)r * K + k0 + c8);
        }
        for (int i = tid; i < 1024; i += 256) {
            int r = i >> 3, c8 = (i & 7) * 8;
            cp_async16(smem_u32(Bh + r * KAH + c8), Bhb + (size_t)r * K + k0 + c8);
            cp_async16(smem_u32(Bl + r * KAH + c8), Blb + (size_t)r * K + k0 + c8);
        }
        asm volatile("cp.async.commit_group;" ::: "memory");
    };

    issue(0, 0);

    for (int kt = 0; kt < nt; kt++) {
        const int b = kt & 1;
        asm volatile("cp.async.wait_group 0;" ::: "memory");
        __syncthreads();
        if (kt + 1 < nt) issue(kt + 1, b ^ 1);

#pragma unroll
        for (int ks16 = 0; ks16 < 4; ks16++) {
            const uint32_t koff = ks16 * 32;
            uint32_t ah0, ah1, ah2, ah3, al0, al1, al2, al3;
            ldsm_x4(ah0, ah1, ah2, ah3, aAddrH[b] + koff);
            ldsm_x4(al0, al1, al2, al3, aAddrL[b] + koff);
#pragma unroll
            for (int nbp = 0; nbp < 4; nbp++) {
                const uint32_t boff = nbp * (16 * KAH * 2) + koff;
                uint32_t bh0a, bh1a, bh0b, bh1b, bl0a, bl1a, bl0b, bl1b;
                ldsm_x4(bh0a, bh1a, bh0b, bh1b, bAddrH[b] + boff);
                ldsm_x4(bl0a, bl1a, bl0b, bl1b, bAddrL[b] + boff);
                const int nA = 2 * nbp, nB = 2 * nbp + 1;
                mma_bf16(c[nA][0], c[nA][1], c[nA][2], c[nA][3],
                         ah0, ah1, ah2, ah3, bh0a, bh1a);
                mma_bf16(c[nA][0], c[nA][1], c[nA][2], c[nA][3],
                         ah0, ah1, ah2, ah3, bl0a, bl1a);
                mma_bf16(c[nA][0], c[nA][1], c[nA][2], c[nA][3],
                         al0, al1, al2, al3, bh0a, bh1a);
                mma_bf16(c[nB][0], c[nB][1], c[nB][2], c[nB][3],
                         ah0, ah1, ah2, ah3, bh0b, bh1b);
                mma_bf16(c[nB][0], c[nB][1], c[nB][2], c[nB][3],
                         ah0, ah1, ah2, ah3, bl0b, bl1b);
                mma_bf16(c[nB][0], c[nB][1], c[nB][2], c[nB][3],
                         al0, al1, al2, al3, bh0b, bh1b);
            }
        }
        __syncthreads();
    }

#pragma unroll
    for (int nb = 0; nb < 8; nb++) {
#pragma unroll
        for (int k = 0; k < 4; k++) {
            int row = by * 64 + rt + gid + (k >> 1) * 8;
            int col = bx * 128 + ch + nb * 8 + 2 * qid + (k & 1);
            C[(size_t)row * ldc + col] = c[nb][k] + bias[col];
        }
    }
}

// ---------------- ||key_store[h,m]||^2 (exact fp32) ----------------
__global__ void ksnorm_kernel(const float* __restrict__ ks, float* __restrict__ nrm) {
    int r = blockIdx.x * blockDim.x + threadIdx.x;
    if (r >= 16 * 8192) return;
    const float4* p = (const float4*)(ks + (size_t)r * 64);
    float s = 0.f;
#pragma unroll
    for (int i = 0; i < 16; i++) {
        float4 f = p[i];
        s += f.x * f.x + f.y * f.y + f.z * f.z + f.w * f.w;
    }
    nrm[r] = s;
}

// ------------- lexicographic (score, idx) compare: stable top-k --------------
__device__ __forceinline__ bool lex_lt(float sa, int ia, float sb, int ib) {
    return sa < sb || (sa == sb && ia < ib);
}

#define TOP4_INSERT(v, m, s0, x0, s1, x1, s2, x2, s3, x3)              \
    if (lex_lt(v, m, s3, x3)) {                                        \
        if (lex_lt(v, m, s2, x2)) {                                    \
            s3 = s2; x3 = x2;                                          \
            if (lex_lt(v, m, s1, x1)) {                                \
                s2 = s1; x2 = x1;                                      \
                if (lex_lt(v, m, s0, x0)) {                            \
                    s1 = s0; x1 = x0; s0 = v; x0 = m;                  \
                } else { s1 = v; x1 = m; }                             \
            } else { s2 = v; x2 = m; }                                 \
        } else { s3 = v; x3 = m; }                                     \
    }

// ---- fused kNN scores + top-4, bf16 mma + ldmatrix + cp.async double buffer ----
#define KNN_SMEM_BYTES (18432 + 73728 + 1024)

__global__ __launch_bounds__(256) void knn_mma_kernel(
    const __nv_bfloat16* __restrict__ kh, const __nv_bfloat16* __restrict__ kl,
    const __nv_bfloat16* __restrict__ mh, const __nv_bfloat16* __restrict__ ml,
    const float* __restrict__ ksn, int* __restrict__ idx_out) {
    extern __shared__ char smc[];
    __nv_bfloat16* Ah = (__nv_bfloat16*)smc;          // [64][72]
    __nv_bfloat16* Al = Ah + 64 * KAH;
    __nv_bfloat16* Bbuf = Al + 64 * KAH;              // 2 x (Bh, Bl) [128][72]
    float* NsBase = (float*)(Bbuf + 4 * 128 * KAH);   // 2 x [128]

    const int tid = threadIdx.x;
    const int t0 = blockIdx.x * 64;
    const int h = blockIdx.y;
    const int w = tid >> 5, lane = tid & 31;
    const int gid = lane >> 2, qid = lane & 3;
    const int rt = (w & 3) * 16;
    const int ch = (w >> 2) * 64;

    const int lrow = lane & 7;
    const int a_row = rt + ((lane >> 3) & 1) * 8 + lrow;
    const int a_col = ((lane >> 4) & 1) * 8;
    const uint32_t aAddrH = smem_u32(Ah + a_row * KAH + a_col);
    const uint32_t aAddrL = smem_u32(Al + a_row * KAH + a_col);
    const int b_row = ch + ((lane >> 4) & 1) * 8 + lrow;
    const int b_col = ((lane >> 3) & 1) * 8;
    uint32_t bAddrH[2], bAddrL[2];
#pragma unroll
    for (int b = 0; b < 2; b++) {
        __nv_bfloat16* BhB = Bbuf + b * (2 * 128 * KAH);
        __nv_bfloat16* BlB = BhB + 128 * KAH;
        bAddrH[b] = smem_u32(BhB + b_row * KAH + b_col);
        bAddrL[b] = smem_u32(BlB + b_row * KAH + b_col);
    }

    const __nv_bfloat16* Ahg = kh + ((size_t)h * 1024 + t0) * 64;
    const __nv_bfloat16* Alg = kl + ((size_t)h * 1024 + t0) * 64;
    for (int i = tid; i < 512; i += 256) {
        int r = i >> 3, c8 = (i & 7) * 8;
        *(uint4*)&Ah[r * KAH + c8] = *(const uint4*)(Ahg + (size_t)r * 64 + c8);
        *(uint4*)&Al[r * KAH + c8] = *(const uint4*)(Alg + (size_t)r * 64 + c8);
    }

    float S[2][4];
    int I[2][4];
#pragma unroll
    for (int r = 0; r < 2; r++)
#pragma unroll
        for (int k = 0; k < 4; k++) { S[r][k] = FLT_MAX; I[r][k] = 0x7fffffff; }

    const __nv_bfloat16* Bhg = mh + (size_t)h * 8192 * 64;
    const __nv_bfloat16* Blg = ml + (size_t)h * 8192 * 64;
    const float* Nbase = ksn + h * 8192;

    auto issue = [&](int chunk, int b) {
        const int m0 = chunk << 7;
        __nv_bfloat16* BhB = Bbuf + b * (2 * 128 * KAH);
        __nv_bfloat16* BlB = BhB + 128 * KAH;
        for (int i = tid; i < 1024; i += 256) {
            int r = i >> 3, c8 = (i & 7) * 8;
            cp_async16(smem_u32(BhB + r * KAH + c8), Bhg + (size_t)(m0 + r) * 64 + c8);
            cp_async16(smem_u32(BlB + r * KAH + c8), Blg + (size_t)(m0 + r) * 64 + c8);
        }
        if (tid < 128) cp_async4(smem_u32(NsBase + b * 128 + tid), Nbase + m0 + tid);
        asm volatile("cp.async.commit_group;" ::: "memory");
    };

    issue(0, 0);

    for (int chunk = 0; chunk < 64; chunk++) {
        const int b = chunk & 1;
        asm volatile("cp.async.wait_group 0;" ::: "memory");
        __syncthreads();
        if (chunk + 1 < 64) issue(chunk + 1, b ^ 1);
        const float* Ns = NsBase + b * 128;

        float c[8][4];
#pragma unroll
        for (int nb = 0; nb < 8; nb++)
#pragma unroll
            for (int k = 0; k < 4; k++) c[nb][k] = 0.f;

#pragma unroll
        for (int ks16 = 0; ks16 < 4; ks16++) {
            const uint32_t koff = ks16 * 32;
            uint32_t ah0, ah1, ah2, ah3, al0, al1, al2, al3;
            ldsm_x4(ah0, ah1, ah2, ah3, aAddrH + koff);
            ldsm_x4(al0, al1, al2, al3, aAddrL + koff);
#pragma unroll
            for (int nbp = 0; nbp < 4; nbp++) {
                const uint32_t boff = nbp * (16 * KAH * 2) + koff;
                uint32_t bh0a, bh1a, bh0b, bh1b, bl0a, bl1a, bl0b, bl1b;
                ldsm_x4(bh0a, bh1a, bh0b, bh1b, bAddrH[b] + boff);
                ldsm_x4(bl0a, bl1a, bl0b, bl1b, bAddrL[b] + boff);
                const int nA = 2 * nbp, nB = 2 * nbp + 1;
                mma_bf16(c[nA][0], c[nA][1], c[nA][2], c[nA][3],
                         ah0, ah1, ah2, ah3, bh0a, bh1a);
                mma_bf16(c[nA][0], c[nA][1], c[nA][2], c[nA][3],
                         ah0, ah1, ah2, ah3, bl0a, bl1a);
                mma_bf16(c[nA][0], c[nA][1], c[nA][2], c[nA][3],
                         al0, al1, al2, al3, bh0a, bh1a);
                mma_bf16(c[nB][0], c[nB][1], c[nB][2], c[nB][3],
                         ah0, ah1, ah2, ah3, bh0b, bh1b);
                mma_bf16(c[nB][0], c[nB][1], c[nB][2], c[nB][3],
                         ah0, ah1, ah2, ah3, bl0b, bl1b);
                mma_bf16(c[nB][0], c[nB][1], c[nB][2], c[nB][3],
                         al0, al1, al2, al3, bh0b, bh1b);
            }
        }

        const int m0 = chunk << 7;
#pragma unroll
        for (int nb = 0; nb < 8; nb++) {
#pragma unroll
            for (int k = 0; k < 4; k++) {
                int cl = ch + nb * 8 + 2 * qid + (k & 1);
                int r = k >> 1;
                float v = Ns[cl] - 2.0f * c[nb][k];
                int mg = m0 + cl;
                TOP4_INSERT(v, mg, S[r][0], I[r][0], S[r][1], I[r][1],
                            S[r][2], I[r][2], S[r][3], I[r][3]);
            }
        }
        __syncthreads();
    }

    float* msc = (float*)smc;                 // [64][32]
    int* mix = (int*)(smc + 16384);
    const int slot = (w >> 2) * 4 + qid;
#pragma unroll
    for (int r = 0; r < 2; r++) {
        int row = rt + gid + r * 8;
#pragma unroll
        for (int k = 0; k < 4; k++) {
            msc[(row * 8 + slot) * 4 + k] = S[r][k];
            mix[(row * 8 + slot) * 4 + k] = I[r][k];
        }
    }
    __syncthreads();
    if (tid < 64) {
        float f0 = FLT_MAX, f1 = FLT_MAX, f2 = FLT_MAX, f3 = FLT_MAX;
        int g0 = 0x7fffffff, g1 = 0x7fffffff, g2 = 0x7fffffff, g3 = 0x7fffffff;
        for (int c2 = 0; c2 < 32; c2++) {
            float v = msc[tid * 32 + c2];
            int m = mix[tid * 32 + c2];
            TOP4_INSERT(v, m, f0, g0, f1, g1, f2, g2, f3, g3);
        }
        size_t row = (size_t)h * 1024 + t0 + tid;
        idx_out[row * 4 + 0] = g0;
        idx_out[row * 4 + 1] = g1;
        idx_out[row * 4 + 2] = g2;
        idx_out[row * 4 + 3] = g3;
    }
}

// ---------------- warp-per-token last-row logits ----------------
__global__ void selA_kernel(const float* __restrict__ qkv, float* __restrict__ lg) {
    int h = blockIdx.y;
    int t = blockIdx.x * 8 + (threadIdx.x >> 5);
    int lane = threadIdx.x & 31;
    int d0 = lane * 2;
    const float* q = qkv + (size_t)1023 * 3072 + h * 64;
    const float* k = qkv + (size_t)t * 3072 + 1024 + h * 64;
    float s = q[d0] * k[d0] + q[d0 + 1] * k[d0 + 1];
#pragma unroll
    for (int o = 16; o > 0; o >>= 1) s += __shfl_xor_sync(0xffffffffu, s, o);
    if (lane == 0) lg[h * 1024 + t] = s * 0.125f;
}

// ---------------- per-head softmax of logits row -> sel ----------------
__global__ void selB_kernel(const float* __restrict__ lg, int* __restrict__ sel) {
    int h = blockIdx.x;
    int tid = threadIdx.x;
    int lane = tid & 31, warp = tid >> 5;
    __shared__ float red[8];
    __shared__ float bcast;

    float v[4];
#pragma unroll
    for (int u = 0; u < 4; u++) v[u] = lg[h * 1024 + tid + u * 256];
    float m = fmaxf(fmaxf(v[0], v[1]), fmaxf(v[2], v[3]));
#pragma unroll
    for (int o = 16; o > 0; o >>= 1) m = fmaxf(m, __shfl_xor_sync(0xffffffffu, m, o));
    if (lane == 0) red[warp] = m;
    __syncthreads();
    if (tid == 0) {
        float x = red[0];
#pragma unroll
        for (int w = 1; w < 8; w++) x = fmaxf(x, red[w]);
        bcast = x;
    }
    __syncthreads();
    m = bcast;
    float e[4], s = 0.f;
#pragma unroll
    for (int u = 0; u < 4; u++) { e[u] = __expf(v[u] - m); s += e[u]; }
#pragma unroll
    for (int o = 16; o > 0; o >>= 1) s += __shfl_xor_sync(0xffffffffu, s, o);
    if (lane == 0) red[warp] = s;
    __syncthreads();
    if (tid == 0) {
        float x = 0.f;
#pragma unroll
        for (int w = 0; w < 8; w++) x += red[w];
        bcast = x;
    }
    __syncthreads();
    float inv = 1.f / bcast;
#pragma unroll
    for (int u = 0; u < 4; u++)
        sel[h * 1024 + tid + u * 256] = (e[u] * inv >= (1.0f / 8192.0f)) ? 1 : 0;
}

// ---------------- per-token 5-way memory softmax & blend -> v_new ----------------
__device__ __forceinline__ float warp_sum(float v) {
#pragma unroll
    for (int o = 16; o > 0; o >>= 1) v += __shfl_xor_sync(0xffffffffu, v, o);
    return v;
}

__global__ void vnew_kernel(const float* __restrict__ qkv, const float* __restrict__ kstore,
                            const float* __restrict__ vstore, const int* __restrict__ idx,
                            const int* __restrict__ sel, float* __restrict__ vnew) {
    int gw = (blockIdx.x * blockDim.x + threadIdx.x) >> 5;
    int lane = threadIdx.x & 31;
    if (gw >= 16 * 1024) return;
    int h = gw >> 10, t = gw & 1023;

    const float* base = qkv + (size_t)t * 3072 + h * 64;
    int d0 = lane * 2;
    float q0 = base[d0],        q1 = base[d0 + 1];
    float k0 = base[1024 + d0], k1 = base[1024 + d0 + 1];
    float v0 = base[2048 + d0], v1 = base[2048 + d0 + 1];
    const float scale = 0.125f;

    float attf[5];
    attf[0] = warp_sum(q0 * k0 + q1 * k1) * scale;

    int ids[4];
#pragma unroll
    for (int s2 = 0; s2 < 4; s2++) ids[s2] = idx[(size_t)gw * 4 + s2];

    float fv0[4], fv1[4];
#pragma unroll
    for (int s2 = 0; s2 < 4; s2++) {
        const float* kp = kstore + ((size_t)h * 8192 + ids[s2]) * 64;
        attf[s2 + 1] = warp_sum(q0 * kp[d0] + q1 * kp[d0 + 1]) * scale;
        const float* vp = vstore + ((size_t)h * 8192 + ids[s2]) * 64;
        fv0[s2] = vp[d0]; fv1[s2] = vp[d0 + 1];
    }

    float mx = attf[0];
#pragma unroll
    for (int s2 = 1; s2 < 5; s2++) mx = fmaxf(mx, attf[s2]);
    float e[5], sum = 0.f;
#pragma unroll
    for (int s2 = 0; s2 < 5; s2++) { e[s2] = expf(attf[s2] - mx); sum += e[s2]; }
    float inv = 1.f / sum;

    float o0 = e[0] * v0, o1 = e[0] * v1;
#pragma unroll
    for (int s2 = 0; s2 < 4; s2++) { o0 += e[s2 + 1] * fv0[s2]; o1 += e[s2 + 1] * fv1[s2]; }
    o0 = o0 * inv * 0.5f + v0 * 0.5f;
    o1 = o1 * inv * 0.5f + v1 * 0.5f;

    bool sl = sel[gw] != 0;
    vnew[(size_t)gw * 64 + d0]     = sl ? o0 : v0;
    vnew[(size_t)gw * 64 + d0 + 1] = sl ? o1 : v1;
}

// ------- transpose+split v_new to bf16 hi/lo, [h][d][t] layout (for flash PV) -------
__global__ void vtrans_kernel(const float* __restrict__ vnew,
                              __nv_bfloat16* __restrict__ vth,
                              __nv_bfloat16* __restrict__ vtl) {
    __shared__ float sm[64][65];
    const int tid = threadIdx.x;
    const int t0 = blockIdx.x * 64, h = blockIdx.y;
    for (int i = tid; i < 4096; i += 256) {
        int tr = i >> 6, d = i & 63;
        sm[tr][d] = vnew[((size_t)h * 1024 + t0 + tr) * 64 + d];
    }
    __syncthreads();
    for (int i = tid; i < 4096; i += 256) {
        int d = i >> 6, tr = i & 63;
        float x = sm[tr][d];
        __nv_bfloat16 hh = __float2bfloat16(x);
        size_t o = ((size_t)h * 64 + d) * 1024 + t0 + tr;
        vth[o] = hh;
        vtl[o] = __float2bfloat16(x - __bfloat162float(hh));
    }
}

// -- flash attention, split-KV + ldmatrix + cp.async K/V double buffer --
// smem: Qh/Ql [128][72] single, 2x (Kh/Kl/Vh/Vl [64][72])
#define FLM_SMEM_BYTES (128 * KAH * 2 * 2 + 2 * (4 * 64 * KAH) * 2)

__global__ __launch_bounds__(256) void flash_mma_kernel(
    const __nv_bfloat16* __restrict__ qhg, const __nv_bfloat16* __restrict__ qlg,
    const __nv_bfloat16* __restrict__ khg, const __nv_bfloat16* __restrict__ klg,
    const __nv_bfloat16* __restrict__ vth, const __nv_bfloat16* __restrict__ vtl,
    float* __restrict__ pO, float* __restrict__ pm, float* __restrict__ pl) {
    extern __shared__ char smc[];
    __nv_bfloat16* Qh = (__nv_bfloat16*)smc;          // [128][72]
    __nv_bfloat16* Ql = Qh + 128 * KAH;
    __nv_bfloat16* KVbuf = Ql + 128 * KAH;            // 2 x (Kh, Kl, Vh, Vl) [64][72]
    const int KVE = 4 * 64 * KAH;                     // elements per buffer

    const int tid = threadIdx.x;
    const int bx = blockIdx.x, h = blockIdx.y;
    const int qb = bx >> 1, half = bx & 1;
    const int w = tid >> 5, lane = tid & 31;
    const int gid = lane >> 2, qid = lane & 3;
    const int rt = w * 16;
    const int t0 = qb * 128;

    const int lrow = lane & 7;
    const int a_row = rt + ((lane >> 3) & 1) * 8 + lrow;
    const int a_col = ((lane >> 4) & 1) * 8;
    const uint32_t qAddrH = smem_u32(Qh + a_row * KAH + a_col);
    const uint32_t qAddrL = smem_u32(Ql + a_row * KAH + a_col);
    const int b_row = ((lane >> 4) & 1) * 8 + lrow;
    const int b_col = ((lane >> 3) & 1) * 8;
    uint32_t kAddrH[2], kAddrL[2], vAddrH[2], vAddrL[2];
    __nv_bfloat16* KVbase[2];
#pragma unroll
    for (int b = 0; b < 2; b++) {
        __nv_bfloat16* Kh = KVbuf + b * KVE;
        __nv_bfloat16* Kl = Kh + 64 * KAH;
        __nv_bfloat16* Vh = Kl + 64 * KAH;
        __nv_bfloat16* Vl = Vh + 64 * KAH;
        KVbase[b] = Kh;
        kAddrH[b] = smem_u32(Kh + b_row * KAH + b_col);
        kAddrL[b] = smem_u32(Kl + b_row * KAH + b_col);
        vAddrH[b] = smem_u32(Vh + b_row * KAH + b_col);
        vAddrL[b] = smem_u32(Vl + b_row * KAH + b_col);
    }

    const __nv_bfloat16* Qhg = qhg + ((size_t)h * 1024 + t0) * 64;
    const __nv_bfloat16* Qlg = qlg + ((size_t)h * 1024 + t0) * 64;
    for (int i = tid; i < 1024; i += 256) {
        int r = i >> 3, c8 = (i & 7) * 8;
        *(uint4*)&Qh[r * KAH + c8] = *(const uint4*)(Qhg + (size_t)r * 64 + c8);
        *(uint4*)&Ql[r * KAH + c8] = *(const uint4*)(Qlg + (size_t)r * 64 + c8);
    }

    float m0 = -FLT_MAX, m1 = -FLT_MAX, l0 = 0.f, l1 = 0.f;
    float O[8][4];
#pragma unroll
    for (int nb = 0; nb < 8; nb++)
#pragma unroll
        for (int k = 0; k < 4; k++) O[nb][k] = 0.f;

    const int row0 = t0 + rt + gid, row1 = row0 + 8;
    const int jlo = half * (qb + 1);
    const int jhi = jlo + qb + 1;

    const __nv_bfloat16* Khg = khg + (size_t)h * 1024 * 64;
    const __nv_bfloat16* Klg = klg + (size_t)h * 1024 * 64;
    const __nv_bfloat16* Vhg = vth + (size_t)h * 64 * 1024;
    const __nv_bfloat16* Vlg = vtl + (size_t)h * 64 * 1024;

    auto issue = [&](int j, int b) {
        const int s0 = j * 64;
        __nv_bfloat16* Kh = KVbase[b];
        __nv_bfloat16* Kl = Kh + 64 * KAH;
        __nv_bfloat16* Vh = Kl + 64 * KAH;
        __nv_bfloat16* Vl = Vh + 64 * KAH;
        for (int i = tid; i < 512; i += 256) {
            int r = i >> 3, c8 = (i & 7) * 8;
            cp_async16(smem_u32(Kh + r * KAH + c8), Khg + (size_t)(s0 + r) * 64 + c8);
            cp_async16(smem_u32(Kl + r * KAH + c8), Klg + (size_t)(s0 + r) * 64 + c8);
            cp_async16(smem_u32(Vh + r * KAH + c8), Vhg + (size_t)r * 1024 + s0 + c8);
            cp_async16(smem_u32(Vl + r * KAH + c8), Vlg + (size_t)r * 1024 + s0 + c8);
        }
        asm volatile("cp.async.commit_group;" ::: "memory");
    };

    issue(jlo, 0);

    for (int j = jlo; j < jhi; j++) {
        const int b = (j - jlo) & 1;
        const int s0 = j * 64;
        asm volatile("cp.async.wait_group 0;" ::: "memory");
        __syncthreads();                              // covers Q stores on first iter
        if (j + 1 < jhi) issue(j + 1, b ^ 1);

        // S = Q K^T (3xBF16, ldmatrix frags)
        float c[8][4];
#pragma unroll
        for (int nb = 0; nb < 8; nb++)
#pragma unroll
            for (int k = 0; k < 4; k++) c[nb][k] = 0.f;

#pragma unroll
        for (int ks16 = 0; ks16 < 4; ks16++) {
            const uint32_t koff = ks16 * 32;
            uint32_t ah0, ah1, ah2, ah3, al0, al1, al2, al3;
            ldsm_x4(ah0, ah1, ah2, ah3, qAddrH + koff);
            ldsm_x4(al0, al1, al2, al3, qAddrL + koff);
#pragma unroll
            for (int nbp = 0; nbp < 4; nbp++) {
                const uint32_t boff = nbp * (16 * KAH * 2) + koff;
                uint32_t bh0a, bh1a, bh0b, bh1b, bl0a, bl1a, bl0b, bl1b;
                ldsm_x4(bh0a, bh1a, bh0b, bh1b, kAddrH[b] + boff);
                ldsm_x4(bl0a, bl1a, bl0b, bl1b, kAddrL[b] + boff);
                const int nA = 2 * nbp, nB = 2 * nbp + 1;
                mma_bf16(c[nA][0], c[nA][1], c[nA][2], c[nA][3],
                         ah0, ah1, ah2, ah3, bh0a, bh1a);
                mma_bf16(c[nA][0], c[nA][1], c[nA][2], c[nA][3],
                         ah0, ah1, ah2, ah3, bl0a, bl1a);
                mma_bf16(c[nA][0], c[nA][1], c[nA][2], c[nA][3],
                         al0, al1, al2, al3, bh0a, bh1a);
                mma_bf16(c[nB][0], c[nB][1], c[nB][2], c[nB][3],
                         ah0, ah1, ah2, ah3, bh0b, bh1b);
                mma_bf16(c[nB][0], c[nB][1], c[nB][2], c[nB][3],
                         ah0, ah1, ah2, ah3, bl0b, bl1b);
                mma_bf16(c[nB][0], c[nB][1], c[nB][2], c[nB][3],
                         al0, al1, al2, al3, bh0b, bh1b);
            }
        }

        // causal mask
        if (s0 + 63 > t0 + rt) {
#pragma unroll
            for (int nb = 0; nb < 8; nb++) {
                int cb = s0 + nb * 8 + 2 * qid;
                if (cb > row0)     c[nb][0] = -FLT_MAX;
                if (cb + 1 > row0) c[nb][1] = -FLT_MAX;
                if (cb > row1)     c[nb][2] = -FLT_MAX;
                if (cb + 1 > row1) c[nb][3] = -FLT_MAX;
            }
        }

        // online softmax
        float rm0 = -FLT_MAX, rm1 = -FLT_MAX;
#pragma unroll
        for (int nb = 0; nb < 8; nb++) {
            rm0 = fmaxf(rm0, fmaxf(c[nb][0], c[nb][1]));
            rm1 = fmaxf(rm1, fmaxf(c[nb][2], c[nb][3]));
        }
        rm0 = fmaxf(rm0, __shfl_xor_sync(0xffffffffu, rm0, 1));
        rm0 = fmaxf(rm0, __shfl_xor_sync(0xffffffffu, rm0, 2));
        rm1 = fmaxf(rm1, __shfl_xor_sync(0xffffffffu, rm1, 1));
        rm1 = fmaxf(rm1, __shfl_xor_sync(0xffffffffu, rm1, 2));

        float mn0 = fmaxf(m0, rm0), mn1 = fmaxf(m1, rm1);
        float alpha0 = __expf(m0 - mn0), alpha1 = __expf(m1 - mn1);
        float ps0 = 0.f, ps1 = 0.f;
#pragma unroll
        for (int nb = 0; nb < 8; nb++) {
            c[nb][0] = __expf(c[nb][0] - mn0); ps0 += c[nb][0];
            c[nb][1] = __expf(c[nb][1] - mn0); ps0 += c[nb][1];
            c[nb][2] = __expf(c[nb][2] - mn1); ps1 += c[nb][2];
            c[nb][3] = __expf(c[nb][3] - mn1); ps1 += c[nb][3];
        }
        ps0 += __shfl_xor_sync(0xffffffffu, ps0, 1);
        ps0 += __shfl_xor_sync(0xffffffffu, ps0, 2);
        ps1 += __shfl_xor_sync(0xffffffffu, ps1, 1);
        ps1 += __shfl_xor_sync(0xffffffffu, ps1, 2);
        l0 = l0 * alpha0 + ps0; m0 = mn0;
        l1 = l1 * alpha1 + ps1; m1 = mn1;
#pragma unroll
        for (int nb = 0; nb < 8; nb++) {
            O[nb][0] *= alpha0; O[nb][1] *= alpha0;
            O[nb][2] *= alpha1; O[nb][3] *= alpha1;
        }

        // P@V (ldmatrix V frags; P converted in registers)
#pragma unroll
        for (int kb = 0; kb < 4; kb++) {
            float p00 = c[2 * kb][0],     p01 = c[2 * kb][1];
            float p02 = c[2 * kb][2],     p03 = c[2 * kb][3];
            float p10 = c[2 * kb + 1][0], p11 = c[2 * kb + 1][1];
            float p12 = c[2 * kb + 1][2], p13 = c[2 * kb + 1][3];
            __nv_bfloat16 h00 = __float2bfloat16(p00), h01 = __float2bfloat16(p01);
            __nv_bfloat16 h02 = __float2bfloat16(p02), h03 = __float2bfloat16(p03);
            __nv_bfloat16 h10 = __float2bfloat16(p10), h11 = __float2bfloat16(p11);
            __nv_bfloat16 h12 = __float2bfloat16(p12), h13 = __float2bfloat16(p13);
            uint32_t Ah0 = pack_bf16(h00, h01);
            uint32_t Ah1 = pack_bf16(h02, h03);
            uint32_t Ah2 = pack_bf16(h10, h11);
            uint32_t Ah3 = pack_bf16(h12, h13);
            uint32_t Al0 = pack_bf16(__float2bfloat16(p00 - __bfloat162float(h00)),
                                     __float2bfloat16(p01 - __bfloat162float(h01)));
            uint32_t Al1 = pack_bf16(__float2bfloat16(p02 - __bfloat162float(h02)),
                                     __float2bfloat16(p03 - __bfloat162float(h03)));
            uint32_t Al2 = pack_bf16(__float2bfloat16(p10 - __bfloat162float(h10)),
                                     __float2bfloat16(p11 - __bfloat162float(h11)));
            uint32_t Al3 = pack_bf16(__float2bfloat16(p12 - __bfloat162float(h12)),
                                     __float2bfloat16(p13 - __bfloat162float(h13)));
            const uint32_t koff = kb * 32;
#pragma unroll
            for (int nbp = 0; nbp < 4; nbp++) {
                const uint32_t boff = nbp * (16 * KAH * 2) + koff;
                uint32_t bh0a, bh1a, bh0b, bh1b, bl0a, bl1a, bl0b, bl1b;
                ldsm_x4(bh0a, bh1a, bh0b, bh1b, vAddrH[b] + boff);
                ldsm_x4(bl0a, bl1a, bl0b, bl1b, vAddrL[b] + boff);
                const int nA = 2 * nbp, nB = 2 * nbp + 1;
                mma_bf16(O[nA][0], O[nA][1], O[nA][2], O[nA][3],
                         Ah0, Ah1, Ah2, Ah3, bh0a, bh1a);
                mma_bf16(O[nA][0], O[nA][1], O[nA][2], O[nA][3],
                         Ah0, Ah1, Ah2, Ah3, bl0a, bl1a);
                mma_bf16(O[nA][0], O[nA][1], O[nA][2], O[nA][3],
                         Al0, Al1, Al2, Al3, bh0a, bh1a);
                mma_bf16(O[nB][0], O[nB][1], O[nB][2], O[nB][3],
                         Ah0, Ah1, Ah2, Ah3, bh0b, bh1b);
                mma_bf16(O[nB][0], O[nB][1], O[nB][2], O[nB][3],
                         Ah0, Ah1, Ah2, Ah3, bl0b, bl1b);
                mma_bf16(O[nB][0], O[nB][1], O[nB][2], O[nB][3],
                         Al0, Al1, Al2, Al3, bh0b, bh1b);
            }
        }
        __syncthreads();   // all warps done with buf b before its next overwrite
    }

    // epilogue: store unnormalized partial (m, l, O)
    const size_t base = ((size_t)half * 16 + h) * 1024;
    if (qid == 0) {
        pm[base + row0] = m0; pl[base + row0] = l0;
        pm[base + row1] = m1; pl[base + row1] = l1;
    }
#pragma unroll
    for (int nb = 0; nb < 8; nb++) {
        int colb = nb * 8 + 2 * qid;
        pO[(base + row0) * 64 + colb]     = O[nb][0];
        pO[(base + row0) * 64 + colb + 1] = O[nb][1];
        pO[(base + row1) * 64 + colb]     = O[nb][2];
        pO[(base + row1) * 64 + colb + 1] = O[nb][3];
    }
}

// ---- merge the two flash partials per (h, t) row -> yh/yl bf16 split directly ----
__global__ void flash_merge_kernel(const float* __restrict__ pO,
                                   const float* __restrict__ pm,
                                   const float* __restrict__ pl,
                                   __nv_bfloat16* __restrict__ yh,
                                   __nv_bfloat16* __restrict__ yl) {
    int i = blockIdx.x * 256 + threadIdx.x;   // < 16*1024*64 = 1M
    int d = i & 63, t = (i >> 6) & 1023, h = i >> 16;
    size_t r0 = (size_t)h * 1024 + t;
    size_t r1 = (size_t)16 * 1024 + r0;
    float ma = pm[r0], mb = pm[r1];
    float mm = fmaxf(ma, mb);
    float ea = __expf(ma - mm), eb = __expf(mb - mm);
    float l = pl[r0] * ea + pl[r1] * eb;
    float o = pO[r0 * 64 + d] * ea + pO[r1 * 64 + d] * eb;
    float val = o / l;
    __nv_bfloat16 hh = __float2bfloat16(val);
    size_t oi = (size_t)t * 1024 + h * 64 + d;
    yh[oi] = hh;
    yl[oi] = __float2bfloat16(val - __bfloat162float(hh));
}

// ---------------- launch ----------------
extern "C" void kernel_launch(void* const* d_in, const int* in_sizes, int n_in,
                              void* d_out, int out_size) {
    const float* x  = (const float*)d_in[0];
    const float* aw = (const float*)d_in[1];
    const float* ab = (const float*)d_in[2];
    const float* pw = (const float*)d_in[3];
    const float* pb = (const float*)d_in[4];
    const float* ks = (const float*)d_in[5];
    const float* vs = (const float*)d_in[6];
    float* out = (float*)d_out;

    float *qkv, *ksn, *lg, *vnw, *pO, *pm, *pl;
    __nv_bfloat16 *kh, *kl, *qh, *ql, *mh, *ml, *xh, *xl, *awh, *awl, *pwh, *pwl, *yh, *yl;
    __nv_bfloat16 *vth, *vtl;
    int *idx, *sel;
    cudaGetSymbolAddress((void**)&qkv, g_qkv);
    cudaGetSymbolAddress((void**)&ksn, g_ksnorm);
    cudaGetSymbolAddress((void**)&kh,  g_kh);
    cudaGetSymbolAddress((void**)&kl,  g_kl);
    cudaGetSymbolAddress((void**)&qh,  g_qh);
    cudaGetSymbolAddress((void**)&ql,  g_ql);
    cudaGetSymbolAddress((void**)&mh,  g_mh);
    cudaGetSymbolAddress((void**)&ml,  g_ml);
    cudaGetSymbolAddress((void**)&xh,  g_xh);
    cudaGetSymbolAddress((void**)&xl,  g_xl);
    cudaGetSymbolAddress((void**)&awh, g_awh);
    cudaGetSymbolAddress((void**)&awl, g_awl);
    cudaGetSymbolAddress((void**)&pwh, g_pwh);
    cudaGetSymbolAddress((void**)&pwl, g_pwl);
    cudaGetSymbolAddress((void**)&yh,  g_yh);
    cudaGetSymbolAddress((void**)&yl,  g_yl);
    cudaGetSymbolAddress((void**)&vth, g_vth);
    cudaGetSymbolAddress((void**)&vtl, g_vtl);
    cudaGetSymbolAddress((void**)&pO,  g_pO);
    cudaGetSymbolAddress((void**)&pm,  g_pm);
    cudaGetSymbolAddress((void**)&pl,  g_pl);
    cudaGetSymbolAddress((void**)&lg,  g_lg);
    cudaGetSymbolAddress((void**)&idx, g_idx);
    cudaGetSymbolAddress((void**)&sel, g_sel);
    cudaGetSymbolAddress((void**)&vnw, g_vnew);

    cudaFuncSetAttribute(knn_mma_kernel,
                         cudaFuncAttributeMaxDynamicSharedMemorySize, KNN_SMEM_BYTES);
    cudaFuncSetAttribute(mma_gemm_bf16_kernel,
                         cudaFuncAttributeMaxDynamicSharedMemorySize, GM_SMEM_BYTES);
    cudaFuncSetAttribute(flash_mma_kernel,
                         cudaFuncAttributeMaxDynamicSharedMemorySize, FLM_SMEM_BYTES);

    // 0) bf16 hi/lo splits
    split_bf16_v4<<<1024, 256>>>((const float4*)x,
                                 (__nv_bfloat162*)xh, (__nv_bfloat162*)xl);
    split_bf16_v4<<<3072, 256>>>((const float4*)aw,
                                 (__nv_bfloat162*)awh, (__nv_bfloat162*)awl);
    split_bf16_v4<<<1024, 256>>>((const float4*)pw,
                                 (__nv_bfloat162*)pwh, (__nv_bfloat162*)pwl);
    split_bf16_v4<<<8192, 256>>>((const float4*)ks,
                                 (__nv_bfloat162*)mh, (__nv_bfloat162*)ml);
    // 1) qkv = x @ c_attn_w^T + b   (3xBF16 mma + ldmatrix + cp.async dbuf)
    mma_gemm_bf16_kernel<<<dim3(24, 16), 256, GM_SMEM_BYTES>>>(
        xh, xl, awh, awl, qkv, 3072, 1024, ab);
    // 2) key_store norms + k/q split/relayout
    ksnorm_kernel<<<512, 256>>>(ks, ksn);
    split_qk_bf16_kernel<<<2048, 1024>>>(qkv, kh, kl, qh, ql);
    // 3) fused kNN scores + top-4 (bf16 mma + ldmatrix + cp.async double buffer)
    knn_mma_kernel<<<dim3(16, 16), 256, KNN_SMEM_BYTES>>>(
        kh, kl, mh, ml, ksn, idx);
    // 4) sel from last-row softmax
    selA_kernel<<<dim3(128, 16), 256>>>(qkv, lg);
    selB_kernel<<<16, 1024>>>(lg, sel);
    // 5) 5-way softmax blend -> v_new
    vnew_kernel<<<2048, 256>>>(qkv, ks, vs, idx, sel, vnw);
    // 5b) transpose+split v_new for flash PV
    vtrans_kernel<<<dim3(16, 16), 256>>>(vnw, vth, vtl);
    // 6) split-KV flash attention (cp.async dbuf) + fused merge/split -> yh/yl
    flash_mma_kernel<<<dim3(16, 16), 256, FLM_SMEM_BYTES>>>(
        qh, ql, kh, kl, vth, vtl, pO, pm, pl);
    flash_merge_kernel<<<4096, 256>>>(pO, pm, pl, yh, yl);
    // 7) out = y @ c_proj_w^T + b   (3xBF16 mma + ldmatrix + cp.async dbuf)
    mma_gemm_bf16_kernel<<<dim3(8, 16), 256, GM_SMEM_BYTES>>>(
        yh, yl, pwh, pwl, out, 1024, 1024, pb);
}